// round 7
// baseline (speedup 1.0000x reference)
#include <cuda_runtime.h>
#include <cuda_bf16.h>
#include <cuda_fp16.h>
#include <cstdint>

// ---------------------------------------------------------------------------
// Problem constants
// ---------------------------------------------------------------------------
#define BATCH   32
#define FRAMES  32
#define NOBJ    36
#define DIN     2048
#define PDIM    512
#define MROWS   (BATCH*FRAMES*NOBJ)     // 36864
#define HEADS   (BATCH*FRAMES)          // 1024
#define NCAT    (4*PDIM)                // 2048 concat output cols

#define MTILE   128
#define NTILE   256

// gemm3 (bf16 3-pass): K-chunk 32 (64B rows), 4 stages
#define NCH3    (DIN/32)                // 64 chunks
#define OFF3_AH 0
#define OFF3_AL 8192
#define OFF3_BH 16384
#define OFF3_BL 32768
#define STAGE3_BYTES 49152
#define GEMM3_SMEM  (4*STAGE3_BYTES)    // 196608

// gemm1 (fp16 1-pass): K-chunk 64 (128B rows), 4 stages
#define NCH1    (DIN/64)                // 32 chunks
#define OFF_AF  0
#define OFF_BF  16384
#define STAGE1_BYTES 49152
#define GEMM1_SMEM  (4*STAGE1_BYTES)    // 196608

// attention smem: v (36*512 f32) + logits (36*36) + transposed probs (36*40)
#define ATTN_SMEM  ((NOBJ*PDIM + NOBJ*NOBJ + NOBJ*40)*4)   // 84672 bytes

#define OUT_HALF   ((size_t)MROWS*PDIM)

// ---------------------------------------------------------------------------
// Device scratch
// ---------------------------------------------------------------------------
__device__ __nv_bfloat16 g_xh[(size_t)MROWS*DIN];
__device__ __nv_bfloat16 g_xl[(size_t)MROWS*DIN];
__device__ __half        g_xf[(size_t)MROWS*DIN];
__device__ __nv_bfloat16 g_wth[(size_t)NCAT*DIN];   // [n][k], K-major (sig/psi rows)
__device__ __nv_bfloat16 g_wtl[(size_t)NCAT*DIN];
__device__ __half        g_wf [(size_t)NCAT*DIN];   // [n][k], K-major (proj/r rows)
__device__ float g_sig[(size_t)MROWS*PDIM];
__device__ float g_psi[(size_t)MROWS*PDIM];
__device__ float g_v  [(size_t)MROWS*PDIM];

// ---------------------------------------------------------------------------
// PTX helpers
// ---------------------------------------------------------------------------
__device__ __forceinline__ uint32_t smem_u32(const void* p) {
    uint32_t a;
    asm("{ .reg .u64 t; cvta.to.shared.u64 t, %1; cvt.u32.u64 %0, t; }"
        : "=r"(a) : "l"(p));
    return a;
}

__device__ __forceinline__ void cp16(uint32_t s, const void* g) {
    asm volatile("cp.async.cg.shared.global [%0], [%1], 16;\n" :: "r"(s), "l"(g) : "memory");
}

#define LDSM4(R, A) \
    asm volatile("ldmatrix.sync.aligned.m8n8.x4.shared.b16 {%0,%1,%2,%3}, [%4];" \
        : "=r"((R)[0]), "=r"((R)[1]), "=r"((R)[2]), "=r"((R)[3]) : "r"(A))

#define MMA_BF16(C, A, B0, B1) \
    asm volatile("mma.sync.aligned.m16n8k16.row.col.f32.bf16.bf16.f32 " \
        "{%0,%1,%2,%3}, {%4,%5,%6,%7}, {%8,%9}, {%0,%1,%2,%3};" \
        : "+f"((C)[0]), "+f"((C)[1]), "+f"((C)[2]), "+f"((C)[3]) \
        : "r"((A)[0]), "r"((A)[1]), "r"((A)[2]), "r"((A)[3]), "r"(B0), "r"(B1))

#define MMA_F16(C, A, B0, B1) \
    asm volatile("mma.sync.aligned.m16n8k16.row.col.f32.f16.f16.f32 " \
        "{%0,%1,%2,%3}, {%4,%5,%6,%7}, {%8,%9}, {%0,%1,%2,%3};" \
        : "+f"((C)[0]), "+f"((C)[1]), "+f"((C)[2]), "+f"((C)[3]) \
        : "r"((A)[0]), "r"((A)[1]), "r"((A)[2]), "r"((A)[3]), "r"(B0), "r"(B1))

// 128B-row swizzle (gemm1): chunk i in 0..7
#define SWZ128(r, i) ((uint32_t)((r) * 128 + (((i) * 16) ^ (((r) & 7) << 4))))
// 64B-row swizzle (gemm3): chunk i in 0..3; bank-quad = (4r + (i + (r>>1))&3) % 8, distinct per 8-row phase
#define SWZ64(r, i)  ((uint32_t)((r) * 64 + ((((i) + ((r) >> 1)) & 3) << 4)))

// ---------------------------------------------------------------------------
// Prep kernels: fp32 -> bf16 hi/lo (sig/psi path) and fp16 (proj/v path)
// ---------------------------------------------------------------------------
__global__ void split_x_kernel(const float* __restrict__ x, long n4) {
    long i = blockIdx.x * (long)blockDim.x + threadIdx.x;
    long stride = (long)gridDim.x * blockDim.x;
    __nv_bfloat162* xh2 = reinterpret_cast<__nv_bfloat162*>(g_xh);
    __nv_bfloat162* xl2 = reinterpret_cast<__nv_bfloat162*>(g_xl);
    __half2*        xf2 = reinterpret_cast<__half2*>(g_xf);
    for (; i < n4; i += stride) {
        float4 v = reinterpret_cast<const float4*>(x)[i];
        __nv_bfloat16 h0 = __float2bfloat16(v.x);
        __nv_bfloat16 h1 = __float2bfloat16(v.y);
        __nv_bfloat16 h2 = __float2bfloat16(v.z);
        __nv_bfloat16 h3 = __float2bfloat16(v.w);
        __nv_bfloat16 l0 = __float2bfloat16(v.x - __bfloat162float(h0));
        __nv_bfloat16 l1 = __float2bfloat16(v.y - __bfloat162float(h1));
        __nv_bfloat16 l2 = __float2bfloat16(v.z - __bfloat162float(h2));
        __nv_bfloat16 l3 = __float2bfloat16(v.w - __bfloat162float(h3));
        __nv_bfloat162 hA; hA.x = h0; hA.y = h1;
        __nv_bfloat162 hB; hB.x = h2; hB.y = h3;
        __nv_bfloat162 lA; lA.x = l0; lA.y = l1;
        __nv_bfloat162 lB; lB.x = l2; lB.y = l3;
        xh2[2*i]   = hA; xh2[2*i+1] = hB;
        xl2[2*i]   = lA; xl2[2*i+1] = lB;
        xf2[2*i]   = __floats2half2_rn(v.x, v.y);
        xf2[2*i+1] = __floats2half2_rn(v.z, v.w);
    }
}

__global__ void split_w_kernel(const float* __restrict__ Wp, const float* __restrict__ Ws,
                               const float* __restrict__ Wq, const float* __restrict__ Wr) {
    long t = blockIdx.x * (long)blockDim.x + threadIdx.x;   // over NCAT*DIN
    if (t >= (long)NCAT * DIN) return;
    int n = (int)(t >> 11);        // /DIN
    int k = (int)(t & (DIN - 1));
    int mat = n >> 9, p = n & 511;
    const float* W = (mat == 0) ? Wp : (mat == 1) ? Ws : (mat == 2) ? Wq : Wr;
    float w = W[(size_t)k * PDIM + p];
    if (mat == 1 || mat == 2) {
        __nv_bfloat16 h = __float2bfloat16(w);
        g_wth[t] = h;
        g_wtl[t] = __float2bfloat16(w - __bfloat162float(h));
    } else {
        g_wf[t] = __float2half_rn(w);
    }
}

// ---------------------------------------------------------------------------
// gemm3: sig/psi columns, bf16 3-pass, K-chunk 32, 4-stage, 1 sync/iter
// ---------------------------------------------------------------------------
__device__ __forceinline__ void load_chunk3(uint32_t sbase, int kc, int m0, int n0, int tid) {
    const char* xh = (const char*)g_xh;
    const char* xl = (const char*)g_xl;
    const char* bh = (const char*)g_wth;
    const char* bl = (const char*)g_wtl;
    size_t kcoff = (size_t)kc * 64;    // 32 bf16 = 64 bytes
    {                                   // A: 128 rows x 4 x 16B = 512 units
        int r = tid >> 2, i = tid & 3;
        uint32_t so = SWZ64(r, i);
        size_t goA = ((size_t)(m0 + r)) * (DIN * 2) + kcoff + i * 16;
        cp16(sbase + OFF3_AH + so, xh + goA);
        cp16(sbase + OFF3_AL + so, xl + goA);
    }
#pragma unroll
    for (int q = 0; q < 2; q++) {       // B: 256 rows x 4 x 16B = 1024 units
        int j = tid + q * 512;
        int r = j >> 2, i = j & 3;
        uint32_t so = SWZ64(r, i);
        size_t goB = ((size_t)(n0 + r)) * (DIN * 2) + kcoff + i * 16;
        cp16(sbase + OFF3_BH + so, bh + goB);
        cp16(sbase + OFF3_BL + so, bl + goB);
    }
    asm volatile("cp.async.commit_group;\n" ::: "memory");
}

__device__ __forceinline__ void compute_chunk3(uint32_t sbase, float (*acc)[8][4],
                                               int wm, int wn, int lane) {
    int r_off  = lane & 15;
    int ia_h   = (lane >> 4);               // A k-half chunk select (0/1)
    int n_off  = (lane & 7) + ((lane >> 4) << 3);
    int ib_h   = ((lane >> 3) & 1);         // B k-half chunk select (0/1)
#pragma unroll
    for (int kk = 0; kk < 2; kk++) {        // 2 x k16 per 32-chunk
        uint32_t ah[2][4], al[2][4], b[4][4];
        int ia = kk * 2 + ia_h;
        int ib = kk * 2 + ib_h;
#pragma unroll
        for (int im = 0; im < 2; im++) {
            int row = wm + im * 16 + r_off;
            uint32_t off = SWZ64(row, ia);
            LDSM4(ah[im], sbase + OFF3_AH + off);
            LDSM4(al[im], sbase + OFF3_AL + off);
        }
#pragma unroll
        for (int j = 0; j < 4; j++) {
            int row = wn + j * 16 + n_off;
            LDSM4(b[j], sbase + OFF3_BH + SWZ64(row, ib));
        }
#pragma unroll
        for (int im = 0; im < 2; im++)
#pragma unroll
            for (int j = 0; j < 4; j++) {
                MMA_BF16(acc[im][2*j],   ah[im], b[j][0], b[j][1]);
                MMA_BF16(acc[im][2*j+1], ah[im], b[j][2], b[j][3]);
            }
#pragma unroll
        for (int im = 0; im < 2; im++)
#pragma unroll
            for (int j = 0; j < 4; j++) {
                MMA_BF16(acc[im][2*j],   al[im], b[j][0], b[j][1]);
                MMA_BF16(acc[im][2*j+1], al[im], b[j][2], b[j][3]);
            }
#pragma unroll
        for (int j = 0; j < 4; j++) {
            int row = wn + j * 16 + n_off;
            LDSM4(b[j], sbase + OFF3_BL + SWZ64(row, ib));
        }
#pragma unroll
        for (int im = 0; im < 2; im++)
#pragma unroll
            for (int j = 0; j < 4; j++) {
                MMA_BF16(acc[im][2*j],   ah[im], b[j][0], b[j][1]);
                MMA_BF16(acc[im][2*j+1], ah[im], b[j][2], b[j][3]);
            }
    }
}

__global__ void __launch_bounds__(512, 1) gemm3_kernel(
    const float* __restrict__ b_sigma, const float* __restrict__ b_psi)
{
    extern __shared__ char smem[];
    uint32_t sb = smem_u32(smem);
    int tid = threadIdx.x;
    int wid = tid >> 5, lane = tid & 31;
    int nt = blockIdx.x & 3;        // N-tile fastest: A reuse in L2
    int mt = blockIdx.x >> 2;
    int m0 = mt * MTILE, n0 = 512 + nt * NTILE;   // concat cols 512..1535
    int wm = (wid >> 2) * 32, wn = (wid & 3) * 64;

    float acc[2][8][4];
#pragma unroll
    for (int a = 0; a < 2; a++)
#pragma unroll
        for (int b = 0; b < 8; b++)
#pragma unroll
            for (int c = 0; c < 4; c++) acc[a][b][c] = 0.f;

    load_chunk3(sb + 0 * STAGE3_BYTES, 0, m0, n0, tid);
    load_chunk3(sb + 1 * STAGE3_BYTES, 1, m0, n0, tid);
    load_chunk3(sb + 2 * STAGE3_BYTES, 2, m0, n0, tid);

    for (int c = 0; c < NCH3; c++) {
        if (c < NCH3 - 2)      asm volatile("cp.async.wait_group 2;" ::: "memory");
        else if (c == NCH3 - 2) asm volatile("cp.async.wait_group 1;" ::: "memory");
        else                    asm volatile("cp.async.wait_group 0;" ::: "memory");
        __syncthreads();
        if (c + 3 < NCH3)
            load_chunk3(sb + ((c + 3) & 3) * STAGE3_BYTES, c + 3, m0, n0, tid);
        compute_chunk3(sb + (c & 3) * STAGE3_BYTES, acc, wm, wn, lane);
    }

    const float* bias = (nt < 2) ? b_sigma : b_psi;
    float* dest = (nt < 2) ? g_sig : g_psi;
    int colbase = (nt & 1) * 256;
    int groupID = lane >> 2, tig = lane & 3;

#pragma unroll
    for (int im = 0; im < 2; im++) {
#pragma unroll
        for (int in = 0; in < 8; in++) {
            int col = colbase + wn + in * 8 + tig * 2;
            float2 bv = __ldg((const float2*)&bias[col]);
            int row0 = m0 + wm + im * 16 + groupID;
            float2 v0, v1;
            v0.x = acc[im][in][0] + bv.x; v0.y = acc[im][in][1] + bv.y;
            v1.x = acc[im][in][2] + bv.x; v1.y = acc[im][in][3] + bv.y;
            *(float2*)&dest[(size_t)row0 * PDIM + col]       = v0;
            *(float2*)&dest[(size_t)(row0 + 8) * PDIM + col] = v1;
        }
    }
}

// ---------------------------------------------------------------------------
// gemm1: r_feat / v columns, fp16 single pass, 4-stage, 1 sync/iter
// ---------------------------------------------------------------------------
__device__ __forceinline__ void load_chunk1(uint32_t sbase, int kc, int m0, int n0, int tid) {
    const char* xf = (const char*)g_xf;
    const char* bf = (const char*)g_wf;
    size_t kcoff = (size_t)kc * 128;
#pragma unroll
    for (int q = 0; q < 2; q++) {                 // A: 128 rows x 8 x 16B
        int j = tid + q * 512;
        int r = j >> 3, i = j & 7;
        uint32_t so = SWZ128(r, i);
        size_t goA = ((size_t)(m0 + r)) * (DIN * 2) + kcoff + i * 16;
        cp16(sbase + OFF_AF + so, xf + goA);
    }
#pragma unroll
    for (int q = 0; q < 4; q++) {                 // B: 256 rows x 8 x 16B
        int j = tid + q * 512;
        int r = j >> 3, i = j & 7;
        uint32_t so = SWZ128(r, i);
        size_t goB = ((size_t)(n0 + r)) * (DIN * 2) + kcoff + i * 16;
        cp16(sbase + OFF_BF + so, bf + goB);
    }
    asm volatile("cp.async.commit_group;\n" ::: "memory");
}

__device__ __forceinline__ void compute_chunk1(uint32_t sbase, float (*acc)[8][4],
                                               int wm, int wn, int lane) {
    int r_off  = lane & 15;
    int kseg   = (lane >> 4) << 3;
    int n_off  = (lane & 7) + ((lane >> 4) << 3);
    int ksegb  = ((lane >> 3) & 1) << 3;
#pragma unroll
    for (int kk = 0; kk < 4; kk++) {
        uint32_t af[2][4], b[4][4];
#pragma unroll
        for (int im = 0; im < 2; im++) {
            int row = wm + im * 16 + r_off;
            int kb = (kk * 16 + kseg) >> 3;       // chunk idx 0..7
            LDSM4(af[im], sbase + OFF_AF + SWZ128(row, kb));
        }
#pragma unroll
        for (int j = 0; j < 4; j++) {
            int row = wn + j * 16 + n_off;
            int kb = (kk * 16 + ksegb) >> 3;
            LDSM4(b[j], sbase + OFF_BF + SWZ128(row, kb));
        }
#pragma unroll
        for (int im = 0; im < 2; im++)
#pragma unroll
            for (int j = 0; j < 4; j++) {
                MMA_F16(acc[im][2*j],   af[im], b[j][0], b[j][1]);
                MMA_F16(acc[im][2*j+1], af[im], b[j][2], b[j][3]);
            }
    }
}

__global__ void __launch_bounds__(512, 1) gemm1_kernel(
    const float* __restrict__ b_proj, float* __restrict__ out_rfeat)
{
    extern __shared__ char smem[];
    uint32_t sb = smem_u32(smem);
    int tid = threadIdx.x;
    int wid = tid >> 5, lane = tid & 31;
    int nt = blockIdx.x & 3;
    int mt = blockIdx.x >> 2;
    int m0 = mt * MTILE;
    int n0 = (nt < 2) ? nt * NTILE : 1536 + (nt - 2) * NTILE;
    int wm = (wid >> 2) * 32, wn = (wid & 3) * 64;

    float acc[2][8][4];
#pragma unroll
    for (int a = 0; a < 2; a++)
#pragma unroll
        for (int b = 0; b < 8; b++)
#pragma unroll
            for (int c = 0; c < 4; c++) acc[a][b][c] = 0.f;

    load_chunk1(sb + 0 * STAGE1_BYTES, 0, m0, n0, tid);
    load_chunk1(sb + 1 * STAGE1_BYTES, 1, m0, n0, tid);
    load_chunk1(sb + 2 * STAGE1_BYTES, 2, m0, n0, tid);

    for (int c = 0; c < NCH1; c++) {
        if (c < NCH1 - 2)       asm volatile("cp.async.wait_group 2;" ::: "memory");
        else if (c == NCH1 - 2) asm volatile("cp.async.wait_group 1;" ::: "memory");
        else                    asm volatile("cp.async.wait_group 0;" ::: "memory");
        __syncthreads();
        if (c + 3 < NCH1)
            load_chunk1(sb + ((c + 3) & 3) * STAGE1_BYTES, c + 3, m0, n0, tid);
        compute_chunk1(sb + (c & 3) * STAGE1_BYTES, acc, wm, wn, lane);
    }

    const float* bias = (nt < 2) ? b_proj : nullptr;
    float* dest = (nt < 2) ? out_rfeat : g_v;
    int colbase = (nt & 1) * 256;
    int groupID = lane >> 2, tig = lane & 3;

#pragma unroll
    for (int im = 0; im < 2; im++) {
#pragma unroll
        for (int in = 0; in < 8; in++) {
            int col = colbase + wn + in * 8 + tig * 2;
            float2 bv = make_float2(0.f, 0.f);
            if (bias) bv = __ldg((const float2*)&bias[col]);
            int row0 = m0 + wm + im * 16 + groupID;
            float2 v0, v1;
            v0.x = acc[im][in][0] + bv.x; v0.y = acc[im][in][1] + bv.y;
            v1.x = acc[im][in][2] + bv.x; v1.y = acc[im][in][3] + bv.y;
            *(float2*)&dest[(size_t)row0 * PDIM + col]       = v0;
            *(float2*)&dest[(size_t)(row0 + 8) * PDIM + col] = v1;
        }
    }
}

// ---------------------------------------------------------------------------
// Attention: per-head softmax(sig psi^T) @ v   (1 CTA per head, 256 threads,
// 2 CTAs/SM; v in smem; sig 6-way-broadcast loads, psi 6-distinct-row loads)
// ---------------------------------------------------------------------------
__global__ void __launch_bounds__(256, 2) attn_kernel(float* __restrict__ out_rhat) {
    extern __shared__ float as[];
    float* v_s = as;                          // 36*512
    float* l_s = as + NOBJ * PDIM;            // 36*36   logits, n-major
    float* l_t = l_s + NOBJ * NOBJ;           // 36*40   probs, m-major (padded)
    int h = blockIdx.x;
    int tid = threadIdx.x;
    size_t base = (size_t)h * NOBJ;

    const float4* gv = (const float4*)(g_v + base * PDIM);
    float4* sv = (float4*)v_s;
#pragma unroll
    for (int q = 0; q < 18; q++) {            // 4608 float4s
        int i = tid + q * 256;
        sv[i] = gv[i];
    }
    __syncthreads();

    // logits: l[n][m] = dot(sig[n], psi[m]); thread (n = tid/6, g = tid%6)
    // computes m = g, g+6, ..., g+30.  Lanes sharing n broadcast the sig load.
    if (tid < 216) {
        int n = tid / 6, g = tid % 6;
        float a0 = 0, a1 = 0, a2 = 0, a3 = 0, a4 = 0, a5 = 0;
        const float4* sg = (const float4*)(g_sig + (base + n) * PDIM);
        const float4* p0 = (const float4*)(g_psi + (base + g +  0) * PDIM);
        const float4* p1 = (const float4*)(g_psi + (base + g +  6) * PDIM);
        const float4* p2 = (const float4*)(g_psi + (base + g + 12) * PDIM);
        const float4* p3 = (const float4*)(g_psi + (base + g + 18) * PDIM);
        const float4* p4 = (const float4*)(g_psi + (base + g + 24) * PDIM);
        const float4* p5 = (const float4*)(g_psi + (base + g + 30) * PDIM);
        for (int k = 0; k < 128; k++) {
            float4 s = __ldg(&sg[k]);
            float4 p;
            p = __ldg(&p0[k]); a0 += s.x * p.x + s.y * p.y + s.z * p.z + s.w * p.w;
            p = __ldg(&p1[k]); a1 += s.x * p.x + s.y * p.y + s.z * p.z + s.w * p.w;
            p = __ldg(&p2[k]); a2 += s.x * p.x + s.y * p.y + s.z * p.z + s.w * p.w;
            p = __ldg(&p3[k]); a3 += s.x * p.x + s.y * p.y + s.z * p.z + s.w * p.w;
            p = __ldg(&p4[k]); a4 += s.x * p.x + s.y * p.y + s.z * p.z + s.w * p.w;
            p = __ldg(&p5[k]); a5 += s.x * p.x + s.y * p.y + s.z * p.z + s.w * p.w;
        }
        l_s[n * 36 + g +  0] = a0;
        l_s[n * 36 + g +  6] = a1;
        l_s[n * 36 + g + 12] = a2;
        l_s[n * 36 + g + 18] = a3;
        l_s[n * 36 + g + 24] = a4;
        l_s[n * 36 + g + 30] = a5;
    }
    __syncthreads();

    // row softmax; write probs transposed (m-major) for vectorized AV loads
    if (tid < 36) {
        float row[36];
        float m = -1e30f;
#pragma unroll
        for (int j = 0; j < 36; j++) { row[j] = l_s[tid * 36 + j]; m = fmaxf(m, row[j]); }
        float ssum = 0.f;
#pragma unroll
        for (int j = 0; j < 36; j++) { float e = __expf(row[j] - m); row[j] = e; ssum += e; }
        float inv = 1.f / ssum;
#pragma unroll
        for (int j = 0; j < 36; j++) l_t[j * 40 + tid] = row[j] * inv;
    }
    __syncthreads();

    // AV: out[n][p] = sum_m a[n][m] v[m][p]; each thread: 1 col-chunk x 18 rows
    int c4 = tid & 127, nh = tid >> 7;
    float4 acc[18];
#pragma unroll
    for (int j = 0; j < 18; j++) acc[j] = make_float4(0.f, 0.f, 0.f, 0.f);
    const float4* vrow = (const float4*)v_s + c4;
#pragma unroll 4
    for (int m = 0; m < 36; m++) {
        float4 vv = vrow[m * 128];
#pragma unroll
        for (int jj = 0; jj < 9; jj++) {
            float2 aa = *(const float2*)&l_t[m * 40 + nh * 18 + jj * 2];
            acc[2*jj].x   += aa.x * vv.x; acc[2*jj].y   += aa.x * vv.y;
            acc[2*jj].z   += aa.x * vv.z; acc[2*jj].w   += aa.x * vv.w;
            acc[2*jj+1].x += aa.y * vv.x; acc[2*jj+1].y += aa.y * vv.y;
            acc[2*jj+1].z += aa.y * vv.z; acc[2*jj+1].w += aa.y * vv.w;
        }
    }
    float4* vo = (float4*)(out_rhat + base * PDIM);
#pragma unroll
    for (int j = 0; j < 18; j++) {
        int n = nh * 18 + j;
        vo[n * 128 + c4] = acc[j];
    }
}

// ---------------------------------------------------------------------------
// Launcher
// ---------------------------------------------------------------------------
extern "C" void kernel_launch(void* const* d_in, const int* in_sizes, int n_in,
                              void* d_out, int out_size) {
    const float* x       = (const float*)d_in[0];
    const float* W_proj  = (const float*)d_in[1];
    const float* b_proj  = (const float*)d_in[2];
    const float* W_sigma = (const float*)d_in[3];
    const float* b_sigma = (const float*)d_in[4];
    const float* W_psi   = (const float*)d_in[5];
    const float* b_psi   = (const float*)d_in[6];
    const float* W_r     = (const float*)d_in[7];
    float* out = (float*)d_out;

    cudaFuncSetAttribute(gemm3_kernel, cudaFuncAttributeMaxDynamicSharedMemorySize, GEMM3_SMEM);
    cudaFuncSetAttribute(gemm1_kernel, cudaFuncAttributeMaxDynamicSharedMemorySize, GEMM1_SMEM);
    cudaFuncSetAttribute(attn_kernel, cudaFuncAttributeMaxDynamicSharedMemorySize, ATTN_SMEM);

    long n4 = (long)MROWS * DIN / 4;
    split_x_kernel<<<8192, 256>>>(x, n4);
    split_w_kernel<<<(NCAT * DIN + 255) / 256, 256>>>(W_proj, W_sigma, W_psi, W_r);
    gemm3_kernel<<<(MROWS / MTILE) * 4, 512, GEMM3_SMEM>>>(b_sigma, b_psi);
    gemm1_kernel<<<(MROWS / MTILE) * 4, 512, GEMM1_SMEM>>>(b_proj, out);
    attn_kernel<<<HEADS, 256, ATTN_SMEM>>>(out + OUT_HALF);
}

// round 8
// speedup vs baseline: 1.0397x; 1.0397x over previous
#include <cuda_runtime.h>
#include <cuda_bf16.h>
#include <cuda_fp16.h>
#include <cstdint>

// ---------------------------------------------------------------------------
// Problem constants
// ---------------------------------------------------------------------------
#define BATCH   32
#define FRAMES  32
#define NOBJ    36
#define DIN     2048
#define PDIM    512
#define MROWS   (BATCH*FRAMES*NOBJ)     // 36864
#define HEADS   (BATCH*FRAMES)          // 1024
#define NCAT    (4*PDIM)                // 2048 concat output cols

#define MTILE   128

// gemm3 (bf16 3-pass): 128x128 tile, K-chunk 64 (128B rows), 3 stages x 64KB
#define NCH3    (DIN/64)                // 32 chunks
#define OFF3_AH 0
#define OFF3_AL 16384
#define OFF3_BH 32768
#define OFF3_BL 49152
#define STAGE3_BYTES 65536
#define GEMM3_SMEM  (3*STAGE3_BYTES)    // 196608

// gemm1 (fp16 1-pass): 128x256 tile, K-chunk 64 (128B rows), 4 stages x 48KB
#define NCH1    (DIN/64)                // 32 chunks
#define OFF_AF  0
#define OFF_BF  16384
#define STAGE1_BYTES 49152
#define GEMM1_SMEM  (4*STAGE1_BYTES)    // 196608

// attention smem: v (36*512 f32) + logits (36*36) + transposed probs (36*40)
#define ATTN_SMEM  ((NOBJ*PDIM + NOBJ*NOBJ + NOBJ*40)*4)   // 84672 bytes

#define OUT_HALF   ((size_t)MROWS*PDIM)

// ---------------------------------------------------------------------------
// Device scratch
// ---------------------------------------------------------------------------
__device__ __nv_bfloat16 g_xh[(size_t)MROWS*DIN];
__device__ __nv_bfloat16 g_xl[(size_t)MROWS*DIN];
__device__ __half        g_xf[(size_t)MROWS*DIN];
__device__ __nv_bfloat16 g_wth[(size_t)NCAT*DIN];   // [n][k], K-major (sig/psi rows)
__device__ __nv_bfloat16 g_wtl[(size_t)NCAT*DIN];
__device__ __half        g_wf [(size_t)NCAT*DIN];   // [n][k], K-major (proj/r rows)
__device__ float g_sig[(size_t)MROWS*PDIM];
__device__ float g_psi[(size_t)MROWS*PDIM];
__device__ float g_v  [(size_t)MROWS*PDIM];

// ---------------------------------------------------------------------------
// PTX helpers
// ---------------------------------------------------------------------------
__device__ __forceinline__ uint32_t smem_u32(const void* p) {
    uint32_t a;
    asm("{ .reg .u64 t; cvta.to.shared.u64 t, %1; cvt.u32.u64 %0, t; }"
        : "=r"(a) : "l"(p));
    return a;
}

__device__ __forceinline__ void cp16(uint32_t s, const void* g) {
    asm volatile("cp.async.cg.shared.global [%0], [%1], 16;\n" :: "r"(s), "l"(g) : "memory");
}

#define LDSM4(R, A) \
    asm volatile("ldmatrix.sync.aligned.m8n8.x4.shared.b16 {%0,%1,%2,%3}, [%4];" \
        : "=r"((R)[0]), "=r"((R)[1]), "=r"((R)[2]), "=r"((R)[3]) : "r"(A))

#define MMA_BF16(C, A, B0, B1) \
    asm volatile("mma.sync.aligned.m16n8k16.row.col.f32.bf16.bf16.f32 " \
        "{%0,%1,%2,%3}, {%4,%5,%6,%7}, {%8,%9}, {%0,%1,%2,%3};" \
        : "+f"((C)[0]), "+f"((C)[1]), "+f"((C)[2]), "+f"((C)[3]) \
        : "r"((A)[0]), "r"((A)[1]), "r"((A)[2]), "r"((A)[3]), "r"(B0), "r"(B1))

#define MMA_F16(C, A, B0, B1) \
    asm volatile("mma.sync.aligned.m16n8k16.row.col.f32.f16.f16.f32 " \
        "{%0,%1,%2,%3}, {%4,%5,%6,%7}, {%8,%9}, {%0,%1,%2,%3};" \
        : "+f"((C)[0]), "+f"((C)[1]), "+f"((C)[2]), "+f"((C)[3]) \
        : "r"((A)[0]), "r"((A)[1]), "r"((A)[2]), "r"((A)[3]), "r"(B0), "r"(B1))

// 128B-row swizzle: chunk i in 0..7
#define SWZ128(r, i) ((uint32_t)((r) * 128 + (((i) * 16) ^ (((r) & 7) << 4))))

// ---------------------------------------------------------------------------
// Prep kernels: fp32 -> bf16 hi/lo (sig/psi path) and fp16 (proj/v path)
// ---------------------------------------------------------------------------
__global__ void split_x_kernel(const float* __restrict__ x, long n4) {
    long i = blockIdx.x * (long)blockDim.x + threadIdx.x;
    long stride = (long)gridDim.x * blockDim.x;
    __nv_bfloat162* xh2 = reinterpret_cast<__nv_bfloat162*>(g_xh);
    __nv_bfloat162* xl2 = reinterpret_cast<__nv_bfloat162*>(g_xl);
    __half2*        xf2 = reinterpret_cast<__half2*>(g_xf);
    for (; i < n4; i += stride) {
        float4 v = reinterpret_cast<const float4*>(x)[i];
        __nv_bfloat16 h0 = __float2bfloat16(v.x);
        __nv_bfloat16 h1 = __float2bfloat16(v.y);
        __nv_bfloat16 h2 = __float2bfloat16(v.z);
        __nv_bfloat16 h3 = __float2bfloat16(v.w);
        __nv_bfloat16 l0 = __float2bfloat16(v.x - __bfloat162float(h0));
        __nv_bfloat16 l1 = __float2bfloat16(v.y - __bfloat162float(h1));
        __nv_bfloat16 l2 = __float2bfloat16(v.z - __bfloat162float(h2));
        __nv_bfloat16 l3 = __float2bfloat16(v.w - __bfloat162float(h3));
        __nv_bfloat162 hA; hA.x = h0; hA.y = h1;
        __nv_bfloat162 hB; hB.x = h2; hB.y = h3;
        __nv_bfloat162 lA; lA.x = l0; lA.y = l1;
        __nv_bfloat162 lB; lB.x = l2; lB.y = l3;
        xh2[2*i]   = hA; xh2[2*i+1] = hB;
        xl2[2*i]   = lA; xl2[2*i+1] = lB;
        xf2[2*i]   = __floats2half2_rn(v.x, v.y);
        xf2[2*i+1] = __floats2half2_rn(v.z, v.w);
    }
}

__global__ void split_w_kernel(const float* __restrict__ Wp, const float* __restrict__ Ws,
                               const float* __restrict__ Wq, const float* __restrict__ Wr) {
    long t = blockIdx.x * (long)blockDim.x + threadIdx.x;   // over NCAT*DIN
    if (t >= (long)NCAT * DIN) return;
    int n = (int)(t >> 11);        // /DIN
    int k = (int)(t & (DIN - 1));
    int mat = n >> 9, p = n & 511;
    const float* W = (mat == 0) ? Wp : (mat == 1) ? Ws : (mat == 2) ? Wq : Wr;
    float w = W[(size_t)k * PDIM + p];
    if (mat == 1 || mat == 2) {
        __nv_bfloat16 h = __float2bfloat16(w);
        g_wth[t] = h;
        g_wtl[t] = __float2bfloat16(w - __bfloat162float(h));
    } else {
        g_wf[t] = __float2half_rn(w);
    }
}

// ---------------------------------------------------------------------------
// gemm3: sig/psi columns, bf16 3-pass, 128x128 tile, 3-stage, 1 sync/iter
// ---------------------------------------------------------------------------
__device__ __forceinline__ void load_chunk3(uint32_t sbase, int kc, int m0, int n0, int tid) {
    const char* xh = (const char*)g_xh;
    const char* xl = (const char*)g_xl;
    const char* bh = (const char*)g_wth;
    const char* bl = (const char*)g_wtl;
    size_t kcoff = (size_t)kc * 128;   // 64 bf16 = 128 bytes
#pragma unroll
    for (int q = 0; q < 2; q++) {      // A & B: 128 rows x 8 x 16B = 1024 units each
        int j = tid + q * 512;
        int r = j >> 3, i = j & 7;
        uint32_t so = SWZ128(r, i);
        size_t goA = ((size_t)(m0 + r)) * (DIN * 2) + kcoff + i * 16;
        size_t goB = ((size_t)(n0 + r)) * (DIN * 2) + kcoff + i * 16;
        cp16(sbase + OFF3_AH + so, xh + goA);
        cp16(sbase + OFF3_AL + so, xl + goA);
        cp16(sbase + OFF3_BH + so, bh + goB);
        cp16(sbase + OFF3_BL + so, bl + goB);
    }
    asm volatile("cp.async.commit_group;\n" ::: "memory");
}

__device__ __forceinline__ void compute_chunk3(uint32_t sbase, float (*acc)[4][4],
                                               int wm, int wn, int lane) {
    int r_off  = lane & 15;
    int ia_h   = (lane >> 4);               // A: k-half chunk select (0/1)
    int n_off  = (lane & 7) + ((lane >> 4) << 3);
    int ib_h   = ((lane >> 3) & 1);         // B: k-half chunk select (0/1)
#pragma unroll
    for (int kk = 0; kk < 4; kk++) {        // 4 x k16 per 64-chunk
        uint32_t ah[2][4], al[2][4], b[2][4];
        int ia = kk * 2 + ia_h;
        int ib = kk * 2 + ib_h;
#pragma unroll
        for (int im = 0; im < 2; im++) {
            int row = wm + im * 16 + r_off;
            uint32_t off = SWZ128(row, ia);
            LDSM4(ah[im], sbase + OFF3_AH + off);
            LDSM4(al[im], sbase + OFF3_AL + off);
        }
#pragma unroll
        for (int j = 0; j < 2; j++) {
            int row = wn + j * 16 + n_off;
            LDSM4(b[j], sbase + OFF3_BH + SWZ128(row, ib));
        }
        // pass 1: Ah*Bh
#pragma unroll
        for (int im = 0; im < 2; im++)
#pragma unroll
            for (int j = 0; j < 2; j++) {
                MMA_BF16(acc[im][2*j],   ah[im], b[j][0], b[j][1]);
                MMA_BF16(acc[im][2*j+1], ah[im], b[j][2], b[j][3]);
            }
        // pass 2: Al*Bh
#pragma unroll
        for (int im = 0; im < 2; im++)
#pragma unroll
            for (int j = 0; j < 2; j++) {
                MMA_BF16(acc[im][2*j],   al[im], b[j][0], b[j][1]);
                MMA_BF16(acc[im][2*j+1], al[im], b[j][2], b[j][3]);
            }
        // B-lo (recycle regs)
#pragma unroll
        for (int j = 0; j < 2; j++) {
            int row = wn + j * 16 + n_off;
            LDSM4(b[j], sbase + OFF3_BL + SWZ128(row, ib));
        }
        // pass 3: Ah*Bl
#pragma unroll
        for (int im = 0; im < 2; im++)
#pragma unroll
            for (int j = 0; j < 2; j++) {
                MMA_BF16(acc[im][2*j],   ah[im], b[j][0], b[j][1]);
                MMA_BF16(acc[im][2*j+1], ah[im], b[j][2], b[j][3]);
            }
    }
}

__global__ void __launch_bounds__(512, 1) gemm3_kernel(
    const float* __restrict__ b_sigma, const float* __restrict__ b_psi)
{
    extern __shared__ char smem[];
    uint32_t sb = smem_u32(smem);
    int tid = threadIdx.x;
    int wid = tid >> 5, lane = tid & 31;
    int nt = blockIdx.x & 7;        // N-tile fastest: A reuse in L2
    int mt = blockIdx.x >> 3;
    int m0 = mt * MTILE, n0 = 512 + nt * 128;   // concat cols 512..1535
    int wm = (wid >> 2) * 32, wn = (wid & 3) * 32;

    float acc[2][4][4];
#pragma unroll
    for (int a = 0; a < 2; a++)
#pragma unroll
        for (int b = 0; b < 4; b++)
#pragma unroll
            for (int c = 0; c < 4; c++) acc[a][b][c] = 0.f;

    load_chunk3(sb + 0 * STAGE3_BYTES, 0, m0, n0, tid);
    load_chunk3(sb + 1 * STAGE3_BYTES, 1, m0, n0, tid);

    for (int c = 0; c < NCH3; c++) {
        if (c < NCH3 - 1) asm volatile("cp.async.wait_group 1;" ::: "memory");
        else              asm volatile("cp.async.wait_group 0;" ::: "memory");
        __syncthreads();
        if (c + 2 < NCH3)
            load_chunk3(sb + ((c + 2) % 3) * STAGE3_BYTES, c + 2, m0, n0, tid);
        compute_chunk3(sb + (c % 3) * STAGE3_BYTES, acc, wm, wn, lane);
    }

    const float* bias = (nt < 4) ? b_sigma : b_psi;
    float* dest = (nt < 4) ? g_sig : g_psi;
    int colbase = (nt & 3) * 128;
    int groupID = lane >> 2, tig = lane & 3;

#pragma unroll
    for (int im = 0; im < 2; im++) {
#pragma unroll
        for (int in = 0; in < 4; in++) {
            int col = colbase + wn + in * 8 + tig * 2;
            float2 bv = __ldg((const float2*)&bias[col]);
            int row0 = m0 + wm + im * 16 + groupID;
            float2 v0, v1;
            v0.x = acc[im][in][0] + bv.x; v0.y = acc[im][in][1] + bv.y;
            v1.x = acc[im][in][2] + bv.x; v1.y = acc[im][in][3] + bv.y;
            *(float2*)&dest[(size_t)row0 * PDIM + col]       = v0;
            *(float2*)&dest[(size_t)(row0 + 8) * PDIM + col] = v1;
        }
    }
}

// ---------------------------------------------------------------------------
// gemm1: r_feat / v columns, fp16 single pass, 128x256 tile, 4-stage
// ---------------------------------------------------------------------------
__device__ __forceinline__ void load_chunk1(uint32_t sbase, int kc, int m0, int n0, int tid) {
    const char* xf = (const char*)g_xf;
    const char* bf = (const char*)g_wf;
    size_t kcoff = (size_t)kc * 128;
#pragma unroll
    for (int q = 0; q < 2; q++) {                 // A: 128 rows x 8 x 16B
        int j = tid + q * 512;
        int r = j >> 3, i = j & 7;
        uint32_t so = SWZ128(r, i);
        size_t goA = ((size_t)(m0 + r)) * (DIN * 2) + kcoff + i * 16;
        cp16(sbase + OFF_AF + so, xf + goA);
    }
#pragma unroll
    for (int q = 0; q < 4; q++) {                 // B: 256 rows x 8 x 16B
        int j = tid + q * 512;
        int r = j >> 3, i = j & 7;
        uint32_t so = SWZ128(r, i);
        size_t goB = ((size_t)(n0 + r)) * (DIN * 2) + kcoff + i * 16;
        cp16(sbase + OFF_BF + so, bf + goB);
    }
    asm volatile("cp.async.commit_group;\n" ::: "memory");
}

__device__ __forceinline__ void compute_chunk1(uint32_t sbase, float (*acc)[8][4],
                                               int wm, int wn, int lane) {
    int r_off  = lane & 15;
    int kseg   = (lane >> 4) << 3;
    int n_off  = (lane & 7) + ((lane >> 4) << 3);
    int ksegb  = ((lane >> 3) & 1) << 3;
#pragma unroll
    for (int kk = 0; kk < 4; kk++) {
        uint32_t af[2][4], b[4][4];
#pragma unroll
        for (int im = 0; im < 2; im++) {
            int row = wm + im * 16 + r_off;
            int kb = (kk * 16 + kseg) >> 3;       // chunk idx 0..7
            LDSM4(af[im], sbase + OFF_AF + SWZ128(row, kb));
        }
#pragma unroll
        for (int j = 0; j < 4; j++) {
            int row = wn + j * 16 + n_off;
            int kb = (kk * 16 + ksegb) >> 3;
            LDSM4(b[j], sbase + OFF_BF + SWZ128(row, kb));
        }
#pragma unroll
        for (int im = 0; im < 2; im++)
#pragma unroll
            for (int j = 0; j < 4; j++) {
                MMA_F16(acc[im][2*j],   af[im], b[j][0], b[j][1]);
                MMA_F16(acc[im][2*j+1], af[im], b[j][2], b[j][3]);
            }
    }
}

__global__ void __launch_bounds__(512, 1) gemm1_kernel(
    const float* __restrict__ b_proj, float* __restrict__ out_rfeat)
{
    extern __shared__ char smem[];
    uint32_t sb = smem_u32(smem);
    int tid = threadIdx.x;
    int wid = tid >> 5, lane = tid & 31;
    int nt = blockIdx.x & 3;
    int mt = blockIdx.x >> 2;
    int m0 = mt * MTILE;
    int n0 = (nt < 2) ? nt * 256 : 1536 + (nt - 2) * 256;
    int wm = (wid >> 2) * 32, wn = (wid & 3) * 64;

    float acc[2][8][4];
#pragma unroll
    for (int a = 0; a < 2; a++)
#pragma unroll
        for (int b = 0; b < 8; b++)
#pragma unroll
            for (int c = 0; c < 4; c++) acc[a][b][c] = 0.f;

    load_chunk1(sb + 0 * STAGE1_BYTES, 0, m0, n0, tid);
    load_chunk1(sb + 1 * STAGE1_BYTES, 1, m0, n0, tid);
    load_chunk1(sb + 2 * STAGE1_BYTES, 2, m0, n0, tid);

    for (int c = 0; c < NCH1; c++) {
        if (c < NCH1 - 2)       asm volatile("cp.async.wait_group 2;" ::: "memory");
        else if (c == NCH1 - 2) asm volatile("cp.async.wait_group 1;" ::: "memory");
        else                    asm volatile("cp.async.wait_group 0;" ::: "memory");
        __syncthreads();
        if (c + 3 < NCH1)
            load_chunk1(sb + ((c + 3) & 3) * STAGE1_BYTES, c + 3, m0, n0, tid);
        compute_chunk1(sb + (c & 3) * STAGE1_BYTES, acc, wm, wn, lane);
    }

    const float* bias = (nt < 2) ? b_proj : nullptr;
    float* dest = (nt < 2) ? out_rfeat : g_v;
    int colbase = (nt & 1) * 256;
    int groupID = lane >> 2, tig = lane & 3;

#pragma unroll
    for (int im = 0; im < 2; im++) {
#pragma unroll
        for (int in = 0; in < 8; in++) {
            int col = colbase + wn + in * 8 + tig * 2;
            float2 bv = make_float2(0.f, 0.f);
            if (bias) bv = __ldg((const float2*)&bias[col]);
            int row0 = m0 + wm + im * 16 + groupID;
            float2 v0, v1;
            v0.x = acc[im][in][0] + bv.x; v0.y = acc[im][in][1] + bv.y;
            v1.x = acc[im][in][2] + bv.x; v1.y = acc[im][in][3] + bv.y;
            *(float2*)&dest[(size_t)row0 * PDIM + col]       = v0;
            *(float2*)&dest[(size_t)(row0 + 8) * PDIM + col] = v1;
        }
    }
}

// ---------------------------------------------------------------------------
// Attention: per-head softmax(sig psi^T) @ v   (1 CTA per head, 256 threads,
// 2 CTAs/SM; v in smem; sig 6-way-broadcast loads, psi 6-distinct-row loads)
// ---------------------------------------------------------------------------
__global__ void __launch_bounds__(256, 2) attn_kernel(float* __restrict__ out_rhat) {
    extern __shared__ float as[];
    float* v_s = as;                          // 36*512
    float* l_s = as + NOBJ * PDIM;            // 36*36   logits, n-major
    float* l_t = l_s + NOBJ * NOBJ;           // 36*40   probs, m-major (padded)
    int h = blockIdx.x;
    int tid = threadIdx.x;
    size_t base = (size_t)h * NOBJ;

    const float4* gv = (const float4*)(g_v + base * PDIM);
    float4* sv = (float4*)v_s;
#pragma unroll
    for (int q = 0; q < 18; q++) {            // 4608 float4s
        int i = tid + q * 256;
        sv[i] = gv[i];
    }
    __syncthreads();

    // logits: l[n][m] = dot(sig[n], psi[m]); thread (n = tid/6, g = tid%6)
    if (tid < 216) {
        int n = tid / 6, g = tid % 6;
        float a0 = 0, a1 = 0, a2 = 0, a3 = 0, a4 = 0, a5 = 0;
        const float4* sg = (const float4*)(g_sig + (base + n) * PDIM);
        const float4* p0 = (const float4*)(g_psi + (base + g +  0) * PDIM);
        const float4* p1 = (const float4*)(g_psi + (base + g +  6) * PDIM);
        const float4* p2 = (const float4*)(g_psi + (base + g + 12) * PDIM);
        const float4* p3 = (const float4*)(g_psi + (base + g + 18) * PDIM);
        const float4* p4 = (const float4*)(g_psi + (base + g + 24) * PDIM);
        const float4* p5 = (const float4*)(g_psi + (base + g + 30) * PDIM);
        for (int k = 0; k < 128; k++) {
            float4 s = __ldg(&sg[k]);
            float4 p;
            p = __ldg(&p0[k]); a0 += s.x * p.x + s.y * p.y + s.z * p.z + s.w * p.w;
            p = __ldg(&p1[k]); a1 += s.x * p.x + s.y * p.y + s.z * p.z + s.w * p.w;
            p = __ldg(&p2[k]); a2 += s.x * p.x + s.y * p.y + s.z * p.z + s.w * p.w;
            p = __ldg(&p3[k]); a3 += s.x * p.x + s.y * p.y + s.z * p.z + s.w * p.w;
            p = __ldg(&p4[k]); a4 += s.x * p.x + s.y * p.y + s.z * p.z + s.w * p.w;
            p = __ldg(&p5[k]); a5 += s.x * p.x + s.y * p.y + s.z * p.z + s.w * p.w;
        }
        l_s[n * 36 + g +  0] = a0;
        l_s[n * 36 + g +  6] = a1;
        l_s[n * 36 + g + 12] = a2;
        l_s[n * 36 + g + 18] = a3;
        l_s[n * 36 + g + 24] = a4;
        l_s[n * 36 + g + 30] = a5;
    }
    __syncthreads();

    // row softmax; write probs transposed (m-major) for vectorized AV loads
    if (tid < 36) {
        float row[36];
        float m = -1e30f;
#pragma unroll
        for (int j = 0; j < 36; j++) { row[j] = l_s[tid * 36 + j]; m = fmaxf(m, row[j]); }
        float ssum = 0.f;
#pragma unroll
        for (int j = 0; j < 36; j++) { float e = __expf(row[j] - m); row[j] = e; ssum += e; }
        float inv = 1.f / ssum;
#pragma unroll
        for (int j = 0; j < 36; j++) l_t[j * 40 + tid] = row[j] * inv;
    }
    __syncthreads();

    // AV: out[n][p] = sum_m a[n][m] v[m][p]; each thread: 1 col-chunk x 18 rows
    int c4 = tid & 127, nh = tid >> 7;
    float4 acc[18];
#pragma unroll
    for (int j = 0; j < 18; j++) acc[j] = make_float4(0.f, 0.f, 0.f, 0.f);
    const float4* vrow = (const float4*)v_s + c4;
#pragma unroll 4
    for (int m = 0; m < 36; m++) {
        float4 vv = vrow[m * 128];
#pragma unroll
        for (int jj = 0; jj < 9; jj++) {
            float2 aa = *(const float2*)&l_t[m * 40 + nh * 18 + jj * 2];
            acc[2*jj].x   += aa.x * vv.x; acc[2*jj].y   += aa.x * vv.y;
            acc[2*jj].z   += aa.x * vv.z; acc[2*jj].w   += aa.x * vv.w;
            acc[2*jj+1].x += aa.y * vv.x; acc[2*jj+1].y += aa.y * vv.y;
            acc[2*jj+1].z += aa.y * vv.z; acc[2*jj+1].w += aa.y * vv.w;
        }
    }
    float4* vo = (float4*)(out_rhat + base * PDIM);
#pragma unroll
    for (int j = 0; j < 18; j++) {
        int n = nh * 18 + j;
        vo[n * 128 + c4] = acc[j];
    }
}

// ---------------------------------------------------------------------------
// Launcher
// ---------------------------------------------------------------------------
extern "C" void kernel_launch(void* const* d_in, const int* in_sizes, int n_in,
                              void* d_out, int out_size) {
    const float* x       = (const float*)d_in[0];
    const float* W_proj  = (const float*)d_in[1];
    const float* b_proj  = (const float*)d_in[2];
    const float* W_sigma = (const float*)d_in[3];
    const float* b_sigma = (const float*)d_in[4];
    const float* W_psi   = (const float*)d_in[5];
    const float* b_psi   = (const float*)d_in[6];
    const float* W_r     = (const float*)d_in[7];
    float* out = (float*)d_out;

    cudaFuncSetAttribute(gemm3_kernel, cudaFuncAttributeMaxDynamicSharedMemorySize, GEMM3_SMEM);
    cudaFuncSetAttribute(gemm1_kernel, cudaFuncAttributeMaxDynamicSharedMemorySize, GEMM1_SMEM);
    cudaFuncSetAttribute(attn_kernel, cudaFuncAttributeMaxDynamicSharedMemorySize, ATTN_SMEM);

    long n4 = (long)MROWS * DIN / 4;
    split_x_kernel<<<8192, 256>>>(x, n4);
    split_w_kernel<<<(NCAT * DIN + 255) / 256, 256>>>(W_proj, W_sigma, W_psi, W_r);
    gemm3_kernel<<<(MROWS / MTILE) * 8, 512, GEMM3_SMEM>>>(b_sigma, b_psi);
    gemm1_kernel<<<(MROWS / MTILE) * 4, 512, GEMM1_SMEM>>>(b_proj, out);
    attn_kernel<<<HEADS, 256, ATTN_SMEM>>>(out + OUT_HALF);
}

// round 9
// speedup vs baseline: 1.0713x; 1.0304x over previous
#include <cuda_runtime.h>
#include <cuda_bf16.h>
#include <cuda_fp16.h>
#include <cstdint>

// ---------------------------------------------------------------------------
// Problem constants
// ---------------------------------------------------------------------------
#define BATCH   32
#define FRAMES  32
#define NOBJ    36
#define DIN     2048
#define PDIM    512
#define MROWS   (BATCH*FRAMES*NOBJ)     // 36864
#define HEADS   (BATCH*FRAMES)          // 1024
#define NCAT    (4*PDIM)                // 2048 concat output cols

#define MTILE   128
#define NTILE   256
#define NCH     (DIN/64)                // 32 K-chunks of 64

// gemm3 (bf16 3-pass): AH 16K | AL 16K | BH 32K | BL 32K = 96K/stage, 2 stages
#define OFF_AH  0
#define OFF_AL  16384
#define OFF_BH  32768
#define OFF_BL  65536
#define STAGE3_BYTES 98304

// gemm1 (fp16 1-pass): AF 16K | BF 32K = 48K/stage, 4 stages
#define OFF_AF  0
#define OFF_BF  16384
#define STAGE1_BYTES 49152

#define GEMM_SMEM 196608
#define NB3 1152                        // gemm3 CTAs (first in grid)

// attention smem: v (36*512 f32) + logits (36*36) + transposed probs (36*40)
#define ATTN_SMEM  ((NOBJ*PDIM + NOBJ*NOBJ + NOBJ*40)*4)   // 84672 bytes

#define OUT_HALF   ((size_t)MROWS*PDIM)

// ---------------------------------------------------------------------------
// Device scratch
// ---------------------------------------------------------------------------
__device__ __nv_bfloat16 g_xh[(size_t)MROWS*DIN];
__device__ __nv_bfloat16 g_xl[(size_t)MROWS*DIN];
__device__ __half        g_xf[(size_t)MROWS*DIN];
__device__ __nv_bfloat16 g_wth[(size_t)NCAT*DIN];   // [n][k], K-major (sig/psi rows)
__device__ __nv_bfloat16 g_wtl[(size_t)NCAT*DIN];
__device__ __half        g_wf [(size_t)NCAT*DIN];   // [n][k], K-major (proj/r rows)
__device__ float g_sig[(size_t)MROWS*PDIM];
__device__ float g_psi[(size_t)MROWS*PDIM];
__device__ float g_v  [(size_t)MROWS*PDIM];

// ---------------------------------------------------------------------------
// PTX helpers
// ---------------------------------------------------------------------------
__device__ __forceinline__ uint32_t smem_u32(const void* p) {
    uint32_t a;
    asm("{ .reg .u64 t; cvta.to.shared.u64 t, %1; cvt.u32.u64 %0, t; }"
        : "=r"(a) : "l"(p));
    return a;
}

__device__ __forceinline__ void cp16(uint32_t s, const void* g) {
    asm volatile("cp.async.cg.shared.global [%0], [%1], 16;\n" :: "r"(s), "l"(g) : "memory");
}

#define LDSM4(R, A) \
    asm volatile("ldmatrix.sync.aligned.m8n8.x4.shared.b16 {%0,%1,%2,%3}, [%4];" \
        : "=r"((R)[0]), "=r"((R)[1]), "=r"((R)[2]), "=r"((R)[3]) : "r"(A))

#define MMA_BF16(C, A, B0, B1) \
    asm volatile("mma.sync.aligned.m16n8k16.row.col.f32.bf16.bf16.f32 " \
        "{%0,%1,%2,%3}, {%4,%5,%6,%7}, {%8,%9}, {%0,%1,%2,%3};" \
        : "+f"((C)[0]), "+f"((C)[1]), "+f"((C)[2]), "+f"((C)[3]) \
        : "r"((A)[0]), "r"((A)[1]), "r"((A)[2]), "r"((A)[3]), "r"(B0), "r"(B1))

#define MMA_F16(C, A, B0, B1) \
    asm volatile("mma.sync.aligned.m16n8k16.row.col.f32.f16.f16.f32 " \
        "{%0,%1,%2,%3}, {%4,%5,%6,%7}, {%8,%9}, {%0,%1,%2,%3};" \
        : "+f"((C)[0]), "+f"((C)[1]), "+f"((C)[2]), "+f"((C)[3]) \
        : "r"((A)[0]), "r"((A)[1]), "r"((A)[2]), "r"((A)[3]), "r"(B0), "r"(B1))

// 128B-row swizzle: chunk i in 0..7
#define SWZ128(r, i) ((uint32_t)((r) * 128 + (((i) * 16) ^ (((r) & 7) << 4))))

// ---------------------------------------------------------------------------
// Prep kernels: fp32 -> bf16 hi/lo (sig/psi path) and fp16 (proj/v path)
// ---------------------------------------------------------------------------
__global__ void split_x_kernel(const float* __restrict__ x, long n4) {
    long i = blockIdx.x * (long)blockDim.x + threadIdx.x;
    long stride = (long)gridDim.x * blockDim.x;
    __nv_bfloat162* xh2 = reinterpret_cast<__nv_bfloat162*>(g_xh);
    __nv_bfloat162* xl2 = reinterpret_cast<__nv_bfloat162*>(g_xl);
    __half2*        xf2 = reinterpret_cast<__half2*>(g_xf);
    for (; i < n4; i += stride) {
        float4 v = reinterpret_cast<const float4*>(x)[i];
        __nv_bfloat16 h0 = __float2bfloat16(v.x);
        __nv_bfloat16 h1 = __float2bfloat16(v.y);
        __nv_bfloat16 h2 = __float2bfloat16(v.z);
        __nv_bfloat16 h3 = __float2bfloat16(v.w);
        __nv_bfloat16 l0 = __float2bfloat16(v.x - __bfloat162float(h0));
        __nv_bfloat16 l1 = __float2bfloat16(v.y - __bfloat162float(h1));
        __nv_bfloat16 l2 = __float2bfloat16(v.z - __bfloat162float(h2));
        __nv_bfloat16 l3 = __float2bfloat16(v.w - __bfloat162float(h3));
        __nv_bfloat162 hA; hA.x = h0; hA.y = h1;
        __nv_bfloat162 hB; hB.x = h2; hB.y = h3;
        __nv_bfloat162 lA; lA.x = l0; lA.y = l1;
        __nv_bfloat162 lB; lB.x = l2; lB.y = l3;
        xh2[2*i]   = hA; xh2[2*i+1] = hB;
        xl2[2*i]   = lA; xl2[2*i+1] = lB;
        xf2[2*i]   = __floats2half2_rn(v.x, v.y);
        xf2[2*i+1] = __floats2half2_rn(v.z, v.w);
    }
}

__global__ void split_w_kernel(const float* __restrict__ Wp, const float* __restrict__ Ws,
                               const float* __restrict__ Wq, const float* __restrict__ Wr) {
    long t = blockIdx.x * (long)blockDim.x + threadIdx.x;   // over NCAT*DIN
    if (t >= (long)NCAT * DIN) return;
    int n = (int)(t >> 11);        // /DIN
    int k = (int)(t & (DIN - 1));
    int mat = n >> 9, p = n & 511;
    const float* W = (mat == 0) ? Wp : (mat == 1) ? Ws : (mat == 2) ? Wq : Wr;
    float w = W[(size_t)k * PDIM + p];
    if (mat == 1 || mat == 2) {
        __nv_bfloat16 h = __float2bfloat16(w);
        g_wth[t] = h;
        g_wtl[t] = __float2bfloat16(w - __bfloat162float(h));
    } else {
        g_wf[t] = __float2half_rn(w);
    }
}

// ---------------------------------------------------------------------------
// gemm3 path: sig/psi columns, bf16 3-pass, 128x256, 2-stage  (round-5 form)
// ---------------------------------------------------------------------------
__device__ __forceinline__ void load_chunk3(uint32_t sbase, int kc, int m0, int n0, int tid) {
    const char* xh = (const char*)g_xh;
    const char* xl = (const char*)g_xl;
    const char* bh = (const char*)g_wth;
    const char* bl = (const char*)g_wtl;
    size_t kcoff = (size_t)kc * 128;   // 64 bf16 = 128 bytes
#pragma unroll
    for (int q = 0; q < 2; q++) {                 // A: 128 rows x 8 x 16B
        int j = tid + q * 512;
        int r = j >> 3, i = j & 7;
        uint32_t so = SWZ128(r, i);
        size_t goA = ((size_t)(m0 + r)) * (DIN * 2) + kcoff + i * 16;
        cp16(sbase + OFF_AH + so, xh + goA);
        cp16(sbase + OFF_AL + so, xl + goA);
    }
#pragma unroll
    for (int q = 0; q < 4; q++) {                 // B: 256 rows x 8 x 16B
        int j = tid + q * 512;
        int r = j >> 3, i = j & 7;
        uint32_t so = SWZ128(r, i);
        size_t goB = ((size_t)(n0 + r)) * (DIN * 2) + kcoff + i * 16;
        cp16(sbase + OFF_BH + so, bh + goB);
        cp16(sbase + OFF_BL + so, bl + goB);
    }
    asm volatile("cp.async.commit_group;\n" ::: "memory");
}

__device__ __forceinline__ void compute_chunk3(uint32_t sbase, float (*acc)[8][4],
                                               int wm, int wn, int lane) {
    int r_off  = lane & 15;
    int kseg   = (lane >> 4) << 3;
    int n_off  = (lane & 7) + ((lane >> 4) << 3);
    int ksegb  = ((lane >> 3) & 1) << 3;
#pragma unroll
    for (int kk = 0; kk < 4; kk++) {
        uint32_t ah[2][4], al[2][4], b[4][4];
#pragma unroll
        for (int im = 0; im < 2; im++) {
            int row = wm + im * 16 + r_off;
            int kb = (kk * 16 + kseg) >> 3;
            LDSM4(ah[im], sbase + OFF_AH + SWZ128(row, kb));
            LDSM4(al[im], sbase + OFF_AL + SWZ128(row, kb));
        }
#pragma unroll
        for (int j = 0; j < 4; j++) {
            int row = wn + j * 16 + n_off;
            int kb = (kk * 16 + ksegb) >> 3;
            LDSM4(b[j], sbase + OFF_BH + SWZ128(row, kb));
        }
        // pass 1: Ah*Bh  (16 independent accumulator chains)
#pragma unroll
        for (int im = 0; im < 2; im++)
#pragma unroll
            for (int j = 0; j < 4; j++) {
                MMA_BF16(acc[im][2*j],   ah[im], b[j][0], b[j][1]);
                MMA_BF16(acc[im][2*j+1], ah[im], b[j][2], b[j][3]);
            }
        // pass 2: Al*Bh
#pragma unroll
        for (int im = 0; im < 2; im++)
#pragma unroll
            for (int j = 0; j < 4; j++) {
                MMA_BF16(acc[im][2*j],   al[im], b[j][0], b[j][1]);
                MMA_BF16(acc[im][2*j+1], al[im], b[j][2], b[j][3]);
            }
        // B-lo (recycle regs)
#pragma unroll
        for (int j = 0; j < 4; j++) {
            int row = wn + j * 16 + n_off;
            int kb = (kk * 16 + ksegb) >> 3;
            LDSM4(b[j], sbase + OFF_BL + SWZ128(row, kb));
        }
        // pass 3: Ah*Bl
#pragma unroll
        for (int im = 0; im < 2; im++)
#pragma unroll
            for (int j = 0; j < 4; j++) {
                MMA_BF16(acc[im][2*j],   ah[im], b[j][0], b[j][1]);
                MMA_BF16(acc[im][2*j+1], ah[im], b[j][2], b[j][3]);
            }
    }
}

// ---------------------------------------------------------------------------
// gemm1 path: r_feat / v columns, fp16 1-pass, 128x256, 4-stage (round-7 form)
// ---------------------------------------------------------------------------
__device__ __forceinline__ void load_chunk1(uint32_t sbase, int kc, int m0, int n0, int tid) {
    const char* xf = (const char*)g_xf;
    const char* bf = (const char*)g_wf;
    size_t kcoff = (size_t)kc * 128;
#pragma unroll
    for (int q = 0; q < 2; q++) {                 // A: 128 rows x 8 x 16B
        int j = tid + q * 512;
        int r = j >> 3, i = j & 7;
        uint32_t so = SWZ128(r, i);
        size_t goA = ((size_t)(m0 + r)) * (DIN * 2) + kcoff + i * 16;
        cp16(sbase + OFF_AF + so, xf + goA);
    }
#pragma unroll
    for (int q = 0; q < 4; q++) {                 // B: 256 rows x 8 x 16B
        int j = tid + q * 512;
        int r = j >> 3, i = j & 7;
        uint32_t so = SWZ128(r, i);
        size_t goB = ((size_t)(n0 + r)) * (DIN * 2) + kcoff + i * 16;
        cp16(sbase + OFF_BF + so, bf + goB);
    }
    asm volatile("cp.async.commit_group;\n" ::: "memory");
}

__device__ __forceinline__ void compute_chunk1(uint32_t sbase, float (*acc)[8][4],
                                               int wm, int wn, int lane) {
    int r_off  = lane & 15;
    int kseg   = (lane >> 4) << 3;
    int n_off  = (lane & 7) + ((lane >> 4) << 3);
    int ksegb  = ((lane >> 3) & 1) << 3;
#pragma unroll
    for (int kk = 0; kk < 4; kk++) {
        uint32_t af[2][4], b[4][4];
#pragma unroll
        for (int im = 0; im < 2; im++) {
            int row = wm + im * 16 + r_off;
            int kb = (kk * 16 + kseg) >> 3;
            LDSM4(af[im], sbase + OFF_AF + SWZ128(row, kb));
        }
#pragma unroll
        for (int j = 0; j < 4; j++) {
            int row = wn + j * 16 + n_off;
            int kb = (kk * 16 + ksegb) >> 3;
            LDSM4(b[j], sbase + OFF_BF + SWZ128(row, kb));
        }
#pragma unroll
        for (int im = 0; im < 2; im++)
#pragma unroll
            for (int j = 0; j < 4; j++) {
                MMA_F16(acc[im][2*j],   af[im], b[j][0], b[j][1]);
                MMA_F16(acc[im][2*j+1], af[im], b[j][2], b[j][3]);
            }
    }
}

// ---------------------------------------------------------------------------
// Fused GEMM kernel: blocks [0,1152) = gemm3 (sig/psi), [1152,2304) = gemm1.
// gemm3 blocks dispatch first (longer CTAs); gemm1 backfills their tail.
// ---------------------------------------------------------------------------
__global__ void __launch_bounds__(512, 1) gemm_fused_kernel(
    const float* __restrict__ b_sigma, const float* __restrict__ b_psi,
    const float* __restrict__ b_proj, float* __restrict__ out_rfeat)
{
    extern __shared__ char smem[];
    uint32_t sb = smem_u32(smem);
    int tid = threadIdx.x;
    int wid = tid >> 5, lane = tid & 31;
    int wm = (wid >> 2) * 32, wn = (wid & 3) * 64;

    float acc[2][8][4];
#pragma unroll
    for (int a = 0; a < 2; a++)
#pragma unroll
        for (int b = 0; b < 8; b++)
#pragma unroll
            for (int c = 0; c < 4; c++) acc[a][b][c] = 0.f;

    if (blockIdx.x < NB3) {
        // ---- gemm3: bf16 3-pass over concat cols 512..1535 ----
        int bid = blockIdx.x;
        int nt = bid & 3, mt = bid >> 2;
        int m0 = mt * MTILE, n0 = 512 + nt * NTILE;

        load_chunk3(sb, 0, m0, n0, tid);
        for (int c = 0; c < NCH; c++) {
            if (c + 1 < NCH) {
                load_chunk3(sb + ((c + 1) & 1) * STAGE3_BYTES, c + 1, m0, n0, tid);
                asm volatile("cp.async.wait_group 1;" ::: "memory");
            } else {
                asm volatile("cp.async.wait_group 0;" ::: "memory");
            }
            __syncthreads();
            compute_chunk3(sb + (c & 1) * STAGE3_BYTES, acc, wm, wn, lane);
            __syncthreads();
        }

        const float* bias = (nt < 2) ? b_sigma : b_psi;
        float* dest = (nt < 2) ? g_sig : g_psi;
        int colbase = (nt & 1) * 256;
        int groupID = lane >> 2, tig = lane & 3;
#pragma unroll
        for (int im = 0; im < 2; im++)
#pragma unroll
            for (int in = 0; in < 8; in++) {
                int col = colbase + wn + in * 8 + tig * 2;
                float2 bv = __ldg((const float2*)&bias[col]);
                int row0 = m0 + wm + im * 16 + groupID;
                float2 v0, v1;
                v0.x = acc[im][in][0] + bv.x; v0.y = acc[im][in][1] + bv.y;
                v1.x = acc[im][in][2] + bv.x; v1.y = acc[im][in][3] + bv.y;
                *(float2*)&dest[(size_t)row0 * PDIM + col]       = v0;
                *(float2*)&dest[(size_t)(row0 + 8) * PDIM + col] = v1;
            }
    } else {
        // ---- gemm1: fp16 1-pass over concat cols 0..511 and 1536..2047 ----
        int bid = blockIdx.x - NB3;
        int nt = bid & 3, mt = bid >> 2;
        int m0 = mt * MTILE;
        int n0 = (nt < 2) ? nt * NTILE : 1536 + (nt - 2) * NTILE;

        load_chunk1(sb + 0 * STAGE1_BYTES, 0, m0, n0, tid);
        load_chunk1(sb + 1 * STAGE1_BYTES, 1, m0, n0, tid);
        load_chunk1(sb + 2 * STAGE1_BYTES, 2, m0, n0, tid);

        for (int c = 0; c < NCH; c++) {
            if (c < NCH - 2)       asm volatile("cp.async.wait_group 2;" ::: "memory");
            else if (c == NCH - 2) asm volatile("cp.async.wait_group 1;" ::: "memory");
            else                   asm volatile("cp.async.wait_group 0;" ::: "memory");
            __syncthreads();
            if (c + 3 < NCH)
                load_chunk1(sb + ((c + 3) & 3) * STAGE1_BYTES, c + 3, m0, n0, tid);
            compute_chunk1(sb + (c & 3) * STAGE1_BYTES, acc, wm, wn, lane);
        }

        const float* bias = (nt < 2) ? b_proj : nullptr;
        float* dest = (nt < 2) ? out_rfeat : g_v;
        int colbase = (nt & 1) * 256;
        int groupID = lane >> 2, tig = lane & 3;
#pragma unroll
        for (int im = 0; im < 2; im++)
#pragma unroll
            for (int in = 0; in < 8; in++) {
                int col = colbase + wn + in * 8 + tig * 2;
                float2 bv = make_float2(0.f, 0.f);
                if (bias) bv = __ldg((const float2*)&bias[col]);
                int row0 = m0 + wm + im * 16 + groupID;
                float2 v0, v1;
                v0.x = acc[im][in][0] + bv.x; v0.y = acc[im][in][1] + bv.y;
                v1.x = acc[im][in][2] + bv.x; v1.y = acc[im][in][3] + bv.y;
                *(float2*)&dest[(size_t)row0 * PDIM + col]       = v0;
                *(float2*)&dest[(size_t)(row0 + 8) * PDIM + col] = v1;
            }
    }
}

// ---------------------------------------------------------------------------
// Attention: per-head softmax(sig psi^T) @ v   (1 CTA per head, 256 threads,
// 2 CTAs/SM; v in smem; sig 6-way-broadcast loads, psi 6-distinct-row loads)
// ---------------------------------------------------------------------------
__global__ void __launch_bounds__(256, 2) attn_kernel(float* __restrict__ out_rhat) {
    extern __shared__ float as[];
    float* v_s = as;                          // 36*512
    float* l_s = as + NOBJ * PDIM;            // 36*36   logits, n-major
    float* l_t = l_s + NOBJ * NOBJ;           // 36*40   probs, m-major (padded)
    int h = blockIdx.x;
    int tid = threadIdx.x;
    size_t base = (size_t)h * NOBJ;

    const float4* gv = (const float4*)(g_v + base * PDIM);
    float4* sv = (float4*)v_s;
#pragma unroll
    for (int q = 0; q < 18; q++) {            // 4608 float4s
        int i = tid + q * 256;
        sv[i] = gv[i];
    }
    __syncthreads();

    // logits: l[n][m] = dot(sig[n], psi[m]); thread (n = tid/6, g = tid%6)
    if (tid < 216) {
        int n = tid / 6, g = tid % 6;
        float a0 = 0, a1 = 0, a2 = 0, a3 = 0, a4 = 0, a5 = 0;
        const float4* sg = (const float4*)(g_sig + (base + n) * PDIM);
        const float4* p0 = (const float4*)(g_psi + (base + g +  0) * PDIM);
        const float4* p1 = (const float4*)(g_psi + (base + g +  6) * PDIM);
        const float4* p2 = (const float4*)(g_psi + (base + g + 12) * PDIM);
        const float4* p3 = (const float4*)(g_psi + (base + g + 18) * PDIM);
        const float4* p4 = (const float4*)(g_psi + (base + g + 24) * PDIM);
        const float4* p5 = (const float4*)(g_psi + (base + g + 30) * PDIM);
        for (int k = 0; k < 128; k++) {
            float4 s = __ldg(&sg[k]);
            float4 p;
            p = __ldg(&p0[k]); a0 += s.x * p.x + s.y * p.y + s.z * p.z + s.w * p.w;
            p = __ldg(&p1[k]); a1 += s.x * p.x + s.y * p.y + s.z * p.z + s.w * p.w;
            p = __ldg(&p2[k]); a2 += s.x * p.x + s.y * p.y + s.z * p.z + s.w * p.w;
            p = __ldg(&p3[k]); a3 += s.x * p.x + s.y * p.y + s.z * p.z + s.w * p.w;
            p = __ldg(&p4[k]); a4 += s.x * p.x + s.y * p.y + s.z * p.z + s.w * p.w;
            p = __ldg(&p5[k]); a5 += s.x * p.x + s.y * p.y + s.z * p.z + s.w * p.w;
        }
        l_s[n * 36 + g +  0] = a0;
        l_s[n * 36 + g +  6] = a1;
        l_s[n * 36 + g + 12] = a2;
        l_s[n * 36 + g + 18] = a3;
        l_s[n * 36 + g + 24] = a4;
        l_s[n * 36 + g + 30] = a5;
    }
    __syncthreads();

    // row softmax; write probs transposed (m-major) for vectorized AV loads
    if (tid < 36) {
        float row[36];
        float m = -1e30f;
#pragma unroll
        for (int j = 0; j < 36; j++) { row[j] = l_s[tid * 36 + j]; m = fmaxf(m, row[j]); }
        float ssum = 0.f;
#pragma unroll
        for (int j = 0; j < 36; j++) { float e = __expf(row[j] - m); row[j] = e; ssum += e; }
        float inv = 1.f / ssum;
#pragma unroll
        for (int j = 0; j < 36; j++) l_t[j * 40 + tid] = row[j] * inv;
    }
    __syncthreads();

    // AV: out[n][p] = sum_m a[n][m] v[m][p]; each thread: 1 col-chunk x 18 rows
    int c4 = tid & 127, nh = tid >> 7;
    float4 acc[18];
#pragma unroll
    for (int j = 0; j < 18; j++) acc[j] = make_float4(0.f, 0.f, 0.f, 0.f);
    const float4* vrow = (const float4*)v_s + c4;
#pragma unroll 4
    for (int m = 0; m < 36; m++) {
        float4 vv = vrow[m * 128];
#pragma unroll
        for (int jj = 0; jj < 9; jj++) {
            float2 aa = *(const float2*)&l_t[m * 40 + nh * 18 + jj * 2];
            acc[2*jj].x   += aa.x * vv.x; acc[2*jj].y   += aa.x * vv.y;
            acc[2*jj].z   += aa.x * vv.z; acc[2*jj].w   += aa.x * vv.w;
            acc[2*jj+1].x += aa.y * vv.x; acc[2*jj+1].y += aa.y * vv.y;
            acc[2*jj+1].z += aa.y * vv.z; acc[2*jj+1].w += aa.y * vv.w;
        }
    }
    float4* vo = (float4*)(out_rhat + base * PDIM);
#pragma unroll
    for (int j = 0; j < 18; j++) {
        int n = nh * 18 + j;
        vo[n * 128 + c4] = acc[j];
    }
}

// ---------------------------------------------------------------------------
// Launcher
// ---------------------------------------------------------------------------
extern "C" void kernel_launch(void* const* d_in, const int* in_sizes, int n_in,
                              void* d_out, int out_size) {
    const float* x       = (const float*)d_in[0];
    const float* W_proj  = (const float*)d_in[1];
    const float* b_proj  = (const float*)d_in[2];
    const float* W_sigma = (const float*)d_in[3];
    const float* b_sigma = (const float*)d_in[4];
    const float* W_psi   = (const float*)d_in[5];
    const float* b_psi   = (const float*)d_in[6];
    const float* W_r     = (const float*)d_in[7];
    float* out = (float*)d_out;

    cudaFuncSetAttribute(gemm_fused_kernel, cudaFuncAttributeMaxDynamicSharedMemorySize, GEMM_SMEM);
    cudaFuncSetAttribute(attn_kernel, cudaFuncAttributeMaxDynamicSharedMemorySize, ATTN_SMEM);

    long n4 = (long)MROWS * DIN / 4;
    split_x_kernel<<<8192, 256>>>(x, n4);
    split_w_kernel<<<(NCAT * DIN + 255) / 256, 256>>>(W_proj, W_sigma, W_psi, W_r);
    gemm_fused_kernel<<<2 * NB3, 512, GEMM_SMEM>>>(b_sigma, b_psi, b_proj, out);
    attn_kernel<<<HEADS, 256, ATTN_SMEM>>>(out + OUT_HALF);
}

// round 10
// speedup vs baseline: 1.2127x; 1.1321x over previous
#include <cuda_runtime.h>
#include <cuda_bf16.h>
#include <cuda_fp16.h>
#include <cstdint>

// ---------------------------------------------------------------------------
// Problem constants
// ---------------------------------------------------------------------------
#define BATCH   32
#define FRAMES  32
#define NOBJ    36
#define DIN     2048
#define PDIM    512
#define MROWS   (BATCH*FRAMES*NOBJ)     // 36864
#define HEADS   (BATCH*FRAMES)          // 1024
#define NCAT    (4*PDIM)                // 2048 concat output cols

#define MTILE   128
#define NTILE   256
#define NCH     (DIN/64)                // 32 K-chunks of 64

// gemm3 (bf16 3-pass): AH 16K | AL 16K | BH 32K | BL 32K = 96K/stage, 2 stages
#define OFF_AH  0
#define OFF_AL  16384
#define OFF_BH  32768
#define OFF_BL  65536
#define STAGE3_BYTES 98304

// gemm1 (fp16 1-pass): AF 16K | BF 32K = 48K/stage, 4 stages
#define OFF_AF  0
#define OFF_BF  16384
#define STAGE1_BYTES 49152

#define GEMM_SMEM 196608
#define NB3 1152                        // gemm3 CTAs (first in grid)

// attention smem: v (36*512 f32) + logits (36*36) + transposed probs (36*40)
#define ATTN_SMEM  ((NOBJ*PDIM + NOBJ*NOBJ + NOBJ*40)*4)   // 84672 bytes

#define OUT_HALF   ((size_t)MROWS*PDIM)

// ---------------------------------------------------------------------------
// Device scratch
// ---------------------------------------------------------------------------
__device__ __nv_bfloat16 g_xh[(size_t)MROWS*DIN];
__device__ __nv_bfloat16 g_xl[(size_t)MROWS*DIN];
__device__ __half        g_xf[(size_t)MROWS*DIN];
__device__ __nv_bfloat16 g_wth[(size_t)NCAT*DIN];   // [n][k], K-major (sig/psi rows)
__device__ __nv_bfloat16 g_wtl[(size_t)NCAT*DIN];
__device__ __half        g_wf [(size_t)NCAT*DIN];   // [n][k], K-major (proj/r rows)
__device__ float g_sig[(size_t)MROWS*PDIM];
__device__ float g_psi[(size_t)MROWS*PDIM];
__device__ float g_v  [(size_t)MROWS*PDIM];

// ---------------------------------------------------------------------------
// PTX helpers
// ---------------------------------------------------------------------------
__device__ __forceinline__ uint32_t smem_u32(const void* p) {
    uint32_t a;
    asm("{ .reg .u64 t; cvta.to.shared.u64 t, %1; cvt.u32.u64 %0, t; }"
        : "=r"(a) : "l"(p));
    return a;
}

__device__ __forceinline__ void cp16(uint32_t s, const void* g) {
    asm volatile("cp.async.cg.shared.global [%0], [%1], 16;\n" :: "r"(s), "l"(g) : "memory");
}

#define LDSM4(R, A) \
    asm volatile("ldmatrix.sync.aligned.m8n8.x4.shared.b16 {%0,%1,%2,%3}, [%4];" \
        : "=r"((R)[0]), "=r"((R)[1]), "=r"((R)[2]), "=r"((R)[3]) : "r"(A))

#define MMA_BF16(C, A, B0, B1) \
    asm volatile("mma.sync.aligned.m16n8k16.row.col.f32.bf16.bf16.f32 " \
        "{%0,%1,%2,%3}, {%4,%5,%6,%7}, {%8,%9}, {%0,%1,%2,%3};" \
        : "+f"((C)[0]), "+f"((C)[1]), "+f"((C)[2]), "+f"((C)[3]) \
        : "r"((A)[0]), "r"((A)[1]), "r"((A)[2]), "r"((A)[3]), "r"(B0), "r"(B1))

#define MMA_F16(C, A, B0, B1) \
    asm volatile("mma.sync.aligned.m16n8k16.row.col.f32.f16.f16.f32 " \
        "{%0,%1,%2,%3}, {%4,%5,%6,%7}, {%8,%9}, {%0,%1,%2,%3};" \
        : "+f"((C)[0]), "+f"((C)[1]), "+f"((C)[2]), "+f"((C)[3]) \
        : "r"((A)[0]), "r"((A)[1]), "r"((A)[2]), "r"((A)[3]), "r"(B0), "r"(B1))

// 128B-row swizzle: chunk i in 0..7
#define SWZ128(r, i) ((uint32_t)((r) * 128 + (((i) * 16) ^ (((r) & 7) << 4))))

// ---------------------------------------------------------------------------
// Prep kernels: fp32 -> bf16 hi/lo (sig/psi path) and fp16 (proj/v path)
// ---------------------------------------------------------------------------
__global__ void split_x_kernel(const float* __restrict__ x, long n4) {
    long i = blockIdx.x * (long)blockDim.x + threadIdx.x;
    long stride = (long)gridDim.x * blockDim.x;
    __nv_bfloat162* xh2 = reinterpret_cast<__nv_bfloat162*>(g_xh);
    __nv_bfloat162* xl2 = reinterpret_cast<__nv_bfloat162*>(g_xl);
    __half2*        xf2 = reinterpret_cast<__half2*>(g_xf);
    for (; i < n4; i += stride) {
        float4 v = reinterpret_cast<const float4*>(x)[i];
        __nv_bfloat16 h0 = __float2bfloat16(v.x);
        __nv_bfloat16 h1 = __float2bfloat16(v.y);
        __nv_bfloat16 h2 = __float2bfloat16(v.z);
        __nv_bfloat16 h3 = __float2bfloat16(v.w);
        __nv_bfloat16 l0 = __float2bfloat16(v.x - __bfloat162float(h0));
        __nv_bfloat16 l1 = __float2bfloat16(v.y - __bfloat162float(h1));
        __nv_bfloat16 l2 = __float2bfloat16(v.z - __bfloat162float(h2));
        __nv_bfloat16 l3 = __float2bfloat16(v.w - __bfloat162float(h3));
        __nv_bfloat162 hA; hA.x = h0; hA.y = h1;
        __nv_bfloat162 hB; hB.x = h2; hB.y = h3;
        __nv_bfloat162 lA; lA.x = l0; lA.y = l1;
        __nv_bfloat162 lB; lB.x = l2; lB.y = l3;
        xh2[2*i]   = hA; xh2[2*i+1] = hB;
        xl2[2*i]   = lA; xl2[2*i+1] = lB;
        xf2[2*i]   = __floats2half2_rn(v.x, v.y);
        xf2[2*i+1] = __floats2half2_rn(v.z, v.w);
    }
}

__global__ void split_w_kernel(const float* __restrict__ Wp, const float* __restrict__ Ws,
                               const float* __restrict__ Wq, const float* __restrict__ Wr) {
    long t = blockIdx.x * (long)blockDim.x + threadIdx.x;   // over NCAT*DIN
    if (t >= (long)NCAT * DIN) return;
    int n = (int)(t >> 11);        // /DIN
    int k = (int)(t & (DIN - 1));
    int mat = n >> 9, p = n & 511;
    const float* W = (mat == 0) ? Wp : (mat == 1) ? Ws : (mat == 2) ? Wq : Wr;
    float w = W[(size_t)k * PDIM + p];
    if (mat == 1 || mat == 2) {
        __nv_bfloat16 h = __float2bfloat16(w);
        g_wth[t] = h;
        g_wtl[t] = __float2bfloat16(w - __bfloat162float(h));
    } else {
        g_wf[t] = __float2half_rn(w);
    }
}

// ---------------------------------------------------------------------------
// gemm3 path: sig/psi columns, bf16 3-pass, 128x256, 2-stage  (round-5 form)
// ---------------------------------------------------------------------------
__device__ __forceinline__ void load_chunk3(uint32_t sbase, int kc, int m0, int n0, int tid) {
    const char* xh = (const char*)g_xh;
    const char* xl = (const char*)g_xl;
    const char* bh = (const char*)g_wth;
    const char* bl = (const char*)g_wtl;
    size_t kcoff = (size_t)kc * 128;   // 64 bf16 = 128 bytes
#pragma unroll
    for (int q = 0; q < 2; q++) {                 // A: 128 rows x 8 x 16B
        int j = tid + q * 512;
        int r = j >> 3, i = j & 7;
        uint32_t so = SWZ128(r, i);
        size_t goA = ((size_t)(m0 + r)) * (DIN * 2) + kcoff + i * 16;
        cp16(sbase + OFF_AH + so, xh + goA);
        cp16(sbase + OFF_AL + so, xl + goA);
    }
#pragma unroll
    for (int q = 0; q < 4; q++) {                 // B: 256 rows x 8 x 16B
        int j = tid + q * 512;
        int r = j >> 3, i = j & 7;
        uint32_t so = SWZ128(r, i);
        size_t goB = ((size_t)(n0 + r)) * (DIN * 2) + kcoff + i * 16;
        cp16(sbase + OFF_BH + so, bh + goB);
        cp16(sbase + OFF_BL + so, bl + goB);
    }
    asm volatile("cp.async.commit_group;\n" ::: "memory");
}

__device__ __forceinline__ void compute_chunk3(uint32_t sbase, float (*acc)[8][4],
                                               int wm, int wn, int lane) {
    int r_off  = lane & 15;
    int kseg   = (lane >> 4) << 3;
    int n_off  = (lane & 7) + ((lane >> 4) << 3);
    int ksegb  = ((lane >> 3) & 1) << 3;
#pragma unroll
    for (int kk = 0; kk < 4; kk++) {
        uint32_t ah[2][4], al[2][4], b[4][4];
#pragma unroll
        for (int im = 0; im < 2; im++) {
            int row = wm + im * 16 + r_off;
            int kb = (kk * 16 + kseg) >> 3;
            LDSM4(ah[im], sbase + OFF_AH + SWZ128(row, kb));
            LDSM4(al[im], sbase + OFF_AL + SWZ128(row, kb));
        }
#pragma unroll
        for (int j = 0; j < 4; j++) {
            int row = wn + j * 16 + n_off;
            int kb = (kk * 16 + ksegb) >> 3;
            LDSM4(b[j], sbase + OFF_BH + SWZ128(row, kb));
        }
        // pass 1: Ah*Bh  (16 independent accumulator chains)
#pragma unroll
        for (int im = 0; im < 2; im++)
#pragma unroll
            for (int j = 0; j < 4; j++) {
                MMA_BF16(acc[im][2*j],   ah[im], b[j][0], b[j][1]);
                MMA_BF16(acc[im][2*j+1], ah[im], b[j][2], b[j][3]);
            }
        // pass 2: Al*Bh
#pragma unroll
        for (int im = 0; im < 2; im++)
#pragma unroll
            for (int j = 0; j < 4; j++) {
                MMA_BF16(acc[im][2*j],   al[im], b[j][0], b[j][1]);
                MMA_BF16(acc[im][2*j+1], al[im], b[j][2], b[j][3]);
            }
        // B-lo (recycle regs)
#pragma unroll
        for (int j = 0; j < 4; j++) {
            int row = wn + j * 16 + n_off;
            int kb = (kk * 16 + ksegb) >> 3;
            LDSM4(b[j], sbase + OFF_BL + SWZ128(row, kb));
        }
        // pass 3: Ah*Bl
#pragma unroll
        for (int im = 0; im < 2; im++)
#pragma unroll
            for (int j = 0; j < 4; j++) {
                MMA_BF16(acc[im][2*j],   ah[im], b[j][0], b[j][1]);
                MMA_BF16(acc[im][2*j+1], ah[im], b[j][2], b[j][3]);
            }
    }
}

// ---------------------------------------------------------------------------
// gemm1 path: r_feat / v columns, fp16 1-pass, 128x256, 4-stage (round-7 form)
// ---------------------------------------------------------------------------
__device__ __forceinline__ void load_chunk1(uint32_t sbase, int kc, int m0, int n0, int tid) {
    const char* xf = (const char*)g_xf;
    const char* bf = (const char*)g_wf;
    size_t kcoff = (size_t)kc * 128;
#pragma unroll
    for (int q = 0; q < 2; q++) {                 // A: 128 rows x 8 x 16B
        int j = tid + q * 512;
        int r = j >> 3, i = j & 7;
        uint32_t so = SWZ128(r, i);
        size_t goA = ((size_t)(m0 + r)) * (DIN * 2) + kcoff + i * 16;
        cp16(sbase + OFF_AF + so, xf + goA);
    }
#pragma unroll
    for (int q = 0; q < 4; q++) {                 // B: 256 rows x 8 x 16B
        int j = tid + q * 512;
        int r = j >> 3, i = j & 7;
        uint32_t so = SWZ128(r, i);
        size_t goB = ((size_t)(n0 + r)) * (DIN * 2) + kcoff + i * 16;
        cp16(sbase + OFF_BF + so, bf + goB);
    }
    asm volatile("cp.async.commit_group;\n" ::: "memory");
}

__device__ __forceinline__ void compute_chunk1(uint32_t sbase, float (*acc)[8][4],
                                               int wm, int wn, int lane) {
    int r_off  = lane & 15;
    int kseg   = (lane >> 4) << 3;
    int n_off  = (lane & 7) + ((lane >> 4) << 3);
    int ksegb  = ((lane >> 3) & 1) << 3;
#pragma unroll
    for (int kk = 0; kk < 4; kk++) {
        uint32_t af[2][4], b[4][4];
#pragma unroll
        for (int im = 0; im < 2; im++) {
            int row = wm + im * 16 + r_off;
            int kb = (kk * 16 + kseg) >> 3;
            LDSM4(af[im], sbase + OFF_AF + SWZ128(row, kb));
        }
#pragma unroll
        for (int j = 0; j < 4; j++) {
            int row = wn + j * 16 + n_off;
            int kb = (kk * 16 + ksegb) >> 3;
            LDSM4(b[j], sbase + OFF_BF + SWZ128(row, kb));
        }
#pragma unroll
        for (int im = 0; im < 2; im++)
#pragma unroll
            for (int j = 0; j < 4; j++) {
                MMA_F16(acc[im][2*j],   af[im], b[j][0], b[j][1]);
                MMA_F16(acc[im][2*j+1], af[im], b[j][2], b[j][3]);
            }
    }
}

// ---------------------------------------------------------------------------
// Fused GEMM kernel: blocks [0,1152) = gemm3 (sig/psi), [1152,2304) = gemm1.
// ---------------------------------------------------------------------------
__global__ void __launch_bounds__(512, 1) gemm_fused_kernel(
    const float* __restrict__ b_sigma, const float* __restrict__ b_psi,
    const float* __restrict__ b_proj, float* __restrict__ out_rfeat)
{
    extern __shared__ char smem[];
    uint32_t sb = smem_u32(smem);
    int tid = threadIdx.x;
    int wid = tid >> 5, lane = tid & 31;
    int wm = (wid >> 2) * 32, wn = (wid & 3) * 64;

    float acc[2][8][4];
#pragma unroll
    for (int a = 0; a < 2; a++)
#pragma unroll
        for (int b = 0; b < 8; b++)
#pragma unroll
            for (int c = 0; c < 4; c++) acc[a][b][c] = 0.f;

    if (blockIdx.x < NB3) {
        // ---- gemm3: bf16 3-pass over concat cols 512..1535 ----
        int bid = blockIdx.x;
        int nt = bid & 3, mt = bid >> 2;
        int m0 = mt * MTILE, n0 = 512 + nt * NTILE;

        load_chunk3(sb, 0, m0, n0, tid);
        for (int c = 0; c < NCH; c++) {
            if (c + 1 < NCH) {
                load_chunk3(sb + ((c + 1) & 1) * STAGE3_BYTES, c + 1, m0, n0, tid);
                asm volatile("cp.async.wait_group 1;" ::: "memory");
            } else {
                asm volatile("cp.async.wait_group 0;" ::: "memory");
            }
            __syncthreads();
            compute_chunk3(sb + (c & 1) * STAGE3_BYTES, acc, wm, wn, lane);
            __syncthreads();
        }

        const float* bias = (nt < 2) ? b_sigma : b_psi;
        float* dest = (nt < 2) ? g_sig : g_psi;
        int colbase = (nt & 1) * 256;
        int groupID = lane >> 2, tig = lane & 3;
#pragma unroll
        for (int im = 0; im < 2; im++)
#pragma unroll
            for (int in = 0; in < 8; in++) {
                int col = colbase + wn + in * 8 + tig * 2;
                float2 bv = __ldg((const float2*)&bias[col]);
                int row0 = m0 + wm + im * 16 + groupID;
                float2 v0, v1;
                v0.x = acc[im][in][0] + bv.x; v0.y = acc[im][in][1] + bv.y;
                v1.x = acc[im][in][2] + bv.x; v1.y = acc[im][in][3] + bv.y;
                *(float2*)&dest[(size_t)row0 * PDIM + col]       = v0;
                *(float2*)&dest[(size_t)(row0 + 8) * PDIM + col] = v1;
            }
    } else {
        // ---- gemm1: fp16 1-pass over concat cols 0..511 and 1536..2047 ----
        int bid = blockIdx.x - NB3;
        int nt = bid & 3, mt = bid >> 2;
        int m0 = mt * MTILE;
        int n0 = (nt < 2) ? nt * NTILE : 1536 + (nt - 2) * NTILE;

        load_chunk1(sb + 0 * STAGE1_BYTES, 0, m0, n0, tid);
        load_chunk1(sb + 1 * STAGE1_BYTES, 1, m0, n0, tid);
        load_chunk1(sb + 2 * STAGE1_BYTES, 2, m0, n0, tid);

        for (int c = 0; c < NCH; c++) {
            if (c < NCH - 2)       asm volatile("cp.async.wait_group 2;" ::: "memory");
            else if (c == NCH - 2) asm volatile("cp.async.wait_group 1;" ::: "memory");
            else                   asm volatile("cp.async.wait_group 0;" ::: "memory");
            __syncthreads();
            if (c + 3 < NCH)
                load_chunk1(sb + ((c + 3) & 3) * STAGE1_BYTES, c + 3, m0, n0, tid);
            compute_chunk1(sb + (c & 3) * STAGE1_BYTES, acc, wm, wn, lane);
        }

        const float* bias = (nt < 2) ? b_proj : nullptr;
        float* dest = (nt < 2) ? out_rfeat : g_v;
        int colbase = (nt & 1) * 256;
        int groupID = lane >> 2, tig = lane & 3;
#pragma unroll
        for (int im = 0; im < 2; im++)
#pragma unroll
            for (int in = 0; in < 8; in++) {
                int col = colbase + wn + in * 8 + tig * 2;
                float2 bv = make_float2(0.f, 0.f);
                if (bias) bv = __ldg((const float2*)&bias[col]);
                int row0 = m0 + wm + im * 16 + groupID;
                float2 v0, v1;
                v0.x = acc[im][in][0] + bv.x; v0.y = acc[im][in][1] + bv.y;
                v1.x = acc[im][in][2] + bv.x; v1.y = acc[im][in][3] + bv.y;
                *(float2*)&dest[(size_t)row0 * PDIM + col]       = v0;
                *(float2*)&dest[(size_t)(row0 + 8) * PDIM + col] = v1;
            }
    }
}

// ---------------------------------------------------------------------------
// Attention (round-5 proven form): per-head softmax(sig psi^T) @ v.
// 1 CTA per head, 256 threads, 2 CTAs/SM; v in smem; sig strided rows,
// psi single-address warp-broadcast streams.
// ---------------------------------------------------------------------------
__global__ void __launch_bounds__(256, 2) attn_kernel(float* __restrict__ out_rhat) {
    extern __shared__ float as[];
    float* v_s = as;                          // 36*512
    float* l_s = as + NOBJ * PDIM;            // 36*36   logits, n-major
    float* l_t = l_s + NOBJ * NOBJ;           // 36*40   probs, m-major (padded)
    int h = blockIdx.x;
    int tid = threadIdx.x;
    size_t base = (size_t)h * NOBJ;

    const float4* gv = (const float4*)(g_v + base * PDIM);
    float4* sv = (float4*)v_s;
#pragma unroll
    for (int q = 0; q < 18; q++) {            // 4608 float4s
        int i = tid + q * 256;
        sv[i] = gv[i];
    }
    __syncthreads();

    // logits: l[n][m] = dot(sig[n], psi[m]); n = tid%36 (strided rows),
    // g = tid/36 -> psi pointers identical across each warp (broadcast).
    if (tid < 216) {
        int n = tid % 36, g = tid / 36;
        float a0 = 0, a1 = 0, a2 = 0, a3 = 0, a4 = 0, a5 = 0;
        const float4* sg = (const float4*)(g_sig + (base + n) * PDIM);
        const float4* p0 = (const float4*)(g_psi + (base + g * 6 + 0) * PDIM);
        const float4* p1 = (const float4*)(g_psi + (base + g * 6 + 1) * PDIM);
        const float4* p2 = (const float4*)(g_psi + (base + g * 6 + 2) * PDIM);
        const float4* p3 = (const float4*)(g_psi + (base + g * 6 + 3) * PDIM);
        const float4* p4 = (const float4*)(g_psi + (base + g * 6 + 4) * PDIM);
        const float4* p5 = (const float4*)(g_psi + (base + g * 6 + 5) * PDIM);
        for (int k = 0; k < 128; k++) {
            float4 s = __ldg(&sg[k]);
            float4 p;
            p = __ldg(&p0[k]); a0 += s.x * p.x + s.y * p.y + s.z * p.z + s.w * p.w;
            p = __ldg(&p1[k]); a1 += s.x * p.x + s.y * p.y + s.z * p.z + s.w * p.w;
            p = __ldg(&p2[k]); a2 += s.x * p.x + s.y * p.y + s.z * p.z + s.w * p.w;
            p = __ldg(&p3[k]); a3 += s.x * p.x + s.y * p.y + s.z * p.z + s.w * p.w;
            p = __ldg(&p4[k]); a4 += s.x * p.x + s.y * p.y + s.z * p.z + s.w * p.w;
            p = __ldg(&p5[k]); a5 += s.x * p.x + s.y * p.y + s.z * p.z + s.w * p.w;
        }
        l_s[n * 36 + g * 6 + 0] = a0;
        l_s[n * 36 + g * 6 + 1] = a1;
        l_s[n * 36 + g * 6 + 2] = a2;
        l_s[n * 36 + g * 6 + 3] = a3;
        l_s[n * 36 + g * 6 + 4] = a4;
        l_s[n * 36 + g * 6 + 5] = a5;
    }
    __syncthreads();

    // row softmax; write probs transposed (m-major) for vectorized AV loads
    if (tid < 36) {
        float row[36];
        float m = -1e30f;
#pragma unroll
        for (int j = 0; j < 36; j++) { row[j] = l_s[tid * 36 + j]; m = fmaxf(m, row[j]); }
        float ssum = 0.f;
#pragma unroll
        for (int j = 0; j < 36; j++) { float e = __expf(row[j] - m); row[j] = e; ssum += e; }
        float inv = 1.f / ssum;
#pragma unroll
        for (int j = 0; j < 36; j++) l_t[j * 40 + tid] = row[j] * inv;
    }
    __syncthreads();

    // AV: out[n][p] = sum_m a[n][m] v[m][p]; each thread: 1 col-chunk x 18 rows
    int c4 = tid & 127, nh = tid >> 7;
    float4 acc[18];
#pragma unroll
    for (int j = 0; j < 18; j++) acc[j] = make_float4(0.f, 0.f, 0.f, 0.f);
    const float4* vrow = (const float4*)v_s + c4;
#pragma unroll 4
    for (int m = 0; m < 36; m++) {
        float4 vv = vrow[m * 128];
#pragma unroll
        for (int jj = 0; jj < 9; jj++) {
            float2 aa = *(const float2*)&l_t[m * 40 + nh * 18 + jj * 2];
            acc[2*jj].x   += aa.x * vv.x; acc[2*jj].y   += aa.x * vv.y;
            acc[2*jj].z   += aa.x * vv.z; acc[2*jj].w   += aa.x * vv.w;
            acc[2*jj+1].x += aa.y * vv.x; acc[2*jj+1].y += aa.y * vv.y;
            acc[2*jj+1].z += aa.y * vv.z; acc[2*jj+1].w += aa.y * vv.w;
        }
    }
    float4* vo = (float4*)(out_rhat + base * PDIM);
#pragma unroll
    for (int j = 0; j < 18; j++) {
        int n = nh * 18 + j;
        vo[n * 128 + c4] = acc[j];
    }
}

// ---------------------------------------------------------------------------
// Launcher
// ---------------------------------------------------------------------------
extern "C" void kernel_launch(void* const* d_in, const int* in_sizes, int n_in,
                              void* d_out, int out_size) {
    const float* x       = (const float*)d_in[0];
    const float* W_proj  = (const float*)d_in[1];
    const float* b_proj  = (const float*)d_in[2];
    const float* W_sigma = (const float*)d_in[3];
    const float* b_sigma = (const float*)d_in[4];
    const float* W_psi   = (const float*)d_in[5];
    const float* b_psi   = (const float*)d_in[6];
    const float* W_r     = (const float*)d_in[7];
    float* out = (float*)d_out;

    cudaFuncSetAttribute(gemm_fused_kernel, cudaFuncAttributeMaxDynamicSharedMemorySize, GEMM_SMEM);
    cudaFuncSetAttribute(attn_kernel, cudaFuncAttributeMaxDynamicSharedMemorySize, ATTN_SMEM);

    long n4 = (long)MROWS * DIN / 4;
    split_x_kernel<<<8192, 256>>>(x, n4);
    split_w_kernel<<<(NCAT * DIN + 255) / 256, 256>>>(W_proj, W_sigma, W_psi, W_r);
    gemm_fused_kernel<<<2 * NB3, 512, GEMM_SMEM>>>(b_sigma, b_psi, b_proj, out);
    attn_kernel<<<HEADS, 256, ATTN_SMEM>>>(out + OUT_HALF);
}

// round 11
// speedup vs baseline: 1.2800x; 1.0555x over previous
#include <cuda_runtime.h>
#include <cuda_bf16.h>
#include <cuda_fp16.h>
#include <cstdint>

// ---------------------------------------------------------------------------
// Problem constants
// ---------------------------------------------------------------------------
#define BATCH   32
#define FRAMES  32
#define NOBJ    36
#define DIN     2048
#define PDIM    512
#define MROWS   (BATCH*FRAMES*NOBJ)     // 36864
#define HEADS   (BATCH*FRAMES)          // 1024
#define NCAT    (4*PDIM)                // 2048 concat output cols

#define MTILE   128
#define NTILE   256
#define NCH     (DIN/64)                // 32 K-chunks of 64

// gemm3 (bf16 3-pass): AH 16K | AL 16K | BH 32K | BL 32K = 96K/stage, 2 stages
#define OFF_AH  0
#define OFF_AL  16384
#define OFF_BH  32768
#define OFF_BL  65536
#define STAGE3_BYTES 98304

// gemm1 (fp16 1-pass): AF 16K | BF 32K = 48K/stage, 4 stages
#define OFF_AF  0
#define OFF_BF  16384
#define STAGE1_BYTES 49152

#define GEMM_SMEM 196608
#define NB3 1152                        // gemm3 CTAs (first in grid)

// attention smem: v (36*512 f32) + logits (36*36) + transposed probs (36*40)
#define ATTN_SMEM  ((NOBJ*PDIM + NOBJ*NOBJ + NOBJ*40)*4)   // 84672 bytes

#define OUT_HALF   ((size_t)MROWS*PDIM)

// ---------------------------------------------------------------------------
// Device scratch
// ---------------------------------------------------------------------------
__device__ __nv_bfloat16 g_xh[(size_t)MROWS*DIN];
__device__ __nv_bfloat16 g_xl[(size_t)MROWS*DIN];
__device__ __half        g_xf[(size_t)MROWS*DIN];
__device__ __nv_bfloat16 g_wth[(size_t)NCAT*DIN];   // [n][k], K-major (sig/psi rows)
__device__ __nv_bfloat16 g_wtl[(size_t)NCAT*DIN];
__device__ __half        g_wf [(size_t)NCAT*DIN];   // [n][k], K-major (proj/r rows)
__device__ float g_sig[(size_t)MROWS*PDIM];
__device__ float g_psi[(size_t)MROWS*PDIM];
__device__ float g_v  [(size_t)MROWS*PDIM];

// ---------------------------------------------------------------------------
// PTX helpers
// ---------------------------------------------------------------------------
__device__ __forceinline__ uint32_t smem_u32(const void* p) {
    uint32_t a;
    asm("{ .reg .u64 t; cvta.to.shared.u64 t, %1; cvt.u32.u64 %0, t; }"
        : "=r"(a) : "l"(p));
    return a;
}

__device__ __forceinline__ void cp16(uint32_t s, const void* g) {
    asm volatile("cp.async.cg.shared.global [%0], [%1], 16;\n" :: "r"(s), "l"(g) : "memory");
}

#define LDSM4(R, A) \
    asm volatile("ldmatrix.sync.aligned.m8n8.x4.shared.b16 {%0,%1,%2,%3}, [%4];" \
        : "=r"((R)[0]), "=r"((R)[1]), "=r"((R)[2]), "=r"((R)[3]) : "r"(A))

#define MMA_BF16(C, A, B0, B1) \
    asm volatile("mma.sync.aligned.m16n8k16.row.col.f32.bf16.bf16.f32 " \
        "{%0,%1,%2,%3}, {%4,%5,%6,%7}, {%8,%9}, {%0,%1,%2,%3};" \
        : "+f"((C)[0]), "+f"((C)[1]), "+f"((C)[2]), "+f"((C)[3]) \
        : "r"((A)[0]), "r"((A)[1]), "r"((A)[2]), "r"((A)[3]), "r"(B0), "r"(B1))

#define MMA_F16(C, A, B0, B1) \
    asm volatile("mma.sync.aligned.m16n8k16.row.col.f32.f16.f16.f32 " \
        "{%0,%1,%2,%3}, {%4,%5,%6,%7}, {%8,%9}, {%0,%1,%2,%3};" \
        : "+f"((C)[0]), "+f"((C)[1]), "+f"((C)[2]), "+f"((C)[3]) \
        : "r"((A)[0]), "r"((A)[1]), "r"((A)[2]), "r"((A)[3]), "r"(B0), "r"(B1))

// 128B-row swizzle: chunk i in 0..7
#define SWZ128(r, i) ((uint32_t)((r) * 128 + (((i) * 16) ^ (((r) & 7) << 4))))

// ---------------------------------------------------------------------------
// Prep kernels: fp32 -> bf16 hi/lo (sig/psi path) and fp16 (proj/v path)
// ---------------------------------------------------------------------------
__global__ void split_x_kernel(const float* __restrict__ x, long n4) {
    long i = blockIdx.x * (long)blockDim.x + threadIdx.x;
    long stride = (long)gridDim.x * blockDim.x;
    __nv_bfloat162* xh2 = reinterpret_cast<__nv_bfloat162*>(g_xh);
    __nv_bfloat162* xl2 = reinterpret_cast<__nv_bfloat162*>(g_xl);
    __half2*        xf2 = reinterpret_cast<__half2*>(g_xf);
    for (; i < n4; i += stride) {
        float4 v = reinterpret_cast<const float4*>(x)[i];
        __nv_bfloat16 h0 = __float2bfloat16(v.x);
        __nv_bfloat16 h1 = __float2bfloat16(v.y);
        __nv_bfloat16 h2 = __float2bfloat16(v.z);
        __nv_bfloat16 h3 = __float2bfloat16(v.w);
        __nv_bfloat16 l0 = __float2bfloat16(v.x - __bfloat162float(h0));
        __nv_bfloat16 l1 = __float2bfloat16(v.y - __bfloat162float(h1));
        __nv_bfloat16 l2 = __float2bfloat16(v.z - __bfloat162float(h2));
        __nv_bfloat16 l3 = __float2bfloat16(v.w - __bfloat162float(h3));
        __nv_bfloat162 hA; hA.x = h0; hA.y = h1;
        __nv_bfloat162 hB; hB.x = h2; hB.y = h3;
        __nv_bfloat162 lA; lA.x = l0; lA.y = l1;
        __nv_bfloat162 lB; lB.x = l2; lB.y = l3;
        xh2[2*i]   = hA; xh2[2*i+1] = hB;
        xl2[2*i]   = lA; xl2[2*i+1] = lB;
        xf2[2*i]   = __floats2half2_rn(v.x, v.y);
        xf2[2*i+1] = __floats2half2_rn(v.z, v.w);
    }
}

__global__ void split_w_kernel(const float* __restrict__ Wp, const float* __restrict__ Ws,
                               const float* __restrict__ Wq, const float* __restrict__ Wr) {
    long t = blockIdx.x * (long)blockDim.x + threadIdx.x;   // over NCAT*DIN
    if (t >= (long)NCAT * DIN) return;
    int n = (int)(t >> 11);        // /DIN
    int k = (int)(t & (DIN - 1));
    int mat = n >> 9, p = n & 511;
    const float* W = (mat == 0) ? Wp : (mat == 1) ? Ws : (mat == 2) ? Wq : Wr;
    float w = W[(size_t)k * PDIM + p];
    if (mat == 1 || mat == 2) {
        __nv_bfloat16 h = __float2bfloat16(w);
        g_wth[t] = h;
        g_wtl[t] = __float2bfloat16(w - __bfloat162float(h));
    } else {
        g_wf[t] = __float2half_rn(w);
    }
}

// ---------------------------------------------------------------------------
// gemm3 path: sig/psi columns, bf16 3-pass, 128x256, 2-stage  (round-5 form)
// ---------------------------------------------------------------------------
__device__ __forceinline__ void load_chunk3(uint32_t sbase, int kc, int m0, int n0, int tid) {
    const char* xh = (const char*)g_xh;
    const char* xl = (const char*)g_xl;
    const char* bh = (const char*)g_wth;
    const char* bl = (const char*)g_wtl;
    size_t kcoff = (size_t)kc * 128;   // 64 bf16 = 128 bytes
#pragma unroll
    for (int q = 0; q < 2; q++) {                 // A: 128 rows x 8 x 16B
        int j = tid + q * 512;
        int r = j >> 3, i = j & 7;
        uint32_t so = SWZ128(r, i);
        size_t goA = ((size_t)(m0 + r)) * (DIN * 2) + kcoff + i * 16;
        cp16(sbase + OFF_AH + so, xh + goA);
        cp16(sbase + OFF_AL + so, xl + goA);
    }
#pragma unroll
    for (int q = 0; q < 4; q++) {                 // B: 256 rows x 8 x 16B
        int j = tid + q * 512;
        int r = j >> 3, i = j & 7;
        uint32_t so = SWZ128(r, i);
        size_t goB = ((size_t)(n0 + r)) * (DIN * 2) + kcoff + i * 16;
        cp16(sbase + OFF_BH + so, bh + goB);
        cp16(sbase + OFF_BL + so, bl + goB);
    }
    asm volatile("cp.async.commit_group;\n" ::: "memory");
}

__device__ __forceinline__ void compute_chunk3(uint32_t sbase, float (*acc)[8][4],
                                               int wm, int wn, int lane) {
    int r_off  = lane & 15;
    int kseg   = (lane >> 4) << 3;
    int n_off  = (lane & 7) + ((lane >> 4) << 3);
    int ksegb  = ((lane >> 3) & 1) << 3;
#pragma unroll
    for (int kk = 0; kk < 4; kk++) {
        uint32_t ah[2][4], al[2][4], b[4][4];
#pragma unroll
        for (int im = 0; im < 2; im++) {
            int row = wm + im * 16 + r_off;
            int kb = (kk * 16 + kseg) >> 3;
            LDSM4(ah[im], sbase + OFF_AH + SWZ128(row, kb));
            LDSM4(al[im], sbase + OFF_AL + SWZ128(row, kb));
        }
#pragma unroll
        for (int j = 0; j < 4; j++) {
            int row = wn + j * 16 + n_off;
            int kb = (kk * 16 + ksegb) >> 3;
            LDSM4(b[j], sbase + OFF_BH + SWZ128(row, kb));
        }
        // pass 1: Ah*Bh  (16 independent accumulator chains)
#pragma unroll
        for (int im = 0; im < 2; im++)
#pragma unroll
            for (int j = 0; j < 4; j++) {
                MMA_BF16(acc[im][2*j],   ah[im], b[j][0], b[j][1]);
                MMA_BF16(acc[im][2*j+1], ah[im], b[j][2], b[j][3]);
            }
        // pass 2: Al*Bh
#pragma unroll
        for (int im = 0; im < 2; im++)
#pragma unroll
            for (int j = 0; j < 4; j++) {
                MMA_BF16(acc[im][2*j],   al[im], b[j][0], b[j][1]);
                MMA_BF16(acc[im][2*j+1], al[im], b[j][2], b[j][3]);
            }
        // B-lo (recycle regs)
#pragma unroll
        for (int j = 0; j < 4; j++) {
            int row = wn + j * 16 + n_off;
            int kb = (kk * 16 + ksegb) >> 3;
            LDSM4(b[j], sbase + OFF_BL + SWZ128(row, kb));
        }
        // pass 3: Ah*Bl
#pragma unroll
        for (int im = 0; im < 2; im++)
#pragma unroll
            for (int j = 0; j < 4; j++) {
                MMA_BF16(acc[im][2*j],   ah[im], b[j][0], b[j][1]);
                MMA_BF16(acc[im][2*j+1], ah[im], b[j][2], b[j][3]);
            }
    }
}

// ---------------------------------------------------------------------------
// gemm1 path: r_feat / v columns, fp16 1-pass, 128x256, 4-stage (round-7 form)
// ---------------------------------------------------------------------------
__device__ __forceinline__ void load_chunk1(uint32_t sbase, int kc, int m0, int n0, int tid) {
    const char* xf = (const char*)g_xf;
    const char* bf = (const char*)g_wf;
    size_t kcoff = (size_t)kc * 128;
#pragma unroll
    for (int q = 0; q < 2; q++) {                 // A: 128 rows x 8 x 16B
        int j = tid + q * 512;
        int r = j >> 3, i = j & 7;
        uint32_t so = SWZ128(r, i);
        size_t goA = ((size_t)(m0 + r)) * (DIN * 2) + kcoff + i * 16;
        cp16(sbase + OFF_AF + so, xf + goA);
    }
#pragma unroll
    for (int q = 0; q < 4; q++) {                 // B: 256 rows x 8 x 16B
        int j = tid + q * 512;
        int r = j >> 3, i = j & 7;
        uint32_t so = SWZ128(r, i);
        size_t goB = ((size_t)(n0 + r)) * (DIN * 2) + kcoff + i * 16;
        cp16(sbase + OFF_BF + so, bf + goB);
    }
    asm volatile("cp.async.commit_group;\n" ::: "memory");
}

__device__ __forceinline__ void compute_chunk1(uint32_t sbase, float (*acc)[8][4],
                                               int wm, int wn, int lane) {
    int r_off  = lane & 15;
    int kseg   = (lane >> 4) << 3;
    int n_off  = (lane & 7) + ((lane >> 4) << 3);
    int ksegb  = ((lane >> 3) & 1) << 3;
#pragma unroll
    for (int kk = 0; kk < 4; kk++) {
        uint32_t af[2][4], b[4][4];
#pragma unroll
        for (int im = 0; im < 2; im++) {
            int row = wm + im * 16 + r_off;
            int kb = (kk * 16 + kseg) >> 3;
            LDSM4(af[im], sbase + OFF_AF + SWZ128(row, kb));
        }
#pragma unroll
        for (int j = 0; j < 4; j++) {
            int row = wn + j * 16 + n_off;
            int kb = (kk * 16 + ksegb) >> 3;
            LDSM4(b[j], sbase + OFF_BF + SWZ128(row, kb));
        }
#pragma unroll
        for (int im = 0; im < 2; im++)
#pragma unroll
            for (int j = 0; j < 4; j++) {
                MMA_F16(acc[im][2*j],   af[im], b[j][0], b[j][1]);
                MMA_F16(acc[im][2*j+1], af[im], b[j][2], b[j][3]);
            }
    }
}

// ---------------------------------------------------------------------------
// Fused GEMM kernel: blocks [0,1152) = gemm3 (sig/psi), [1152,2304) = gemm1.
// ---------------------------------------------------------------------------
__global__ void __launch_bounds__(512, 1) gemm_fused_kernel(
    const float* __restrict__ b_sigma, const float* __restrict__ b_psi,
    const float* __restrict__ b_proj, float* __restrict__ out_rfeat)
{
    extern __shared__ char smem[];
    uint32_t sb = smem_u32(smem);
    int tid = threadIdx.x;
    int wid = tid >> 5, lane = tid & 31;
    int wm = (wid >> 2) * 32, wn = (wid & 3) * 64;

    float acc[2][8][4];
#pragma unroll
    for (int a = 0; a < 2; a++)
#pragma unroll
        for (int b = 0; b < 8; b++)
#pragma unroll
            for (int c = 0; c < 4; c++) acc[a][b][c] = 0.f;

    if (blockIdx.x < NB3) {
        // ---- gemm3: bf16 3-pass over concat cols 512..1535 ----
        int bid = blockIdx.x;
        int nt = bid & 3, mt = bid >> 2;
        int m0 = mt * MTILE, n0 = 512 + nt * NTILE;

        load_chunk3(sb, 0, m0, n0, tid);
        for (int c = 0; c < NCH; c++) {
            if (c + 1 < NCH) {
                load_chunk3(sb + ((c + 1) & 1) * STAGE3_BYTES, c + 1, m0, n0, tid);
                asm volatile("cp.async.wait_group 1;" ::: "memory");
            } else {
                asm volatile("cp.async.wait_group 0;" ::: "memory");
            }
            __syncthreads();
            compute_chunk3(sb + (c & 1) * STAGE3_BYTES, acc, wm, wn, lane);
            __syncthreads();
        }

        const float* bias = (nt < 2) ? b_sigma : b_psi;
        float* dest = (nt < 2) ? g_sig : g_psi;
        int colbase = (nt & 1) * 256;
        int groupID = lane >> 2, tig = lane & 3;
#pragma unroll
        for (int im = 0; im < 2; im++)
#pragma unroll
            for (int in = 0; in < 8; in++) {
                int col = colbase + wn + in * 8 + tig * 2;
                float2 bv = __ldg((const float2*)&bias[col]);
                int row0 = m0 + wm + im * 16 + groupID;
                float2 v0, v1;
                v0.x = acc[im][in][0] + bv.x; v0.y = acc[im][in][1] + bv.y;
                v1.x = acc[im][in][2] + bv.x; v1.y = acc[im][in][3] + bv.y;
                *(float2*)&dest[(size_t)row0 * PDIM + col]       = v0;
                *(float2*)&dest[(size_t)(row0 + 8) * PDIM + col] = v1;
            }
    } else {
        // ---- gemm1: fp16 1-pass over concat cols 0..511 and 1536..2047 ----
        int bid = blockIdx.x - NB3;
        int nt = bid & 3, mt = bid >> 2;
        int m0 = mt * MTILE;
        int n0 = (nt < 2) ? nt * NTILE : 1536 + (nt - 2) * NTILE;

        load_chunk1(sb + 0 * STAGE1_BYTES, 0, m0, n0, tid);
        load_chunk1(sb + 1 * STAGE1_BYTES, 1, m0, n0, tid);
        load_chunk1(sb + 2 * STAGE1_BYTES, 2, m0, n0, tid);

        for (int c = 0; c < NCH; c++) {
            if (c < NCH - 2)       asm volatile("cp.async.wait_group 2;" ::: "memory");
            else if (c == NCH - 2) asm volatile("cp.async.wait_group 1;" ::: "memory");
            else                   asm volatile("cp.async.wait_group 0;" ::: "memory");
            __syncthreads();
            if (c + 3 < NCH)
                load_chunk1(sb + ((c + 3) & 3) * STAGE1_BYTES, c + 3, m0, n0, tid);
            compute_chunk1(sb + (c & 3) * STAGE1_BYTES, acc, wm, wn, lane);
        }

        const float* bias = (nt < 2) ? b_proj : nullptr;
        float* dest = (nt < 2) ? out_rfeat : g_v;
        int colbase = (nt & 1) * 256;
        int groupID = lane >> 2, tig = lane & 3;
#pragma unroll
        for (int im = 0; im < 2; im++)
#pragma unroll
            for (int in = 0; in < 8; in++) {
                int col = colbase + wn + in * 8 + tig * 2;
                float2 bv = make_float2(0.f, 0.f);
                if (bias) bv = __ldg((const float2*)&bias[col]);
                int row0 = m0 + wm + im * 16 + groupID;
                float2 v0, v1;
                v0.x = acc[im][in][0] + bv.x; v0.y = acc[im][in][1] + bv.y;
                v1.x = acc[im][in][2] + bv.x; v1.y = acc[im][in][3] + bv.y;
                *(float2*)&dest[(size_t)row0 * PDIM + col]       = v0;
                *(float2*)&dest[(size_t)(row0 + 8) * PDIM + col] = v1;
            }
    }
}

// ---------------------------------------------------------------------------
// Attention: per-head softmax(sig psi^T) @ v.  1 CTA/head, 256 threads,
// 2 CTAs/SM.  QK: warp-per-row, lanes split K (all loads coalesced),
// 36 register accumulators, shfl-butterfly reduce.  AV: v in smem,
// transposed probs, 18-row reuse (round-5 proven form).
// ---------------------------------------------------------------------------
__global__ void __launch_bounds__(256, 2) attn_kernel(float* __restrict__ out_rhat) {
    extern __shared__ float as[];
    float* v_s = as;                          // 36*512
    float* l_s = as + NOBJ * PDIM;            // 36*36   logits, n-major
    float* l_t = l_s + NOBJ * NOBJ;           // 36*40   probs, m-major (padded)
    int h = blockIdx.x;
    int tid = threadIdx.x;
    int w = tid >> 5, lane = tid & 31;
    size_t base = (size_t)h * NOBJ;

    const float4* gv = (const float4*)(g_v + base * PDIM);
    float4* sv = (float4*)v_s;
#pragma unroll
    for (int q = 0; q < 18; q++) {            // 4608 float4s
        int i = tid + q * 256;
        sv[i] = gv[i];
    }
    __syncthreads();

    // QK: warp w owns rows n = w, w+8, w+16, w+24 (+ 32+w for w<4).
    // Lanes split the 512-dim K: lane reads float4 at k4 = lane + 32*it.
    // All sig/psi loads are fully coalesced; 36 dots accumulate in registers.
    const float4* pp = (const float4*)(g_psi + base * PDIM);   // psi row m at pp+m*128
    for (int rr = 0; rr < 5; rr++) {
        if (rr == 4 && w >= 4) break;
        int n = (rr < 4) ? (w + 8 * rr) : (32 + w);
        float accm[36];
#pragma unroll
        for (int m = 0; m < 36; m++) accm[m] = 0.f;
        const float4* sg = (const float4*)(g_sig + (base + n) * PDIM);
#pragma unroll
        for (int it = 0; it < 4; it++) {
            float4 s = __ldg(&sg[lane + 32 * it]);
#pragma unroll
            for (int m = 0; m < 36; m++) {
                float4 p = __ldg(&pp[m * 128 + lane + 32 * it]);
                accm[m] += s.x * p.x + s.y * p.y + s.z * p.z + s.w * p.w;
            }
        }
        // butterfly reduction over the 32-way K split
#pragma unroll
        for (int off = 16; off > 0; off >>= 1)
#pragma unroll
            for (int m = 0; m < 36; m++)
                accm[m] += __shfl_xor_sync(0xFFFFFFFF, accm[m], off);
        if (lane == 0) {
#pragma unroll
            for (int m = 0; m < 36; m++) l_s[n * 36 + m] = accm[m];
        }
    }
    __syncthreads();

    // row softmax; write probs transposed (m-major) for vectorized AV loads
    if (tid < 36) {
        float row[36];
        float m = -1e30f;
#pragma unroll
        for (int j = 0; j < 36; j++) { row[j] = l_s[tid * 36 + j]; m = fmaxf(m, row[j]); }
        float ssum = 0.f;
#pragma unroll
        for (int j = 0; j < 36; j++) { float e = __expf(row[j] - m); row[j] = e; ssum += e; }
        float inv = 1.f / ssum;
#pragma unroll
        for (int j = 0; j < 36; j++) l_t[j * 40 + tid] = row[j] * inv;
    }
    __syncthreads();

    // AV: out[n][p] = sum_m a[n][m] v[m][p]; each thread: 1 col-chunk x 18 rows
    int c4 = tid & 127, nh = tid >> 7;
    float4 acc[18];
#pragma unroll
    for (int j = 0; j < 18; j++) acc[j] = make_float4(0.f, 0.f, 0.f, 0.f);
    const float4* vrow = (const float4*)v_s + c4;
#pragma unroll 4
    for (int m = 0; m < 36; m++) {
        float4 vv = vrow[m * 128];
#pragma unroll
        for (int jj = 0; jj < 9; jj++) {
            float2 aa = *(const float2*)&l_t[m * 40 + nh * 18 + jj * 2];
            acc[2*jj].x   += aa.x * vv.x; acc[2*jj].y   += aa.x * vv.y;
            acc[2*jj].z   += aa.x * vv.z; acc[2*jj].w   += aa.x * vv.w;
            acc[2*jj+1].x += aa.y * vv.x; acc[2*jj+1].y += aa.y * vv.y;
            acc[2*jj+1].z += aa.y * vv.z; acc[2*jj+1].w += aa.y * vv.w;
        }
    }
    float4* vo = (float4*)(out_rhat + base * PDIM);
#pragma unroll
    for (int j = 0; j < 18; j++) {
        int n = nh * 18 + j;
        vo[n * 128 + c4] = acc[j];
    }
}

// ---------------------------------------------------------------------------
// Launcher
// ---------------------------------------------------------------------------
extern "C" void kernel_launch(void* const* d_in, const int* in_sizes, int n_in,
                              void* d_out, int out_size) {
    const float* x       = (const float*)d_in[0];
    const float* W_proj  = (const float*)d_in[1];
    const float* b_proj  = (const float*)d_in[2];
    const float* W_sigma = (const float*)d_in[3];
    const float* b_sigma = (const float*)d_in[4];
    const float* W_psi   = (const float*)d_in[5];
    const float* b_psi   = (const float*)d_in[6];
    const float* W_r     = (const float*)d_in[7];
    float* out = (float*)d_out;

    cudaFuncSetAttribute(gemm_fused_kernel, cudaFuncAttributeMaxDynamicSharedMemorySize, GEMM_SMEM);
    cudaFuncSetAttribute(attn_kernel, cudaFuncAttributeMaxDynamicSharedMemorySize, ATTN_SMEM);

    long n4 = (long)MROWS * DIN / 4;
    split_x_kernel<<<8192, 256>>>(x, n4);
    split_w_kernel<<<(NCAT * DIN + 255) / 256, 256>>>(W_proj, W_sigma, W_psi, W_r);
    gemm_fused_kernel<<<2 * NB3, 512, GEMM_SMEM>>>(b_sigma, b_psi, b_proj, out);
    attn_kernel<<<HEADS, 256, ATTN_SMEM>>>(out + OUT_HALF);
}

// round 13
// speedup vs baseline: 1.2928x; 1.0100x over previous
#include <cuda_runtime.h>
#include <cuda_bf16.h>
#include <cuda_fp16.h>
#include <cstdint>

// ---------------------------------------------------------------------------
// Problem constants
// ---------------------------------------------------------------------------
#define BATCH   32
#define FRAMES  32
#define NOBJ    36
#define DIN     2048
#define PDIM    512
#define MROWS   (BATCH*FRAMES*NOBJ)     // 36864
#define HEADS   (BATCH*FRAMES)          // 1024
#define NCAT    (4*PDIM)                // 2048 concat output cols

#define MTILE   128
#define NTILE   256
#define NCH     (DIN/64)                // 32 K-chunks of 64

// gemm3 (bf16 3-pass): AH 16K | AL 16K | BH 32K | BL 32K = 96K/stage, 2 stages
#define OFF_AH  0
#define OFF_AL  16384
#define OFF_BH  32768
#define OFF_BL  65536
#define STAGE3_BYTES 98304

// gemm1 (fp16 1-pass): AF 16K | BF 32K = 48K/stage, 4 stages
#define OFF_AF  0
#define OFF_BF  16384
#define STAGE1_BYTES 49152

#define GEMM_SMEM 196608
#define NB3 1152                        // gemm3 CTAs (first in grid)

// attention smem: v (36*512 f32) + logits (36*36) + transposed probs (36*40)
#define ATTN_SMEM  ((NOBJ*PDIM + NOBJ*NOBJ + NOBJ*40)*4)   // 84672 bytes

#define OUT_HALF   ((size_t)MROWS*PDIM)

// ---------------------------------------------------------------------------
// Device scratch
// ---------------------------------------------------------------------------
__device__ __nv_bfloat16 g_xh[(size_t)MROWS*DIN];
__device__ __nv_bfloat16 g_xl[(size_t)MROWS*DIN];
__device__ __half        g_xf[(size_t)MROWS*DIN];
__device__ __nv_bfloat16 g_wth[(size_t)NCAT*DIN];   // [n][k], K-major (sig/psi rows)
__device__ __nv_bfloat16 g_wtl[(size_t)NCAT*DIN];
__device__ __half        g_wf [(size_t)NCAT*DIN];   // [n][k], K-major (proj/r rows)
__device__ float g_sig[(size_t)MROWS*PDIM];
__device__ float g_psi[(size_t)MROWS*PDIM];
__device__ float g_v  [(size_t)MROWS*PDIM];

// ---------------------------------------------------------------------------
// PTX helpers
// ---------------------------------------------------------------------------
__device__ __forceinline__ uint32_t smem_u32(const void* p) {
    uint32_t a;
    asm("{ .reg .u64 t; cvta.to.shared.u64 t, %1; cvt.u32.u64 %0, t; }"
        : "=r"(a) : "l"(p));
    return a;
}

__device__ __forceinline__ void cp16(uint32_t s, const void* g) {
    asm volatile("cp.async.cg.shared.global [%0], [%1], 16;\n" :: "r"(s), "l"(g) : "memory");
}

#define LDSM4(R, A) \
    asm volatile("ldmatrix.sync.aligned.m8n8.x4.shared.b16 {%0,%1,%2,%3}, [%4];" \
        : "=r"((R)[0]), "=r"((R)[1]), "=r"((R)[2]), "=r"((R)[3]) : "r"(A))

#define MMA_BF16(C, A, B0, B1) \
    asm volatile("mma.sync.aligned.m16n8k16.row.col.f32.bf16.bf16.f32 " \
        "{%0,%1,%2,%3}, {%4,%5,%6,%7}, {%8,%9}, {%0,%1,%2,%3};" \
        : "+f"((C)[0]), "+f"((C)[1]), "+f"((C)[2]), "+f"((C)[3]) \
        : "r"((A)[0]), "r"((A)[1]), "r"((A)[2]), "r"((A)[3]), "r"(B0), "r"(B1))

#define MMA_F16(C, A, B0, B1) \
    asm volatile("mma.sync.aligned.m16n8k16.row.col.f32.f16.f16.f32 " \
        "{%0,%1,%2,%3}, {%4,%5,%6,%7}, {%8,%9}, {%0,%1,%2,%3};" \
        : "+f"((C)[0]), "+f"((C)[1]), "+f"((C)[2]), "+f"((C)[3]) \
        : "r"((A)[0]), "r"((A)[1]), "r"((A)[2]), "r"((A)[3]), "r"(B0), "r"(B1))

// 128B-row swizzle: chunk i in 0..7
#define SWZ128(r, i) ((uint32_t)((r) * 128 + (((i) * 16) ^ (((r) & 7) << 4))))

// ---------------------------------------------------------------------------
// Prep kernels: fp32 -> bf16 hi/lo (sig/psi path) and fp16 (proj/v path)
// ---------------------------------------------------------------------------
__global__ void split_x_kernel(const float* __restrict__ x, long n4) {
    long i = blockIdx.x * (long)blockDim.x + threadIdx.x;
    long stride = (long)gridDim.x * blockDim.x;
    __nv_bfloat162* xh2 = reinterpret_cast<__nv_bfloat162*>(g_xh);
    __nv_bfloat162* xl2 = reinterpret_cast<__nv_bfloat162*>(g_xl);
    __half2*        xf2 = reinterpret_cast<__half2*>(g_xf);
    for (; i < n4; i += stride) {
        float4 v = reinterpret_cast<const float4*>(x)[i];
        __nv_bfloat16 h0 = __float2bfloat16(v.x);
        __nv_bfloat16 h1 = __float2bfloat16(v.y);
        __nv_bfloat16 h2 = __float2bfloat16(v.z);
        __nv_bfloat16 h3 = __float2bfloat16(v.w);
        __nv_bfloat16 l0 = __float2bfloat16(v.x - __bfloat162float(h0));
        __nv_bfloat16 l1 = __float2bfloat16(v.y - __bfloat162float(h1));
        __nv_bfloat16 l2 = __float2bfloat16(v.z - __bfloat162float(h2));
        __nv_bfloat16 l3 = __float2bfloat16(v.w - __bfloat162float(h3));
        __nv_bfloat162 hA; hA.x = h0; hA.y = h1;
        __nv_bfloat162 hB; hB.x = h2; hB.y = h3;
        __nv_bfloat162 lA; lA.x = l0; lA.y = l1;
        __nv_bfloat162 lB; lB.x = l2; lB.y = l3;
        xh2[2*i]   = hA; xh2[2*i+1] = hB;
        xl2[2*i]   = lA; xl2[2*i+1] = lB;
        xf2[2*i]   = __floats2half2_rn(v.x, v.y);
        xf2[2*i+1] = __floats2half2_rn(v.z, v.w);
    }
}

__global__ void split_w_kernel(const float* __restrict__ Wp, const float* __restrict__ Ws,
                               const float* __restrict__ Wq, const float* __restrict__ Wr) {
    long t = blockIdx.x * (long)blockDim.x + threadIdx.x;   // over NCAT*DIN
    if (t >= (long)NCAT * DIN) return;
    int n = (int)(t >> 11);        // /DIN
    int k = (int)(t & (DIN - 1));
    int mat = n >> 9, p = n & 511;
    const float* W = (mat == 0) ? Wp : (mat == 1) ? Ws : (mat == 2) ? Wq : Wr;
    float w = W[(size_t)k * PDIM + p];
    if (mat == 1 || mat == 2) {
        __nv_bfloat16 h = __float2bfloat16(w);
        g_wth[t] = h;
        g_wtl[t] = __float2bfloat16(w - __bfloat162float(h));
    } else {
        g_wf[t] = __float2half_rn(w);
    }
}

// ---------------------------------------------------------------------------
// gemm3 path: sig/psi columns, bf16 3-pass, 128x256, 2-stage, 1 sync/chunk
// ---------------------------------------------------------------------------
__device__ __forceinline__ void load_chunk3(uint32_t sbase, int kc, int m0, int n0, int tid) {
    const char* xh = (const char*)g_xh;
    const char* xl = (const char*)g_xl;
    const char* bh = (const char*)g_wth;
    const char* bl = (const char*)g_wtl;
    size_t kcoff = (size_t)kc * 128;   // 64 bf16 = 128 bytes
#pragma unroll
    for (int q = 0; q < 2; q++) {                 // A: 128 rows x 8 x 16B
        int j = tid + q * 512;
        int r = j >> 3, i = j & 7;
        uint32_t so = SWZ128(r, i);
        size_t goA = ((size_t)(m0 + r)) * (DIN * 2) + kcoff + i * 16;
        cp16(sbase + OFF_AH + so, xh + goA);
        cp16(sbase + OFF_AL + so, xl + goA);
    }
#pragma unroll
    for (int q = 0; q < 4; q++) {                 // B: 256 rows x 8 x 16B
        int j = tid + q * 512;
        int r = j >> 3, i = j & 7;
        uint32_t so = SWZ128(r, i);
        size_t goB = ((size_t)(n0 + r)) * (DIN * 2) + kcoff + i * 16;
        cp16(sbase + OFF_BH + so, bh + goB);
        cp16(sbase + OFF_BL + so, bl + goB);
    }
    asm volatile("cp.async.commit_group;\n" ::: "memory");
}

__device__ __forceinline__ void compute_chunk3(uint32_t sbase, float (*acc)[8][4],
                                               int wm, int wn, int lane) {
    int r_off  = lane & 15;
    int kseg   = (lane >> 4) << 3;
    int n_off  = (lane & 7) + ((lane >> 4) << 3);
    int ksegb  = ((lane >> 3) & 1) << 3;
#pragma unroll
    for (int kk = 0; kk < 4; kk++) {
        uint32_t ah[2][4], al[2][4], b[4][4];
#pragma unroll
        for (int im = 0; im < 2; im++) {
            int row = wm + im * 16 + r_off;
            int kb = (kk * 16 + kseg) >> 3;
            LDSM4(ah[im], sbase + OFF_AH + SWZ128(row, kb));
            LDSM4(al[im], sbase + OFF_AL + SWZ128(row, kb));
        }
#pragma unroll
        for (int j = 0; j < 4; j++) {
            int row = wn + j * 16 + n_off;
            int kb = (kk * 16 + ksegb) >> 3;
            LDSM4(b[j], sbase + OFF_BH + SWZ128(row, kb));
        }
        // pass 1: Ah*Bh  (16 independent accumulator chains)
#pragma unroll
        for (int im = 0; im < 2; im++)
#pragma unroll
            for (int j = 0; j < 4; j++) {
                MMA_BF16(acc[im][2*j],   ah[im], b[j][0], b[j][1]);
                MMA_BF16(acc[im][2*j+1], ah[im], b[j][2], b[j][3]);
            }
        // pass 2: Al*Bh
#pragma unroll
        for (int im = 0; im < 2; im++)
#pragma unroll
            for (int j = 0; j < 4; j++) {
                MMA_BF16(acc[im][2*j],   al[im], b[j][0], b[j][1]);
                MMA_BF16(acc[im][2*j+1], al[im], b[j][2], b[j][3]);
            }
        // B-lo (recycle regs)
#pragma unroll
        for (int j = 0; j < 4; j++) {
            int row = wn + j * 16 + n_off;
            int kb = (kk * 16 + ksegb) >> 3;
            LDSM4(b[j], sbase + OFF_BL + SWZ128(row, kb));
        }
        // pass 3: Ah*Bl
#pragma unroll
        for (int im = 0; im < 2; im++)
#pragma unroll
            for (int j = 0; j < 4; j++) {
                MMA_BF16(acc[im][2*j],   ah[im], b[j][0], b[j][1]);
                MMA_BF16(acc[im][2*j+1], ah[im], b[j][2], b[j][3]);
            }
    }
}

// ---------------------------------------------------------------------------
// gemm1 path: r_feat / v columns, fp16 1-pass, 128x256, 4-stage (round-7 form)
// ---------------------------------------------------------------------------
__device__ __forceinline__ void load_chunk1(uint32_t sbase, int kc, int m0, int n0, int tid) {
    const char* xf = (const char*)g_xf;
    const char* bf = (const char*)g_wf;
    size_t kcoff = (size_t)kc * 128;
#pragma unroll
    for (int q = 0; q < 2; q++) {                 // A: 128 rows x 8 x 16B
        int j = tid + q * 512;
        int r = j >> 3, i = j & 7;
        uint32_t so = SWZ128(r, i);
        size_t goA = ((size_t)(m0 + r)) * (DIN * 2) + kcoff + i * 16;
        cp16(sbase + OFF_AF + so, xf + goA);
    }
#pragma unroll
    for (int q = 0; q < 4; q++) {                 // B: 256 rows x 8 x 16B
        int j = tid + q * 512;
        int r = j >> 3, i = j & 7;
        uint32_t so = SWZ128(r, i);
        size_t goB = ((size_t)(n0 + r)) * (DIN * 2) + kcoff + i * 16;
        cp16(sbase + OFF_BF + so, bf + goB);
    }
    asm volatile("cp.async.commit_group;\n" ::: "memory");
}

__device__ __forceinline__ void compute_chunk1(uint32_t sbase, float (*acc)[8][4],
                                               int wm, int wn, int lane) {
    int r_off  = lane & 15;
    int kseg   = (lane >> 4) << 3;
    int n_off  = (lane & 7) + ((lane >> 4) << 3);
    int ksegb  = ((lane >> 3) & 1) << 3;
#pragma unroll
    for (int kk = 0; kk < 4; kk++) {
        uint32_t af[2][4], b[4][4];
#pragma unroll
        for (int im = 0; im < 2; im++) {
            int row = wm + im * 16 + r_off;
            int kb = (kk * 16 + kseg) >> 3;
            LDSM4(af[im], sbase + OFF_AF + SWZ128(row, kb));
        }
#pragma unroll
        for (int j = 0; j < 4; j++) {
            int row = wn + j * 16 + n_off;
            int kb = (kk * 16 + ksegb) >> 3;
            LDSM4(b[j], sbase + OFF_BF + SWZ128(row, kb));
        }
#pragma unroll
        for (int im = 0; im < 2; im++)
#pragma unroll
            for (int j = 0; j < 4; j++) {
                MMA_F16(acc[im][2*j],   af[im], b[j][0], b[j][1]);
                MMA_F16(acc[im][2*j+1], af[im], b[j][2], b[j][3]);
            }
    }
}

// ---------------------------------------------------------------------------
// Fused GEMM kernel: blocks [0,1152) = gemm3 (sig/psi), [1152,2304) = gemm1.
// ---------------------------------------------------------------------------
__global__ void __launch_bounds__(512, 1) gemm_fused_kernel(
    const float* __restrict__ b_sigma, const float* __restrict__ b_psi,
    const float* __restrict__ b_proj, float* __restrict__ out_rfeat)
{
    extern __shared__ char smem[];
    uint32_t sb = smem_u32(smem);
    int tid = threadIdx.x;
    int wid = tid >> 5, lane = tid & 31;
    int wm = (wid >> 2) * 32, wn = (wid & 3) * 64;

    float acc[2][8][4];
#pragma unroll
    for (int a = 0; a < 2; a++)
#pragma unroll
        for (int b = 0; b < 8; b++)
#pragma unroll
            for (int c = 0; c < 4; c++) acc[a][b][c] = 0.f;

    if (blockIdx.x < NB3) {
        // ---- gemm3: bf16 3-pass over concat cols 512..1535 ----
        int bid = blockIdx.x;
        int nt = bid & 3, mt = bid >> 2;
        int m0 = mt * MTILE, n0 = 512 + nt * NTILE;

        load_chunk3(sb, 0, m0, n0, tid);
        for (int c = 0; c < NCH; c++) {
            // chunk c is the only outstanding group; wait for it.
            asm volatile("cp.async.wait_group 0;" ::: "memory");
            __syncthreads();   // all warps past compute of chunk c-1: stage
                               // (c+1)&1 is free; chunk c data visible to all
            if (c + 1 < NCH)
                load_chunk3(sb + ((c + 1) & 1) * STAGE3_BYTES, c + 1, m0, n0, tid);
            compute_chunk3(sb + (c & 1) * STAGE3_BYTES, acc, wm, wn, lane);
        }

        const float* bias = (nt < 2) ? b_sigma : b_psi;
        float* dest = (nt < 2) ? g_sig : g_psi;
        int colbase = (nt & 1) * 256;
        int groupID = lane >> 2, tig = lane & 3;
#pragma unroll
        for (int im = 0; im < 2; im++)
#pragma unroll
            for (int in = 0; in < 8; in++) {
                int col = colbase + wn + in * 8 + tig * 2;
                float2 bv = __ldg((const float2*)&bias[col]);
                int row0 = m0 + wm + im * 16 + groupID;
                float2 v0, v1;
                v0.x = acc[im][in][0] + bv.x; v0.y = acc[im][in][1] + bv.y;
                v1.x = acc[im][in][2] + bv.x; v1.y = acc[im][in][3] + bv.y;
                *(float2*)&dest[(size_t)row0 * PDIM + col]       = v0;
                *(float2*)&dest[(size_t)(row0 + 8) * PDIM + col] = v1;
            }
    } else {
        // ---- gemm1: fp16 1-pass over concat cols 0..511 and 1536..2047 ----
        int bid = blockIdx.x - NB3;
        int nt = bid & 3, mt = bid >> 2;
        int m0 = mt * MTILE;
        int n0 = (nt < 2) ? nt * NTILE : 1536 + (nt - 2) * NTILE;

        load_chunk1(sb + 0 * STAGE1_BYTES, 0, m0, n0, tid);
        load_chunk1(sb + 1 * STAGE1_BYTES, 1, m0, n0, tid);
        load_chunk1(sb + 2 * STAGE1_BYTES, 2, m0, n0, tid);

        for (int c = 0; c < NCH; c++) {
            if (c < NCH - 2)       asm volatile("cp.async.wait_group 2;" ::: "memory");
            else if (c == NCH - 2) asm volatile("cp.async.wait_group 1;" ::: "memory");
            else                   asm volatile("cp.async.wait_group 0;" ::: "memory");
            __syncthreads();
            if (c + 3 < NCH)
                load_chunk1(sb + ((c + 3) & 3) * STAGE1_BYTES, c + 3, m0, n0, tid);
            compute_chunk1(sb + (c & 3) * STAGE1_BYTES, acc, wm, wn, lane);
        }

        const float* bias = (nt < 2) ? b_proj : nullptr;
        float* dest = (nt < 2) ? out_rfeat : g_v;
        int colbase = (nt & 1) * 256;
        int groupID = lane >> 2, tig = lane & 3;
#pragma unroll
        for (int im = 0; im < 2; im++)
#pragma unroll
            for (int in = 0; in < 8; in++) {
                int col = colbase + wn + in * 8 + tig * 2;
                float2 bv = make_float2(0.f, 0.f);
                if (bias) bv = __ldg((const float2*)&bias[col]);
                int row0 = m0 + wm + im * 16 + groupID;
                float2 v0, v1;
                v0.x = acc[im][in][0] + bv.x; v0.y = acc[im][in][1] + bv.y;
                v1.x = acc[im][in][2] + bv.x; v1.y = acc[im][in][3] + bv.y;
                *(float2*)&dest[(size_t)row0 * PDIM + col]       = v0;
                *(float2*)&dest[(size_t)(row0 + 8) * PDIM + col] = v1;
            }
    }
}

// ---------------------------------------------------------------------------
// Attention: per-head softmax(sig psi^T) @ v.  1 CTA/head, 256 threads,
// 2 CTAs/SM.  v staged via cp.async overlapped with QK.  QK: warp-per-row,
// lanes split K (coalesced), 36 register accumulators, shfl reduce.
// AV: transposed probs, 18-row v reuse.
// ---------------------------------------------------------------------------
__global__ void __launch_bounds__(256, 2) attn_kernel(float* __restrict__ out_rhat) {
    extern __shared__ float as[];
    float* v_s = as;                          // 36*512
    float* l_s = as + NOBJ * PDIM;            // 36*36   logits, n-major
    float* l_t = l_s + NOBJ * NOBJ;           // 36*40   probs, m-major (padded)
    int h = blockIdx.x;
    int tid = threadIdx.x;
    int w = tid >> 5, lane = tid & 31;
    size_t base = (size_t)h * NOBJ;

    // v staging via cp.async — overlapped with the QK phase below.
    {
        uint32_t vsb = smem_u32(v_s);
        const float4* gv = (const float4*)(g_v + base * PDIM);
#pragma unroll
        for (int q = 0; q < 18; q++) {        // 4608 float4s
            int i = tid + q * 256;
            cp16(vsb + (uint32_t)i * 16, gv + i);
        }
        asm volatile("cp.async.commit_group;\n" ::: "memory");
    }

    // QK: warp w owns rows n = w, w+8, w+16, w+24 (+ 32+w for w<4).
    // Lanes split the 512-dim K: lane reads float4 at k4 = lane + 32*it.
    const float4* pp = (const float4*)(g_psi + base * PDIM);   // psi row m at pp+m*128
    for (int rr = 0; rr < 5; rr++) {
        if (rr == 4 && w >= 4) break;
        int n = (rr < 4) ? (w + 8 * rr) : (32 + w);
        float accm[36];
#pragma unroll
        for (int m = 0; m < 36; m++) accm[m] = 0.f;
        const float4* sg = (const float4*)(g_sig + (base + n) * PDIM);
#pragma unroll
        for (int it = 0; it < 4; it++) {
            float4 s = __ldg(&sg[lane + 32 * it]);
#pragma unroll
            for (int m = 0; m < 36; m++) {
                float4 p = __ldg(&pp[m * 128 + lane + 32 * it]);
                accm[m] += s.x * p.x + s.y * p.y + s.z * p.z + s.w * p.w;
            }
        }
#pragma unroll
        for (int off = 16; off > 0; off >>= 1)
#pragma unroll
            for (int m = 0; m < 36; m++)
                accm[m] += __shfl_xor_sync(0xFFFFFFFF, accm[m], off);
        if (lane == 0) {
#pragma unroll
            for (int m = 0; m < 36; m++) l_s[n * 36 + m] = accm[m];
        }
    }
    // v staging must be complete (per-thread) before the barrier publishes it.
    asm volatile("cp.async.wait_group 0;" ::: "memory");
    __syncthreads();

    // row softmax; write probs transposed (m-major) for vectorized AV loads
    if (tid < 36) {
        float row[36];
        float m = -1e30f;
#pragma unroll
        for (int j = 0; j < 36; j++) { row[j] = l_s[tid * 36 + j]; m = fmaxf(m, row[j]); }
        float ssum = 0.f;
#pragma unroll
        for (int j = 0; j < 36; j++) { float e = __expf(row[j] - m); row[j] = e; ssum += e; }
        float inv = 1.f / ssum;
#pragma unroll
        for (int j = 0; j < 36; j++) l_t[j * 40 + tid] = row[j] * inv;
    }
    __syncthreads();

    // AV: out[n][p] = sum_m a[n][m] v[m][p]; each thread: 1 col-chunk x 18 rows
    int c4 = tid & 127, nh = tid >> 7;
    float4 acc[18];
#pragma unroll
    for (int j = 0; j < 18; j++) acc[j] = make_float4(0.f, 0.f, 0.f, 0.f);
    const float4* vrow = (const float4*)v_s + c4;
#pragma unroll 4
    for (int m = 0; m < 36; m++) {
        float4 vv = vrow[m * 128];
#pragma unroll
        for (int jj = 0; jj < 9; jj++) {
            float2 aa = *(const float2*)&l_t[m * 40 + nh * 18 + jj * 2];
            acc[2*jj].x   += aa.x * vv.x; acc[2*jj].y   += aa.x * vv.y;
            acc[2*jj].z   += aa.x * vv.z; acc[2*jj].w   += aa.x * vv.w;
            acc[2*jj+1].x += aa.y * vv.x; acc[2*jj+1].y += aa.y * vv.y;
            acc[2*jj+1].z += aa.y * vv.z; acc[2*jj+1].w += aa.y * vv.w;
        }
    }
    float4* vo = (float4*)(out_rhat + base * PDIM);
#pragma unroll
    for (int j = 0; j < 18; j++) {
        int n = nh * 18 + j;
        vo[n * 128 + c4] = acc[j];
    }
}

// ---------------------------------------------------------------------------
// Launcher
// ---------------------------------------------------------------------------
extern "C" void kernel_launch(void* const* d_in, const int* in_sizes, int n_in,
                              void* d_out, int out_size) {
    const float* x       = (const float*)d_in[0];
    const float* W_proj  = (const float*)d_in[1];
    const float* b_proj  = (const float*)d_in[2];
    const float* W_sigma = (const float*)d_in[3];
    const float* b_sigma = (const float*)d_in[4];
    const float* W_psi   = (const float*)d_in[5];
    const float* b_psi   = (const float*)d_in[6];
    const float* W_r     = (const float*)d_in[7];
    float* out = (float*)d_out;

    cudaFuncSetAttribute(gemm_fused_kernel, cudaFuncAttributeMaxDynamicSharedMemorySize, GEMM_SMEM);
    cudaFuncSetAttribute(attn_kernel, cudaFuncAttributeMaxDynamicSharedMemorySize, ATTN_SMEM);

    long n4 = (long)MROWS * DIN / 4;
    split_x_kernel<<<8192, 256>>>(x, n4);
    split_w_kernel<<<(NCAT * DIN + 255) / 256, 256>>>(W_proj, W_sigma, W_psi, W_r);
    gemm_fused_kernel<<<2 * NB3, 512, GEMM_SMEM>>>(b_sigma, b_psi, b_proj, out);
    attn_kernel<<<HEADS, 256, ATTN_SMEM>>>(out + OUT_HALF);
}

// round 15
// speedup vs baseline: 1.3036x; 1.0083x over previous
#include <cuda_runtime.h>
#include <cuda_bf16.h>
#include <cuda_fp16.h>
#include <cstdint>

// ---------------------------------------------------------------------------
// Problem constants
// ---------------------------------------------------------------------------
#define BATCH   32
#define FRAMES  32
#define NOBJ    36
#define DIN     2048
#define PDIM    512
#define MROWS   (BATCH*FRAMES*NOBJ)     // 36864
#define HEADS   (BATCH*FRAMES)          // 1024
#define NCAT    (4*PDIM)                // 2048 concat output cols

#define MTILE   128
#define NTILE   256
#define NCH     (DIN/64)                // 32 K-chunks of 64

// gemm3 (bf16 3-pass): AH 16K | AL 16K | BH 32K | BL 32K = 96K/stage, 2 stages
#define OFF_AH  0
#define OFF_AL  16384
#define OFF_BH  32768
#define OFF_BL  65536
#define STAGE3_BYTES 98304

// gemm1 (fp16 1-pass): AF 16K | BF 32K = 48K/stage, 4 stages
#define OFF_AF  0
#define OFF_BF  16384
#define STAGE1_BYTES 49152

#define GEMM_SMEM 196608
#define NB3 1152                        // gemm3 CTAs (first in grid)

// attention smem: v (36*512 f32) + logits (36*36) + transposed probs (36*40)
#define ATTN_SMEM  ((NOBJ*PDIM + NOBJ*NOBJ + NOBJ*40)*4)   // 84672 bytes

#define OUT_HALF   ((size_t)MROWS*PDIM)

// ---------------------------------------------------------------------------
// Device scratch
// ---------------------------------------------------------------------------
__device__ __nv_bfloat16 g_xh[(size_t)MROWS*DIN];
__device__ __nv_bfloat16 g_xl[(size_t)MROWS*DIN];
__device__ __half        g_xf[(size_t)MROWS*DIN];
__device__ __nv_bfloat16 g_wth[(size_t)NCAT*DIN];   // [n][k], K-major (sig/psi rows)
__device__ __nv_bfloat16 g_wtl[(size_t)NCAT*DIN];
__device__ __half        g_wf [(size_t)NCAT*DIN];   // [n][k], K-major (proj/r rows)
__device__ float g_sig[(size_t)MROWS*PDIM];
__device__ float g_psi[(size_t)MROWS*PDIM];
__device__ float g_v  [(size_t)MROWS*PDIM];

// ---------------------------------------------------------------------------
// PTX helpers
// ---------------------------------------------------------------------------
__device__ __forceinline__ uint32_t smem_u32(const void* p) {
    uint32_t a;
    asm("{ .reg .u64 t; cvta.to.shared.u64 t, %1; cvt.u32.u64 %0, t; }"
        : "=r"(a) : "l"(p));
    return a;
}

__device__ __forceinline__ void cp16(uint32_t s, const void* g) {
    asm volatile("cp.async.cg.shared.global [%0], [%1], 16;\n" :: "r"(s), "l"(g) : "memory");
}

#define LDSM4(R, A) \
    asm volatile("ldmatrix.sync.aligned.m8n8.x4.shared.b16 {%0,%1,%2,%3}, [%4];" \
        : "=r"((R)[0]), "=r"((R)[1]), "=r"((R)[2]), "=r"((R)[3]) : "r"(A))

#define MMA_BF16(C, A, B0, B1) \
    asm volatile("mma.sync.aligned.m16n8k16.row.col.f32.bf16.bf16.f32 " \
        "{%0,%1,%2,%3}, {%4,%5,%6,%7}, {%8,%9}, {%0,%1,%2,%3};" \
        : "+f"((C)[0]), "+f"((C)[1]), "+f"((C)[2]), "+f"((C)[3]) \
        : "r"((A)[0]), "r"((A)[1]), "r"((A)[2]), "r"((A)[3]), "r"(B0), "r"(B1))

#define MMA_F16(C, A, B0, B1) \
    asm volatile("mma.sync.aligned.m16n8k16.row.col.f32.f16.f16.f32 " \
        "{%0,%1,%2,%3}, {%4,%5,%6,%7}, {%8,%9}, {%0,%1,%2,%3};" \
        : "+f"((C)[0]), "+f"((C)[1]), "+f"((C)[2]), "+f"((C)[3]) \
        : "r"((A)[0]), "r"((A)[1]), "r"((A)[2]), "r"((A)[3]), "r"(B0), "r"(B1))

// 128B-row swizzle: chunk i in 0..7
#define SWZ128(r, i) ((uint32_t)((r) * 128 + (((i) * 16) ^ (((r) & 7) << 4))))

// ---------------------------------------------------------------------------
// Prep kernels: fp32 -> bf16 hi/lo (sig/psi path) and fp16 (proj/v path)
// ---------------------------------------------------------------------------
__global__ void split_x_kernel(const float* __restrict__ x, long n4) {
    long i = blockIdx.x * (long)blockDim.x + threadIdx.x;
    long stride = (long)gridDim.x * blockDim.x;
    __nv_bfloat162* xh2 = reinterpret_cast<__nv_bfloat162*>(g_xh);
    __nv_bfloat162* xl2 = reinterpret_cast<__nv_bfloat162*>(g_xl);
    __half2*        xf2 = reinterpret_cast<__half2*>(g_xf);
    for (; i < n4; i += stride) {
        float4 v = reinterpret_cast<const float4*>(x)[i];
        __nv_bfloat16 h0 = __float2bfloat16(v.x);
        __nv_bfloat16 h1 = __float2bfloat16(v.y);
        __nv_bfloat16 h2 = __float2bfloat16(v.z);
        __nv_bfloat16 h3 = __float2bfloat16(v.w);
        __nv_bfloat16 l0 = __float2bfloat16(v.x - __bfloat162float(h0));
        __nv_bfloat16 l1 = __float2bfloat16(v.y - __bfloat162float(h1));
        __nv_bfloat16 l2 = __float2bfloat16(v.z - __bfloat162float(h2));
        __nv_bfloat16 l3 = __float2bfloat16(v.w - __bfloat162float(h3));
        __nv_bfloat162 hA; hA.x = h0; hA.y = h1;
        __nv_bfloat162 hB; hB.x = h2; hB.y = h3;
        __nv_bfloat162 lA; lA.x = l0; lA.y = l1;
        __nv_bfloat162 lB; lB.x = l2; lB.y = l3;
        xh2[2*i]   = hA; xh2[2*i+1] = hB;
        xl2[2*i]   = lA; xl2[2*i+1] = lB;
        xf2[2*i]   = __floats2half2_rn(v.x, v.y);
        xf2[2*i+1] = __floats2half2_rn(v.z, v.w);
    }
}

__global__ void split_w_kernel(const float* __restrict__ Wp, const float* __restrict__ Ws,
                               const float* __restrict__ Wq, const float* __restrict__ Wr) {
    long t = blockIdx.x * (long)blockDim.x + threadIdx.x;   // over NCAT*DIN
    if (t >= (long)NCAT * DIN) return;
    int n = (int)(t >> 11);        // /DIN
    int k = (int)(t & (DIN - 1));
    int mat = n >> 9, p = n & 511;
    const float* W = (mat == 0) ? Wp : (mat == 1) ? Ws : (mat == 2) ? Wq : Wr;
    float w = W[(size_t)k * PDIM + p];
    if (mat == 1 || mat == 2) {
        __nv_bfloat16 h = __float2bfloat16(w);
        g_wth[t] = h;
        g_wtl[t] = __float2bfloat16(w - __bfloat162float(h));
    } else {
        g_wf[t] = __float2half_rn(w);
    }
}

// ---------------------------------------------------------------------------
// gemm3 path: sig/psi columns, bf16 3-pass, 128x256, 2-stage, 1 sync/chunk
// ---------------------------------------------------------------------------
__device__ __forceinline__ void load_chunk3(uint32_t sbase, int kc, int m0, int n0, int tid) {
    const char* xh = (const char*)g_xh;
    const char* xl = (const char*)g_xl;
    const char* bh = (const char*)g_wth;
    const char* bl = (const char*)g_wtl;
    size_t kcoff = (size_t)kc * 128;   // 64 bf16 = 128 bytes
#pragma unroll
    for (int q = 0; q < 2; q++) {                 // A: 128 rows x 8 x 16B
        int j = tid + q * 512;
        int r = j >> 3, i = j & 7;
        uint32_t so = SWZ128(r, i);
        size_t goA = ((size_t)(m0 + r)) * (DIN * 2) + kcoff + i * 16;
        cp16(sbase + OFF_AH + so, xh + goA);
        cp16(sbase + OFF_AL + so, xl + goA);
    }
#pragma unroll
    for (int q = 0; q < 4; q++) {                 // B: 256 rows x 8 x 16B
        int j = tid + q * 512;
        int r = j >> 3, i = j & 7;
        uint32_t so = SWZ128(r, i);
        size_t goB = ((size_t)(n0 + r)) * (DIN * 2) + kcoff + i * 16;
        cp16(sbase + OFF_BH + so, bh + goB);
        cp16(sbase + OFF_BL + so, bl + goB);
    }
    asm volatile("cp.async.commit_group;\n" ::: "memory");
}

__device__ __forceinline__ void compute_chunk3(uint32_t sbase, float (*acc)[8][4],
                                               int wm, int wn, int lane) {
    int r_off  = lane & 15;
    int kseg   = (lane >> 4) << 3;
    int n_off  = (lane & 7) + ((lane >> 4) << 3);
    int ksegb  = ((lane >> 3) & 1) << 3;
#pragma unroll
    for (int kk = 0; kk < 4; kk++) {
        uint32_t ah[2][4], al[2][4], b[4][4];
#pragma unroll
        for (int im = 0; im < 2; im++) {
            int row = wm + im * 16 + r_off;
            int kb = (kk * 16 + kseg) >> 3;
            LDSM4(ah[im], sbase + OFF_AH + SWZ128(row, kb));
            LDSM4(al[im], sbase + OFF_AL + SWZ128(row, kb));
        }
#pragma unroll
        for (int j = 0; j < 4; j++) {
            int row = wn + j * 16 + n_off;
            int kb = (kk * 16 + ksegb) >> 3;
            LDSM4(b[j], sbase + OFF_BH + SWZ128(row, kb));
        }
        // pass 1: Ah*Bh  (16 independent accumulator chains)
#pragma unroll
        for (int im = 0; im < 2; im++)
#pragma unroll
            for (int j = 0; j < 4; j++) {
                MMA_BF16(acc[im][2*j],   ah[im], b[j][0], b[j][1]);
                MMA_BF16(acc[im][2*j+1], ah[im], b[j][2], b[j][3]);
            }
        // pass 2: Al*Bh
#pragma unroll
        for (int im = 0; im < 2; im++)
#pragma unroll
            for (int j = 0; j < 4; j++) {
                MMA_BF16(acc[im][2*j],   al[im], b[j][0], b[j][1]);
                MMA_BF16(acc[im][2*j+1], al[im], b[j][2], b[j][3]);
            }
        // B-lo (recycle regs)
#pragma unroll
        for (int j = 0; j < 4; j++) {
            int row = wn + j * 16 + n_off;
            int kb = (kk * 16 + ksegb) >> 3;
            LDSM4(b[j], sbase + OFF_BL + SWZ128(row, kb));
        }
        // pass 3: Ah*Bl
#pragma unroll
        for (int im = 0; im < 2; im++)
#pragma unroll
            for (int j = 0; j < 4; j++) {
                MMA_BF16(acc[im][2*j],   ah[im], b[j][0], b[j][1]);
                MMA_BF16(acc[im][2*j+1], ah[im], b[j][2], b[j][3]);
            }
    }
}

// ---------------------------------------------------------------------------
// gemm1 path: r_feat / v columns, fp16 1-pass, 128x256, 4-stage (round-7 form)
// ---------------------------------------------------------------------------
__device__ __forceinline__ void load_chunk1(uint32_t sbase, int kc, int m0, int n0, int tid) {
    const char* xf = (const char*)g_xf;
    const char* bf = (const char*)g_wf;
    size_t kcoff = (size_t)kc * 128;
#pragma unroll
    for (int q = 0; q < 2; q++) {                 // A: 128 rows x 8 x 16B
        int j = tid + q * 512;
        int r = j >> 3, i = j & 7;
        uint32_t so = SWZ128(r, i);
        size_t goA = ((size_t)(m0 + r)) * (DIN * 2) + kcoff + i * 16;
        cp16(sbase + OFF_AF + so, xf + goA);
    }
#pragma unroll
    for (int q = 0; q < 4; q++) {                 // B: 256 rows x 8 x 16B
        int j = tid + q * 512;
        int r = j >> 3, i = j & 7;
        uint32_t so = SWZ128(r, i);
        size_t goB = ((size_t)(n0 + r)) * (DIN * 2) + kcoff + i * 16;
        cp16(sbase + OFF_BF + so, bf + goB);
    }
    asm volatile("cp.async.commit_group;\n" ::: "memory");
}

__device__ __forceinline__ void compute_chunk1(uint32_t sbase, float (*acc)[8][4],
                                               int wm, int wn, int lane) {
    int r_off  = lane & 15;
    int kseg   = (lane >> 4) << 3;
    int n_off  = (lane & 7) + ((lane >> 4) << 3);
    int ksegb  = ((lane >> 3) & 1) << 3;
#pragma unroll
    for (int kk = 0; kk < 4; kk++) {
        uint32_t af[2][4], b[4][4];
#pragma unroll
        for (int im = 0; im < 2; im++) {
            int row = wm + im * 16 + r_off;
            int kb = (kk * 16 + kseg) >> 3;
            LDSM4(af[im], sbase + OFF_AF + SWZ128(row, kb));
        }
#pragma unroll
        for (int j = 0; j < 4; j++) {
            int row = wn + j * 16 + n_off;
            int kb = (kk * 16 + ksegb) >> 3;
            LDSM4(b[j], sbase + OFF_BF + SWZ128(row, kb));
        }
#pragma unroll
        for (int im = 0; im < 2; im++)
#pragma unroll
            for (int j = 0; j < 4; j++) {
                MMA_F16(acc[im][2*j],   af[im], b[j][0], b[j][1]);
                MMA_F16(acc[im][2*j+1], af[im], b[j][2], b[j][3]);
            }
    }
}

// ---------------------------------------------------------------------------
// Fused GEMM kernel: blocks [0,1152) = gemm3 (sig/psi), [1152,2304) = gemm1.
// ---------------------------------------------------------------------------
__global__ void __launch_bounds__(512, 1) gemm_fused_kernel(
    const float* __restrict__ b_sigma, const float* __restrict__ b_psi,
    const float* __restrict__ b_proj, float* __restrict__ out_rfeat)
{
    extern __shared__ char smem[];
    uint32_t sb = smem_u32(smem);
    int tid = threadIdx.x;
    int wid = tid >> 5, lane = tid & 31;
    int wm = (wid >> 2) * 32, wn = (wid & 3) * 64;

    float acc[2][8][4];
#pragma unroll
    for (int a = 0; a < 2; a++)
#pragma unroll
        for (int b = 0; b < 8; b++)
#pragma unroll
            for (int c = 0; c < 4; c++) acc[a][b][c] = 0.f;

    if (blockIdx.x < NB3) {
        // ---- gemm3: bf16 3-pass over concat cols 512..1535 ----
        int bid = blockIdx.x;
        int nt = bid & 3, mt = bid >> 2;
        int m0 = mt * MTILE, n0 = 512 + nt * NTILE;

        load_chunk3(sb, 0, m0, n0, tid);
        for (int c = 0; c < NCH; c++) {
            asm volatile("cp.async.wait_group 0;" ::: "memory");
            __syncthreads();
            if (c + 1 < NCH)
                load_chunk3(sb + ((c + 1) & 1) * STAGE3_BYTES, c + 1, m0, n0, tid);
            compute_chunk3(sb + (c & 1) * STAGE3_BYTES, acc, wm, wn, lane);
        }

        const float* bias = (nt < 2) ? b_sigma : b_psi;
        float* dest = (nt < 2) ? g_sig : g_psi;
        int colbase = (nt & 1) * 256;
        int groupID = lane >> 2, tig = lane & 3;
#pragma unroll
        for (int im = 0; im < 2; im++)
#pragma unroll
            for (int in = 0; in < 8; in++) {
                int col = colbase + wn + in * 8 + tig * 2;
                float2 bv = __ldg((const float2*)&bias[col]);
                int row0 = m0 + wm + im * 16 + groupID;
                float2 v0, v1;
                v0.x = acc[im][in][0] + bv.x; v0.y = acc[im][in][1] + bv.y;
                v1.x = acc[im][in][2] + bv.x; v1.y = acc[im][in][3] + bv.y;
                *(float2*)&dest[(size_t)row0 * PDIM + col]       = v0;
                *(float2*)&dest[(size_t)(row0 + 8) * PDIM + col] = v1;
            }
    } else {
        // ---- gemm1: fp16 1-pass over concat cols 0..511 and 1536..2047 ----
        int bid = blockIdx.x - NB3;
        int nt = bid & 3, mt = bid >> 2;
        int m0 = mt * MTILE;
        int n0 = (nt < 2) ? nt * NTILE : 1536 + (nt - 2) * NTILE;

        load_chunk1(sb + 0 * STAGE1_BYTES, 0, m0, n0, tid);
        load_chunk1(sb + 1 * STAGE1_BYTES, 1, m0, n0, tid);
        load_chunk1(sb + 2 * STAGE1_BYTES, 2, m0, n0, tid);

        for (int c = 0; c < NCH; c++) {
            if (c < NCH - 2)       asm volatile("cp.async.wait_group 2;" ::: "memory");
            else if (c == NCH - 2) asm volatile("cp.async.wait_group 1;" ::: "memory");
            else                   asm volatile("cp.async.wait_group 0;" ::: "memory");
            __syncthreads();
            if (c + 3 < NCH)
                load_chunk1(sb + ((c + 3) & 3) * STAGE1_BYTES, c + 3, m0, n0, tid);
            compute_chunk1(sb + (c & 3) * STAGE1_BYTES, acc, wm, wn, lane);
        }

        const float* bias = (nt < 2) ? b_proj : nullptr;
        float* dest = (nt < 2) ? out_rfeat : g_v;
        int colbase = (nt & 1) * 256;
        int groupID = lane >> 2, tig = lane & 3;
#pragma unroll
        for (int im = 0; im < 2; im++)
#pragma unroll
            for (int in = 0; in < 8; in++) {
                int col = colbase + wn + in * 8 + tig * 2;
                float2 bv = make_float2(0.f, 0.f);
                if (bias) bv = __ldg((const float2*)&bias[col]);
                int row0 = m0 + wm + im * 16 + groupID;
                float2 v0, v1;
                v0.x = acc[im][in][0] + bv.x; v0.y = acc[im][in][1] + bv.y;
                v1.x = acc[im][in][2] + bv.x; v1.y = acc[im][in][3] + bv.y;
                *(float2*)&dest[(size_t)row0 * PDIM + col]       = v0;
                *(float2*)&dest[(size_t)(row0 + 8) * PDIM + col] = v1;
            }
    }
}

// ---------------------------------------------------------------------------
// Attention: per-head softmax(sig psi^T) @ v.  1 CTA/head, 256 threads,
// 2 CTAs/SM.  v staged via cp.async overlapped with QK.  QK: warp handles
// row PAIRS so each psi load feeds two accumulator rows (halves LDG traffic);
// lanes split K (coalesced), shfl-butterfly reduce.  AV: transposed probs,
// 18-row v reuse.
// ---------------------------------------------------------------------------
__global__ void __launch_bounds__(256, 2) attn_kernel(float* __restrict__ out_rhat) {
    extern __shared__ float as[];
    float* v_s = as;                          // 36*512
    float* l_s = as + NOBJ * PDIM;            // 36*36   logits, n-major
    float* l_t = l_s + NOBJ * NOBJ;           // 36*40   probs, m-major (padded)
    int h = blockIdx.x;
    int tid = threadIdx.x;
    int w = tid >> 5, lane = tid & 31;
    size_t base = (size_t)h * NOBJ;

    // v staging via cp.async — overlapped with the QK phase below.
    {
        uint32_t vsb = smem_u32(v_s);
        const float4* gv = (const float4*)(g_v + base * PDIM);
#pragma unroll
        for (int q = 0; q < 18; q++) {        // 4608 float4s
            int i = tid + q * 256;
            cp16(vsb + (uint32_t)i * 16, gv + i);
        }
        asm volatile("cp.async.commit_group;\n" ::: "memory");
    }

    const float4* pp = (const float4*)(g_psi + base * PDIM);   // psi row m at pp+m*128

    // Row pairs: warp w computes (w, w+8) then (w+16, w+24).
#pragma unroll
    for (int pr = 0; pr < 2; pr++) {
        int n0 = w + 16 * pr, n1 = w + 8 + 16 * pr;
        const float4* sg0 = (const float4*)(g_sig + (base + n0) * PDIM);
        const float4* sg1 = (const float4*)(g_sig + (base + n1) * PDIM);
#pragma unroll
        for (int mh = 0; mh < 2; mh++) {
            float a0[18], a1[18];
#pragma unroll
            for (int m = 0; m < 18; m++) { a0[m] = 0.f; a1[m] = 0.f; }
#pragma unroll
            for (int it = 0; it < 4; it++) {
                float4 s0 = __ldg(&sg0[lane + 32 * it]);
                float4 s1 = __ldg(&sg1[lane + 32 * it]);
#pragma unroll
                for (int m = 0; m < 18; m++) {
                    float4 p = __ldg(&pp[(mh * 18 + m) * 128 + lane + 32 * it]);
                    a0[m] += s0.x * p.x + s0.y * p.y + s0.z * p.z + s0.w * p.w;
                    a1[m] += s1.x * p.x + s1.y * p.y + s1.z * p.z + s1.w * p.w;
                }
            }
#pragma unroll
            for (int off = 16; off > 0; off >>= 1)
#pragma unroll
                for (int m = 0; m < 18; m++) {
                    a0[m] += __shfl_xor_sync(0xFFFFFFFF, a0[m], off);
                    a1[m] += __shfl_xor_sync(0xFFFFFFFF, a1[m], off);
                }
            if (lane == 0) {
#pragma unroll
                for (int m = 0; m < 18; m++) {
                    l_s[n0 * 36 + mh * 18 + m] = a0[m];
                    l_s[n1 * 36 + mh * 18 + m] = a1[m];
                }
            }
        }
    }
    // Remaining rows 32..35: warps 0..3, single-row path.
    if (w < 4) {
        int n = 32 + w;
        const float4* sg = (const float4*)(g_sig + (base + n) * PDIM);
        float accm[36];
#pragma unroll
        for (int m = 0; m < 36; m++) accm[m] = 0.f;
#pragma unroll
        for (int it = 0; it < 4; it++) {
            float4 s = __ldg(&sg[lane + 32 * it]);
#pragma unroll
            for (int m = 0; m < 36; m++) {
                float4 p = __ldg(&pp[m * 128 + lane + 32 * it]);
                accm[m] += s.x * p.x + s.y * p.y + s.z * p.z + s.w * p.w;
            }
        }
#pragma unroll
        for (int off = 16; off > 0; off >>= 1)
#pragma unroll
            for (int m = 0; m < 36; m++)
                accm[m] += __shfl_xor_sync(0xFFFFFFFF, accm[m], off);
        if (lane == 0) {
#pragma unroll
            for (int m = 0; m < 36; m++) l_s[n * 36 + m] = accm[m];
        }
    }

    // v staging must be complete (per-thread) before the barrier publishes it.
    asm volatile("cp.async.wait_group 0;" ::: "memory");
    __syncthreads();

    // row softmax; write probs transposed (m-major) for vectorized AV loads
    if (tid < 36) {
        float row[36];
        float m = -1e30f;
#pragma unroll
        for (int j = 0; j < 36; j++) { row[j] = l_s[tid * 36 + j]; m = fmaxf(m, row[j]); }
        float ssum = 0.f;
#pragma unroll
        for (int j = 0; j < 36; j++) { float e = __expf(row[j] - m); row[j] = e; ssum += e; }
        float inv = 1.f / ssum;
#pragma unroll
        for (int j = 0; j < 36; j++) l_t[j * 40 + tid] = row[j] * inv;
    }
    __syncthreads();

    // AV: out[n][p] = sum_m a[n][m] v[m][p]; each thread: 1 col-chunk x 18 rows
    int c4 = tid & 127, nh = tid >> 7;
    float4 acc[18];
#pragma unroll
    for (int j = 0; j < 18; j++) acc[j] = make_float4(0.f, 0.f, 0.f, 0.f);
    const float4* vrow = (const float4*)v_s + c4;
#pragma unroll 4
    for (int m = 0; m < 36; m++) {
        float4 vv = vrow[m * 128];
#pragma unroll
        for (int jj = 0; jj < 9; jj++) {
            float2 aa = *(const float2*)&l_t[m * 40 + nh * 18 + jj * 2];
            acc[2*jj].x   += aa.x * vv.x; acc[2*jj].y   += aa.x * vv.y;
            acc[2*jj].z   += aa.x * vv.z; acc[2*jj].w   += aa.x * vv.w;
            acc[2*jj+1].x += aa.y * vv.x; acc[2*jj+1].y += aa.y * vv.y;
            acc[2*jj+1].z += aa.y * vv.z; acc[2*jj+1].w += aa.y * vv.w;
        }
    }
    float4* vo = (float4*)(out_rhat + base * PDIM);
#pragma unroll
    for (int j = 0; j < 18; j++) {
        int n = nh * 18 + j;
        vo[n * 128 + c4] = acc[j];
    }
}

// ---------------------------------------------------------------------------
// Launcher
// ---------------------------------------------------------------------------
extern "C" void kernel_launch(void* const* d_in, const int* in_sizes, int n_in,
                              void* d_out, int out_size) {
    const float* x       = (const float*)d_in[0];
    const float* W_proj  = (const float*)d_in[1];
    const float* b_proj  = (const float*)d_in[2];
    const float* W_sigma = (const float*)d_in[3];
    const float* b_sigma = (const float*)d_in[4];
    const float* W_psi   = (const float*)d_in[5];
    const float* b_psi   = (const float*)d_in[6];
    const float* W_r     = (const float*)d_in[7];
    float* out = (float*)d_out;

    cudaFuncSetAttribute(gemm_fused_kernel, cudaFuncAttributeMaxDynamicSharedMemorySize, GEMM_SMEM);
    cudaFuncSetAttribute(attn_kernel, cudaFuncAttributeMaxDynamicSharedMemorySize, ATTN_SMEM);

    long n4 = (long)MROWS * DIN / 4;
    split_x_kernel<<<8192, 256>>>(x, n4);
    split_w_kernel<<<(NCAT * DIN + 255) / 256, 256>>>(W_proj, W_sigma, W_psi, W_r);
    gemm_fused_kernel<<<2 * NB3, 512, GEMM_SMEM>>>(b_sigma, b_psi, b_proj, out);
    attn_kernel<<<HEADS, 256, ATTN_SMEM>>>(out + OUT_HALF);
}

// round 16
// speedup vs baseline: 1.3175x; 1.0107x over previous
#include <cuda_runtime.h>
#include <cuda_bf16.h>
#include <cuda_fp16.h>
#include <cstdint>

// ---------------------------------------------------------------------------
// Problem constants
// ---------------------------------------------------------------------------
#define BATCH   32
#define FRAMES  32
#define NOBJ    36
#define DIN     2048
#define PDIM    512
#define MROWS   (BATCH*FRAMES*NOBJ)     // 36864
#define HEADS   (BATCH*FRAMES)          // 1024
#define NCAT    (4*PDIM)                // 2048 concat output cols

#define MTILE   128
#define NTILE   256
#define NCH     (DIN/64)                // 32 K-chunks of 64

// gemm3 (fp16 hi/lo 3-pass): AH 16K | AL 16K | BH 32K | BL 32K = 96K/stage, 2 stages
#define OFF_AH  0
#define OFF_AL  16384
#define OFF_BH  32768
#define OFF_BL  65536
#define STAGE3_BYTES 98304

// gemm1 (fp16 1-pass): AF 16K | BF 32K = 48K/stage, 4 stages
#define OFF_AF  0
#define OFF_BF  16384
#define STAGE1_BYTES 49152

#define GEMM_SMEM 196608
#define NB3 1152                        // gemm3 CTAs (first in grid)

// attention smem: v (36*512 f32) + logits (36*36) + transposed probs (36*40)
#define ATTN_SMEM  ((NOBJ*PDIM + NOBJ*NOBJ + NOBJ*40)*4)   // 84672 bytes

#define OUT_HALF   ((size_t)MROWS*PDIM)

// ---------------------------------------------------------------------------
// Device scratch — x split once in fp16; g_xh doubles as gemm1's A operand.
// ---------------------------------------------------------------------------
__device__ __half g_xh[(size_t)MROWS*DIN];          // fp16(x)          (hi)
__device__ __half g_xl[(size_t)MROWS*DIN];          // fp16(x - hi)     (lo)
__device__ __half g_wth[(size_t)NCAT*DIN];          // [n][k] K-major, sig/psi W hi
__device__ __half g_wtl[(size_t)NCAT*DIN];          // sig/psi W lo
__device__ __half g_wf [(size_t)NCAT*DIN];          // [n][k] K-major, proj/r W fp16
__device__ float g_sig[(size_t)MROWS*PDIM];
__device__ float g_psi[(size_t)MROWS*PDIM];
__device__ float g_v  [(size_t)MROWS*PDIM];

// ---------------------------------------------------------------------------
// PTX helpers
// ---------------------------------------------------------------------------
__device__ __forceinline__ uint32_t smem_u32(const void* p) {
    uint32_t a;
    asm("{ .reg .u64 t; cvta.to.shared.u64 t, %1; cvt.u32.u64 %0, t; }"
        : "=r"(a) : "l"(p));
    return a;
}

__device__ __forceinline__ void cp16(uint32_t s, const void* g) {
    asm volatile("cp.async.cg.shared.global [%0], [%1], 16;\n" :: "r"(s), "l"(g) : "memory");
}

#define LDSM4(R, A) \
    asm volatile("ldmatrix.sync.aligned.m8n8.x4.shared.b16 {%0,%1,%2,%3}, [%4];" \
        : "=r"((R)[0]), "=r"((R)[1]), "=r"((R)[2]), "=r"((R)[3]) : "r"(A))

#define MMA_F16(C, A, B0, B1) \
    asm volatile("mma.sync.aligned.m16n8k16.row.col.f32.f16.f16.f32 " \
        "{%0,%1,%2,%3}, {%4,%5,%6,%7}, {%8,%9}, {%0,%1,%2,%3};" \
        : "+f"((C)[0]), "+f"((C)[1]), "+f"((C)[2]), "+f"((C)[3]) \
        : "r"((A)[0]), "r"((A)[1]), "r"((A)[2]), "r"((A)[3]), "r"(B0), "r"(B1))

// 128B-row swizzle: chunk i in 0..7
#define SWZ128(r, i) ((uint32_t)((r) * 128 + (((i) * 16) ^ (((r) & 7) << 4))))

// ---------------------------------------------------------------------------
// Prep kernels: fp32 -> fp16 hi/lo (x) ; W -> fp16 hi/lo (sig/psi) or fp16
// ---------------------------------------------------------------------------
__global__ void split_x_kernel(const float* __restrict__ x, long n4) {
    long i = blockIdx.x * (long)blockDim.x + threadIdx.x;
    long stride = (long)gridDim.x * blockDim.x;
    __half2* xh2 = reinterpret_cast<__half2*>(g_xh);
    __half2* xl2 = reinterpret_cast<__half2*>(g_xl);
    for (; i < n4; i += stride) {
        float4 v = reinterpret_cast<const float4*>(x)[i];
        __half h0 = __float2half_rn(v.x);
        __half h1 = __float2half_rn(v.y);
        __half h2 = __float2half_rn(v.z);
        __half h3 = __float2half_rn(v.w);
        __half l0 = __float2half_rn(v.x - __half2float(h0));
        __half l1 = __float2half_rn(v.y - __half2float(h1));
        __half l2 = __float2half_rn(v.z - __half2float(h2));
        __half l3 = __float2half_rn(v.w - __half2float(h3));
        __half2 hA; hA.x = h0; hA.y = h1;
        __half2 hB; hB.x = h2; hB.y = h3;
        __half2 lA; lA.x = l0; lA.y = l1;
        __half2 lB; lB.x = l2; lB.y = l3;
        xh2[2*i]   = hA; xh2[2*i+1] = hB;
        xl2[2*i]   = lA; xl2[2*i+1] = lB;
    }
}

__global__ void split_w_kernel(const float* __restrict__ Wp, const float* __restrict__ Ws,
                               const float* __restrict__ Wq, const float* __restrict__ Wr) {
    long t = blockIdx.x * (long)blockDim.x + threadIdx.x;   // over NCAT*DIN
    if (t >= (long)NCAT * DIN) return;
    int n = (int)(t >> 11);        // /DIN
    int k = (int)(t & (DIN - 1));
    int mat = n >> 9, p = n & 511;
    const float* W = (mat == 0) ? Wp : (mat == 1) ? Ws : (mat == 2) ? Wq : Wr;
    float w = W[(size_t)k * PDIM + p];
    if (mat == 1 || mat == 2) {
        __half h = __float2half_rn(w);
        g_wth[t] = h;
        g_wtl[t] = __float2half_rn(w - __half2float(h));
    } else {
        g_wf[t] = __float2half_rn(w);
    }
}

// ---------------------------------------------------------------------------
// gemm3 path: sig/psi columns, fp16 hi/lo 3-pass, 128x256, 2-stage, 1 sync/chunk
// ---------------------------------------------------------------------------
__device__ __forceinline__ void load_chunk3(uint32_t sbase, int kc, int m0, int n0, int tid) {
    const char* xh = (const char*)g_xh;
    const char* xl = (const char*)g_xl;
    const char* bh = (const char*)g_wth;
    const char* bl = (const char*)g_wtl;
    size_t kcoff = (size_t)kc * 128;   // 64 fp16 = 128 bytes
#pragma unroll
    for (int q = 0; q < 2; q++) {                 // A: 128 rows x 8 x 16B
        int j = tid + q * 512;
        int r = j >> 3, i = j & 7;
        uint32_t so = SWZ128(r, i);
        size_t goA = ((size_t)(m0 + r)) * (DIN * 2) + kcoff + i * 16;
        cp16(sbase + OFF_AH + so, xh + goA);
        cp16(sbase + OFF_AL + so, xl + goA);
    }
#pragma unroll
    for (int q = 0; q < 4; q++) {                 // B: 256 rows x 8 x 16B
        int j = tid + q * 512;
        int r = j >> 3, i = j & 7;
        uint32_t so = SWZ128(r, i);
        size_t goB = ((size_t)(n0 + r)) * (DIN * 2) + kcoff + i * 16;
        cp16(sbase + OFF_BH + so, bh + goB);
        cp16(sbase + OFF_BL + so, bl + goB);
    }
    asm volatile("cp.async.commit_group;\n" ::: "memory");
}

__device__ __forceinline__ void compute_chunk3(uint32_t sbase, float (*acc)[8][4],
                                               int wm, int wn, int lane) {
    int r_off  = lane & 15;
    int kseg   = (lane >> 4) << 3;
    int n_off  = (lane & 7) + ((lane >> 4) << 3);
    int ksegb  = ((lane >> 3) & 1) << 3;
#pragma unroll
    for (int kk = 0; kk < 4; kk++) {
        uint32_t ah[2][4], al[2][4], b[4][4];
#pragma unroll
        for (int im = 0; im < 2; im++) {
            int row = wm + im * 16 + r_off;
            int kb = (kk * 16 + kseg) >> 3;
            LDSM4(ah[im], sbase + OFF_AH + SWZ128(row, kb));
            LDSM4(al[im], sbase + OFF_AL + SWZ128(row, kb));
        }
#pragma unroll
        for (int j = 0; j < 4; j++) {
            int row = wn + j * 16 + n_off;
            int kb = (kk * 16 + ksegb) >> 3;
            LDSM4(b[j], sbase + OFF_BH + SWZ128(row, kb));
        }
        // pass 1: Ah*Bh  (16 independent accumulator chains)
#pragma unroll
        for (int im = 0; im < 2; im++)
#pragma unroll
            for (int j = 0; j < 4; j++) {
                MMA_F16(acc[im][2*j],   ah[im], b[j][0], b[j][1]);
                MMA_F16(acc[im][2*j+1], ah[im], b[j][2], b[j][3]);
            }
        // pass 2: Al*Bh
#pragma unroll
        for (int im = 0; im < 2; im++)
#pragma unroll
            for (int j = 0; j < 4; j++) {
                MMA_F16(acc[im][2*j],   al[im], b[j][0], b[j][1]);
                MMA_F16(acc[im][2*j+1], al[im], b[j][2], b[j][3]);
            }
        // B-lo (recycle regs)
#pragma unroll
        for (int j = 0; j < 4; j++) {
            int row = wn + j * 16 + n_off;
            int kb = (kk * 16 + ksegb) >> 3;
            LDSM4(b[j], sbase + OFF_BL + SWZ128(row, kb));
        }
        // pass 3: Ah*Bl
#pragma unroll
        for (int im = 0; im < 2; im++)
#pragma unroll
            for (int j = 0; j < 4; j++) {
                MMA_F16(acc[im][2*j],   ah[im], b[j][0], b[j][1]);
                MMA_F16(acc[im][2*j+1], ah[im], b[j][2], b[j][3]);
            }
    }
}

// ---------------------------------------------------------------------------
// gemm1 path: r_feat / v columns, fp16 1-pass, 128x256, 4-stage
// A operand = g_xh (fp16(x), identical values to the old dedicated fp16 copy)
// ---------------------------------------------------------------------------
__device__ __forceinline__ void load_chunk1(uint32_t sbase, int kc, int m0, int n0, int tid) {
    const char* xf = (const char*)g_xh;
    const char* bf = (const char*)g_wf;
    size_t kcoff = (size_t)kc * 128;
#pragma unroll
    for (int q = 0; q < 2; q++) {                 // A: 128 rows x 8 x 16B
        int j = tid + q * 512;
        int r = j >> 3, i = j & 7;
        uint32_t so = SWZ128(r, i);
        size_t goA = ((size_t)(m0 + r)) * (DIN * 2) + kcoff + i * 16;
        cp16(sbase + OFF_AF + so, xf + goA);
    }
#pragma unroll
    for (int q = 0; q < 4; q++) {                 // B: 256 rows x 8 x 16B
        int j = tid + q * 512;
        int r = j >> 3, i = j & 7;
        uint32_t so = SWZ128(r, i);
        size_t goB = ((size_t)(n0 + r)) * (DIN * 2) + kcoff + i * 16;
        cp16(sbase + OFF_BF + so, bf + goB);
    }
    asm volatile("cp.async.commit_group;\n" ::: "memory");
}

__device__ __forceinline__ void compute_chunk1(uint32_t sbase, float (*acc)[8][4],
                                               int wm, int wn, int lane) {
    int r_off  = lane & 15;
    int kseg   = (lane >> 4) << 3;
    int n_off  = (lane & 7) + ((lane >> 4) << 3);
    int ksegb  = ((lane >> 3) & 1) << 3;
#pragma unroll
    for (int kk = 0; kk < 4; kk++) {
        uint32_t af[2][4], b[4][4];
#pragma unroll
        for (int im = 0; im < 2; im++) {
            int row = wm + im * 16 + r_off;
            int kb = (kk * 16 + kseg) >> 3;
            LDSM4(af[im], sbase + OFF_AF + SWZ128(row, kb));
        }
#pragma unroll
        for (int j = 0; j < 4; j++) {
            int row = wn + j * 16 + n_off;
            int kb = (kk * 16 + ksegb) >> 3;
            LDSM4(b[j], sbase + OFF_BF + SWZ128(row, kb));
        }
#pragma unroll
        for (int im = 0; im < 2; im++)
#pragma unroll
            for (int j = 0; j < 4; j++) {
                MMA_F16(acc[im][2*j],   af[im], b[j][0], b[j][1]);
                MMA_F16(acc[im][2*j+1], af[im], b[j][2], b[j][3]);
            }
    }
}

// ---------------------------------------------------------------------------
// Fused GEMM kernel: blocks [0,1152) = gemm3 (sig/psi), [1152,2304) = gemm1.
// ---------------------------------------------------------------------------
__global__ void __launch_bounds__(512, 1) gemm_fused_kernel(
    const float* __restrict__ b_sigma, const float* __restrict__ b_psi,
    const float* __restrict__ b_proj, float* __restrict__ out_rfeat)
{
    extern __shared__ char smem[];
    uint32_t sb = smem_u32(smem);
    int tid = threadIdx.x;
    int wid = tid >> 5, lane = tid & 31;
    int wm = (wid >> 2) * 32, wn = (wid & 3) * 64;

    float acc[2][8][4];
#pragma unroll
    for (int a = 0; a < 2; a++)
#pragma unroll
        for (int b = 0; b < 8; b++)
#pragma unroll
            for (int c = 0; c < 4; c++) acc[a][b][c] = 0.f;

    if (blockIdx.x < NB3) {
        // ---- gemm3: fp16 hi/lo 3-pass over concat cols 512..1535 ----
        int bid = blockIdx.x;
        int nt = bid & 3, mt = bid >> 2;
        int m0 = mt * MTILE, n0 = 512 + nt * NTILE;

        load_chunk3(sb, 0, m0, n0, tid);
        for (int c = 0; c < NCH; c++) {
            asm volatile("cp.async.wait_group 0;" ::: "memory");
            __syncthreads();
            if (c + 1 < NCH)
                load_chunk3(sb + ((c + 1) & 1) * STAGE3_BYTES, c + 1, m0, n0, tid);
            compute_chunk3(sb + (c & 1) * STAGE3_BYTES, acc, wm, wn, lane);
        }

        const float* bias = (nt < 2) ? b_sigma : b_psi;
        float* dest = (nt < 2) ? g_sig : g_psi;
        int colbase = (nt & 1) * 256;
        int groupID = lane >> 2, tig = lane & 3;
#pragma unroll
        for (int im = 0; im < 2; im++)
#pragma unroll
            for (int in = 0; in < 8; in++) {
                int col = colbase + wn + in * 8 + tig * 2;
                float2 bv = __ldg((const float2*)&bias[col]);
                int row0 = m0 + wm + im * 16 + groupID;
                float2 v0, v1;
                v0.x = acc[im][in][0] + bv.x; v0.y = acc[im][in][1] + bv.y;
                v1.x = acc[im][in][2] + bv.x; v1.y = acc[im][in][3] + bv.y;
                *(float2*)&dest[(size_t)row0 * PDIM + col]       = v0;
                *(float2*)&dest[(size_t)(row0 + 8) * PDIM + col] = v1;
            }
    } else {
        // ---- gemm1: fp16 1-pass over concat cols 0..511 and 1536..2047 ----
        int bid = blockIdx.x - NB3;
        int nt = bid & 3, mt = bid >> 2;
        int m0 = mt * MTILE;
        int n0 = (nt < 2) ? nt * NTILE : 1536 + (nt - 2) * NTILE;

        load_chunk1(sb + 0 * STAGE1_BYTES, 0, m0, n0, tid);
        load_chunk1(sb + 1 * STAGE1_BYTES, 1, m0, n0, tid);
        load_chunk1(sb + 2 * STAGE1_BYTES, 2, m0, n0, tid);

        for (int c = 0; c < NCH; c++) {
            if (c < NCH - 2)       asm volatile("cp.async.wait_group 2;" ::: "memory");
            else if (c == NCH - 2) asm volatile("cp.async.wait_group 1;" ::: "memory");
            else                   asm volatile("cp.async.wait_group 0;" ::: "memory");
            __syncthreads();
            if (c + 3 < NCH)
                load_chunk1(sb + ((c + 3) & 3) * STAGE1_BYTES, c + 3, m0, n0, tid);
            compute_chunk1(sb + (c & 3) * STAGE1_BYTES, acc, wm, wn, lane);
        }

        const float* bias = (nt < 2) ? b_proj : nullptr;
        float* dest = (nt < 2) ? out_rfeat : g_v;
        int colbase = (nt & 1) * 256;
        int groupID = lane >> 2, tig = lane & 3;
#pragma unroll
        for (int im = 0; im < 2; im++)
#pragma unroll
            for (int in = 0; in < 8; in++) {
                int col = colbase + wn + in * 8 + tig * 2;
                float2 bv = make_float2(0.f, 0.f);
                if (bias) bv = __ldg((const float2*)&bias[col]);
                int row0 = m0 + wm + im * 16 + groupID;
                float2 v0, v1;
                v0.x = acc[im][in][0] + bv.x; v0.y = acc[im][in][1] + bv.y;
                v1.x = acc[im][in][2] + bv.x; v1.y = acc[im][in][3] + bv.y;
                *(float2*)&dest[(size_t)row0 * PDIM + col]       = v0;
                *(float2*)&dest[(size_t)(row0 + 8) * PDIM + col] = v1;
            }
    }
}

// ---------------------------------------------------------------------------
// Attention: per-head softmax(sig psi^T) @ v.  1 CTA/head, 256 threads,
// 2 CTAs/SM.  v staged via cp.async overlapped with QK.  QK: warp handles
// row PAIRS so each psi load feeds two accumulator rows; lanes split K
// (coalesced), shfl-butterfly reduce.  AV: transposed probs, 18-row v reuse.
// ---------------------------------------------------------------------------
__global__ void __launch_bounds__(256, 2) attn_kernel(float* __restrict__ out_rhat) {
    extern __shared__ float as[];
    float* v_s = as;                          // 36*512
    float* l_s = as + NOBJ * PDIM;            // 36*36   logits, n-major
    float* l_t = l_s + NOBJ * NOBJ;           // 36*40   probs, m-major (padded)
    int h = blockIdx.x;
    int tid = threadIdx.x;
    int w = tid >> 5, lane = tid & 31;
    size_t base = (size_t)h * NOBJ;

    // v staging via cp.async — overlapped with the QK phase below.
    {
        uint32_t vsb = smem_u32(v_s);
        const float4* gv = (const float4*)(g_v + base * PDIM);
#pragma unroll
        for (int q = 0; q < 18; q++) {        // 4608 float4s
            int i = tid + q * 256;
            cp16(vsb + (uint32_t)i * 16, gv + i);
        }
        asm volatile("cp.async.commit_group;\n" ::: "memory");
    }

    const float4* pp = (const float4*)(g_psi + base * PDIM);   // psi row m at pp+m*128

    // Row pairs: warp w computes (w, w+8) then (w+16, w+24).
#pragma unroll
    for (int pr = 0; pr < 2; pr++) {
        int n0 = w + 16 * pr, n1 = w + 8 + 16 * pr;
        const float4* sg0 = (const float4*)(g_sig + (base + n0) * PDIM);
        const float4* sg1 = (const float4*)(g_sig + (base + n1) * PDIM);
#pragma unroll
        for (int mh = 0; mh < 2; mh++) {
            float a0[18], a1[18];
#pragma unroll
            for (int m = 0; m < 18; m++) { a0[m] = 0.f; a1[m] = 0.f; }
#pragma unroll
            for (int it = 0; it < 4; it++) {
                float4 s0 = __ldg(&sg0[lane + 32 * it]);
                float4 s1 = __ldg(&sg1[lane + 32 * it]);
#pragma unroll
                for (int m = 0; m < 18; m++) {
                    float4 p = __ldg(&pp[(mh * 18 + m) * 128 + lane + 32 * it]);
                    a0[m] += s0.x * p.x + s0.y * p.y + s0.z * p.z + s0.w * p.w;
                    a1[m] += s1.x * p.x + s1.y * p.y + s1.z * p.z + s1.w * p.w;
                }
            }
#pragma unroll
            for (int off = 16; off > 0; off >>= 1)
#pragma unroll
                for (int m = 0; m < 18; m++) {
                    a0[m] += __shfl_xor_sync(0xFFFFFFFF, a0[m], off);
                    a1[m] += __shfl_xor_sync(0xFFFFFFFF, a1[m], off);
                }
            if (lane == 0) {
#pragma unroll
                for (int m = 0; m < 18; m++) {
                    l_s[n0 * 36 + mh * 18 + m] = a0[m];
                    l_s[n1 * 36 + mh * 18 + m] = a1[m];
                }
            }
        }
    }
    // Remaining rows 32..35: warps 0..3, single-row path.
    if (w < 4) {
        int n = 32 + w;
        const float4* sg = (const float4*)(g_sig + (base + n) * PDIM);
        float accm[36];
#pragma unroll
        for (int m = 0; m < 36; m++) accm[m] = 0.f;
#pragma unroll
        for (int it = 0; it < 4; it++) {
            float4 s = __ldg(&sg[lane + 32 * it]);
#pragma unroll
            for (int m = 0; m < 36; m++) {
                float4 p = __ldg(&pp[m * 128 + lane + 32 * it]);
                accm[m] += s.x * p.x + s.y * p.y + s.z * p.z + s.w * p.w;
            }
        }
#pragma unroll
        for (int off = 16; off > 0; off >>= 1)
#pragma unroll
            for (int m = 0; m < 36; m++)
                accm[m] += __shfl_xor_sync(0xFFFFFFFF, accm[m], off);
        if (lane == 0) {
#pragma unroll
            for (int m = 0; m < 36; m++) l_s[n * 36 + m] = accm[m];
        }
    }

    // v staging must be complete (per-thread) before the barrier publishes it.
    asm volatile("cp.async.wait_group 0;" ::: "memory");
    __syncthreads();

    // row softmax; write probs transposed (m-major) for vectorized AV loads
    if (tid < 36) {
        float row[36];
        float m = -1e30f;
#pragma unroll
        for (int j = 0; j < 36; j++) { row[j] = l_s[tid * 36 + j]; m = fmaxf(m, row[j]); }
        float ssum = 0.f;
#pragma unroll
        for (int j = 0; j < 36; j++) { float e = __expf(row[j] - m); row[j] = e; ssum += e; }
        float inv = 1.f / ssum;
#pragma unroll
        for (int j = 0; j < 36; j++) l_t[j * 40 + tid] = row[j] * inv;
    }
    __syncthreads();

    // AV: out[n][p] = sum_m a[n][m] v[m][p]; each thread: 1 col-chunk x 18 rows
    int c4 = tid & 127, nh = tid >> 7;
    float4 acc[18];
#pragma unroll
    for (int j = 0; j < 18; j++) acc[j] = make_float4(0.f, 0.f, 0.f, 0.f);
    const float4* vrow = (const float4*)v_s + c4;
#pragma unroll 4
    for (int m = 0; m < 36; m++) {
        float4 vv = vrow[m * 128];
#pragma unroll
        for (int jj = 0; jj < 9; jj++) {
            float2 aa = *(const float2*)&l_t[m * 40 + nh * 18 + jj * 2];
            acc[2*jj].x   += aa.x * vv.x; acc[2*jj].y   += aa.x * vv.y;
            acc[2*jj].z   += aa.x * vv.z; acc[2*jj].w   += aa.x * vv.w;
            acc[2*jj+1].x += aa.y * vv.x; acc[2*jj+1].y += aa.y * vv.y;
            acc[2*jj+1].z += aa.y * vv.z; acc[2*jj+1].w += aa.y * vv.w;
        }
    }
    float4* vo = (float4*)(out_rhat + base * PDIM);
#pragma unroll
    for (int j = 0; j < 18; j++) {
        int n = nh * 18 + j;
        vo[n * 128 + c4] = acc[j];
    }
}

// ---------------------------------------------------------------------------
// Launcher
// ---------------------------------------------------------------------------
extern "C" void kernel_launch(void* const* d_in, const int* in_sizes, int n_in,
                              void* d_out, int out_size) {
    const float* x       = (const float*)d_in[0];
    const float* W_proj  = (const float*)d_in[1];
    const float* b_proj  = (const float*)d_in[2];
    const float* W_sigma = (const float*)d_in[3];
    const float* b_sigma = (const float*)d_in[4];
    const float* W_psi   = (const float*)d_in[5];
    const float* b_psi   = (const float*)d_in[6];
    const float* W_r     = (const float*)d_in[7];
    float* out = (float*)d_out;

    cudaFuncSetAttribute(gemm_fused_kernel, cudaFuncAttributeMaxDynamicSharedMemorySize, GEMM_SMEM);
    cudaFuncSetAttribute(attn_kernel, cudaFuncAttributeMaxDynamicSharedMemorySize, ATTN_SMEM);

    long n4 = (long)MROWS * DIN / 4;
    split_x_kernel<<<8192, 256>>>(x, n4);
    split_w_kernel<<<(NCAT * DIN + 255) / 256, 256>>>(W_proj, W_sigma, W_psi, W_r);
    gemm_fused_kernel<<<2 * NB3, 512, GEMM_SMEM>>>(b_sigma, b_psi, b_proj, out);
    attn_kernel<<<HEADS, 256, ATTN_SMEM>>>(out + OUT_HALF);
}